// round 6
// baseline (speedup 1.0000x reference)
#include <cuda_runtime.h>
#include <math.h>
#include <stdint.h>

#define Bn   4
#define CIN  256
#define CQK  64
#define CS   128
#define Hh   128
#define Ww   128
#define HW   (Hh*Ww)
#define NCH  64
#define PIX_PER_CHUNK (HW/NCH)     // 256

// ---- scratch ----
__device__ float g_simp[Bn*NCH*CQK*CIN];   // 16MB
__device__ float g_sim [Bn*CQK*CIN];

// packed tf32 pair buffers (zero-initialized .bss; borders of g_ft stay zero)
__device__ __align__(16) uint2 g_Aqk[16384];            // qk weights
__device__ __align__(16) uint2 g_Av [32768];            // v weights
__device__ __align__(16) uint2 g_wp2[147456];           // conv weights
__device__ __align__(16) uint2 g_AM2[Bn*8192];          // M2 packed: [b][krow8][co256][kk4]
__device__ __align__(16) uint2 g_xt [Bn*8*16*HW];       // x packed: [(b*8+it)*16+kkb][n]
__device__ __align__(16) uint2 g_qnt[Bn*32*HW];         // qn packed, channel pairs: [b][row32][n]
__device__ __align__(16) uint2 g_knt[Bn*64*(HW/2)];     // kn packed, pixel pairs: [b][m64][pair]
__device__ __align__(16) uint2 g_vt [Bn*256*(HW/2)];    // v packed, pixel pairs: [b][co256][pair]
__device__ __align__(16) uint2 g_ft [Bn*128*130*132];   // fuse packed+padded: [b*128+ch*8+kkb][h+1][w+1]

__device__ __forceinline__ uint32_t f2tf(float f) {
    uint32_t u; asm("cvt.rna.tf32.f32 %0, %1;" : "=r"(u) : "f"(f)); return u;
}

__device__ __forceinline__ void mma8(float* c, uint2 a01, uint2 a13, uint2 b) {
    asm volatile(
        "mma.sync.aligned.m16n8k8.row.col.f32.tf32.tf32.f32 "
        "{%0,%1,%2,%3}, {%4,%5,%6,%7}, {%8,%9}, {%0,%1,%2,%3};"
        : "+f"(c[0]), "+f"(c[1]), "+f"(c[2]), "+f"(c[3])
        : "r"(a01.x), "r"(a13.x), "r"(a01.y), "r"(a13.y), "r"(b.x), "r"(b.y));
}

__device__ __forceinline__ void cpa16(uint32_t saddr, const void* g) {
    asm volatile("cp.async.cg.shared.global [%0], [%1], 16;" :: "r"(saddr), "l"(g));
}
__device__ __forceinline__ void cpa_commit() { asm volatile("cp.async.commit_group;"); }
__device__ __forceinline__ void cpa_wait0()  { asm volatile("cp.async.wait_group 0;" ::: "memory"); }

// ============ pack kernels ============
__global__ void k_pack_qk(const float* __restrict__ qW, const float* __restrict__ kW)
{
    int idx = blockIdx.x * 256 + threadIdx.x;
    int kk = idx & 3, m = (idx >> 2) & 127, kb = idx >> 9;
    int k0 = kb * 8 + kk;
    const float* wr = (m < 64) ? (qW + (size_t)m * CIN) : (kW + (size_t)(m - 64) * CIN);
    g_Aqk[idx] = make_uint2(f2tf(wr[k0]), f2tf(wr[k0 + 4]));
}

__global__ void k_pack_v(const float* __restrict__ vW)
{
    int idx = blockIdx.x * 256 + threadIdx.x;
    int kk = idx & 3, m = (idx >> 2) & 255, kb = idx >> 10;
    int k0 = kb * 8 + kk;
    const float* wr = vW + (size_t)m * CIN;
    g_Av[idx] = make_uint2(f2tf(wr[k0]), f2tf(wr[k0 + 4]));
}

__global__ void k_pack_conv(const float* __restrict__ sW)
{
    int idx = blockIdx.x * 256 + threadIdx.x;
    int r = idx & 1023, s = idx >> 10;
    int kk = r & 3, co = (r >> 2) & 127, kb = r >> 9;
    int tap = s % 3, t2 = s / 3, ch = t2 & 15, dh = t2 >> 4;
    int ci = ch * 16 + kb * 8 + kk;
    float w0 = sW[((size_t)co * CIN + ci) * 9 + dh * 3 + tap];
    float w1 = sW[((size_t)co * CIN + ci + 4) * 9 + dh * 3 + tap];
    g_wp2[idx] = make_uint2(f2tf(w0), f2tf(w1));
}

// x -> tf32 pair layout, 4 pixels per thread
__global__ void k_packx(const float* __restrict__ x)
{
    int idx = blockIdx.x * 256 + threadIdx.x;   // < 2097152
    int n4 = (idx & 4095) * 4;
    int kkb = (idx >> 12) & 15;
    int it = (idx >> 16) & 7;
    int b = idx >> 19;
    int k0 = it * 32 + ((kkb >> 2) << 3) + (kkb & 3);
    const float* xb = x + ((size_t)b * CIN + k0) * HW + n4;
    float4 lo = *(const float4*)xb;
    float4 hi = *(const float4*)(xb + 4 * HW);
    uint2* dst = g_xt + ((size_t)((b * 8 + it) * 16 + kkb)) * HW + n4;
    *(uint4*)dst = make_uint4(f2tf(lo.x), f2tf(hi.x), f2tf(lo.y), f2tf(hi.y));
    *(uint4*)(dst + 2) = make_uint4(f2tf(lo.z), f2tf(hi.z), f2tf(lo.w), f2tf(hi.w));
}

// ============ K1: q,k projections + BN + L2 norm -> packed g_qnt / g_knt ============
// dyn smem: Asm 2x2048 uint2, Bsm 2x2112 uint2, Sq 4x128 f32, Nn 2x128 f32 = 69632 B
__global__ void __launch_bounds__(256, 2)
k_qk_mma(const float* __restrict__ qs, const float* __restrict__ qb,
         const float* __restrict__ kscale, const float* __restrict__ kshift)
{
    extern __shared__ uint2 dynsm[];
    uint2* Asm = dynsm;              // 2 x 2048
    uint2* Bsm = dynsm + 4096;       // 2 x 2112
    float* Sq  = (float*)(dynsm + 8320);
    float* Nn  = Sq + 512;

    const int b = blockIdx.y, n0 = blockIdx.x * 128;
    const int tid = threadIdx.x, lane = tid & 31, w = tid >> 5;
    const int g = lane >> 2, kk = lane & 3;
    const int mg = w >> 1, ng = w & 1;
    const int m0w = mg * 32, n0w = ng * 64;

    const uint32_t aBase = (uint32_t)__cvta_generic_to_shared(dynsm);
    const uint2* xtb = g_xt + (size_t)b * 8 * 16 * HW + n0;

    float acc[2][8][4];
#pragma unroll
    for (int mt = 0; mt < 2; mt++)
#pragma unroll
        for (int nt = 0; nt < 8; nt++)
#pragma unroll
            for (int i = 0; i < 4; i++) acc[mt][nt][i] = 0.f;

#pragma unroll
    for (int i = 0; i < 4; i++) {
        int j = i * 256 + tid;
        cpa16(aBase + j * 16, g_Aqk + j * 2);
    }
#pragma unroll
    for (int i = 0; i < 4; i++) {
        int j = i * 256 + tid;
        int kkb = j >> 6, npair = (j & 63) * 2;
        cpa16(aBase + 4096 * 8 + (kkb * 132 + npair) * 8,
              xtb + (size_t)kkb * HW + npair);
    }
    cpa_commit();
    cpa_wait0();
    __syncthreads();

    for (int it = 0; it < 8; it++) {
        int cur = it & 1, nxt = cur ^ 1;
        if (it < 7) {
#pragma unroll
            for (int i = 0; i < 4; i++) {
                int j = i * 256 + tid;
                cpa16(aBase + nxt * 16384 + j * 16, g_Aqk + (it + 1) * 2048 + j * 2);
            }
#pragma unroll
            for (int i = 0; i < 4; i++) {
                int j = i * 256 + tid;
                int kkb = j >> 6, npair = (j & 63) * 2;
                cpa16(aBase + 4096 * 8 + nxt * 16896 + (kkb * 132 + npair) * 8,
                      xtb + (size_t)((it + 1) * 16 + kkb) * HW + npair);
            }
            cpa_commit();
        }
        const uint2* Ac = Asm + cur * 2048;
        const uint2* Bc = Bsm + cur * 2112;
#pragma unroll
        for (int kb = 0; kb < 4; kb++) {
            uint2 a01[2], a13[2];
#pragma unroll
            for (int mt = 0; mt < 2; mt++) {
                a01[mt] = Ac[(kb * 128 + m0w + mt * 16 + g) * 4 + kk];
                a13[mt] = Ac[(kb * 128 + m0w + mt * 16 + 8 + g) * 4 + kk];
            }
#pragma unroll
            for (int nt = 0; nt < 8; nt++) {
                uint2 bb = Bc[(kb * 4 + kk) * 132 + n0w + nt * 8 + g];
                mma8(acc[0][nt], a01[0], a13[0], bb);
                mma8(acc[1][nt], a01[1], a13[1], bb);
            }
        }
        cpa_wait0();
        __syncthreads();
    }

    // BN + column sums of squares
    float sq[8][2];
#pragma unroll
    for (int nt = 0; nt < 8; nt++) { sq[nt][0] = 0.f; sq[nt][1] = 0.f; }
#pragma unroll
    for (int mt = 0; mt < 2; mt++) {
        int r0 = m0w + mt * 16 + g, r1 = r0 + 8;
        bool isq = (r0 < 64);
        float sc0 = isq ? qs[r0] : kscale[r0 - 64];
        float sh0 = isq ? qb[r0] : kshift[r0 - 64];
        float sc1 = isq ? qs[r1] : kscale[r1 - 64];
        float sh1 = isq ? qb[r1] : kshift[r1 - 64];
#pragma unroll
        for (int nt = 0; nt < 8; nt++) {
            float v0 = fmaf(acc[mt][nt][0], sc0, sh0);
            float v1 = fmaf(acc[mt][nt][1], sc0, sh0);
            float v2 = fmaf(acc[mt][nt][2], sc1, sh1);
            float v3 = fmaf(acc[mt][nt][3], sc1, sh1);
            acc[mt][nt][0] = v0; acc[mt][nt][1] = v1;
            acc[mt][nt][2] = v2; acc[mt][nt][3] = v3;
            sq[nt][0] += v0 * v0 + v2 * v2;
            sq[nt][1] += v1 * v1 + v3 * v3;
        }
    }
#pragma unroll
    for (int nt = 0; nt < 8; nt++) {
#pragma unroll
        for (int o = 4; o < 32; o <<= 1) {
            sq[nt][0] += __shfl_xor_sync(0xffffffffu, sq[nt][0], o);
            sq[nt][1] += __shfl_xor_sync(0xffffffffu, sq[nt][1], o);
        }
    }
    if (lane < 4) {
#pragma unroll
        for (int nt = 0; nt < 8; nt++) {
            int c = n0w + nt * 8 + lane * 2;
            Sq[mg * 128 + c] = sq[nt][0];
            Sq[mg * 128 + c + 1] = sq[nt][1];
        }
    }
    __syncthreads();
    {
        int col = tid & 127, half = tid >> 7;
        float s = Sq[half * 256 + col] + Sq[half * 256 + 128 + col];
        Nn[half * 128 + col] = 1.f / fmaxf(sqrtf(s), 1e-12f);
    }
    __syncthreads();

    if (mg < 2) {
        // q half -> g_qnt: channel pairs (ch, ch+4) via shfl_xor 16
#pragma unroll
        for (int mt = 0; mt < 2; mt++) {
            int r0 = m0w + mt * 16 + g;
#pragma unroll
            for (int nt = 0; nt < 8; nt++) {
                int c = n0w + nt * 8 + (lane & 3) * 2;
                float i0 = Nn[c], i1 = Nn[c + 1];
                float v0 = acc[mt][nt][0] * i0, v1 = acc[mt][nt][1] * i1;
                float v2 = acc[mt][nt][2] * i0, v3 = acc[mt][nt][3] * i1;
                float p0 = __shfl_xor_sync(0xffffffffu, v0, 16);
                float p1 = __shfl_xor_sync(0xffffffffu, v1, 16);
                float p2 = __shfl_xor_sync(0xffffffffu, v2, 16);
                float p3 = __shfl_xor_sync(0xffffffffu, v3, 16);
                if (g < 4) {
                    int row0 = (r0 >> 3) * 4 + g;
                    int row1 = ((r0 + 8) >> 3) * 4 + g;
                    *(uint4*)(g_qnt + (size_t)(b * 32 + row0) * HW + n0 + c) =
                        make_uint4(f2tf(v0), f2tf(p0), f2tf(v1), f2tf(p1));
                    *(uint4*)(g_qnt + (size_t)(b * 32 + row1) * HW + n0 + c) =
                        make_uint4(f2tf(v2), f2tf(p2), f2tf(v3), f2tf(p3));
                }
            }
        }
    } else {
        // k half -> g_knt: pixel pairs (p, p+4) via shfl_xor 2
#pragma unroll
        for (int mt = 0; mt < 2; mt++) {
            int r0 = m0w + mt * 16 + g - 64;
#pragma unroll
            for (int nt = 0; nt < 8; nt++) {
                int c = n0w + nt * 8 + (lane & 3) * 2;
                float i0 = Nn[128 + c], i1 = Nn[128 + c + 1];
                float v0 = acc[mt][nt][0] * i0, v1 = acc[mt][nt][1] * i1;
                float v2 = acc[mt][nt][2] * i0, v3 = acc[mt][nt][3] * i1;
                float p0 = __shfl_xor_sync(0xffffffffu, v0, 2);
                float p1 = __shfl_xor_sync(0xffffffffu, v1, 2);
                float p2 = __shfl_xor_sync(0xffffffffu, v2, 2);
                float p3 = __shfl_xor_sync(0xffffffffu, v3, 2);
                if ((lane & 2) == 0) {
                    size_t pb = (size_t)((n0 + c) >> 3) * 4 + (c & 3);
                    *(uint4*)(g_knt + (size_t)(b * 64 + r0) * 8192 + pb) =
                        make_uint4(f2tf(v0), f2tf(p0), f2tf(v1), f2tf(p1));
                    *(uint4*)(g_knt + (size_t)(b * 64 + r0 + 8) * 8192 + pb) =
                        make_uint4(f2tf(v2), f2tf(p2), f2tf(v3), f2tf(p3));
                }
            }
        }
    }
}

// ============ K2: v projection + BN + ReLU -> packed g_vt ============
// dyn smem: Asm 2x2048 + Bsm 2x2112 uint2 = 66560 B
__global__ void __launch_bounds__(256, 2)
k_v_mma(const float* __restrict__ vs, const float* __restrict__ vb)
{
    extern __shared__ uint2 dynsm[];
    uint2* Asm = dynsm;
    uint2* Bsm = dynsm + 4096;

    const int b = blockIdx.z, co0 = blockIdx.y * 128, n0 = blockIdx.x * 128;
    const int tid = threadIdx.x, lane = tid & 31, w = tid >> 5;
    const int g = lane >> 2, kk = lane & 3;
    const int mg = w >> 1, ng = w & 1;
    const int m0w = mg * 32, n0w = ng * 64;

    const uint32_t aBase = (uint32_t)__cvta_generic_to_shared(dynsm);
    const uint2* xtb = g_xt + (size_t)b * 8 * 16 * HW + n0;

    float acc[2][8][4];
#pragma unroll
    for (int mt = 0; mt < 2; mt++)
#pragma unroll
        for (int nt = 0; nt < 8; nt++)
#pragma unroll
            for (int i = 0; i < 4; i++) acc[mt][nt][i] = 0.f;

#pragma unroll
    for (int i = 0; i < 4; i++) {
        int j = i * 256 + tid;
        int u = j * 2, kbl = u >> 9, r = u & 511;
        cpa16(aBase + u * 8, g_Av + (size_t)kbl * 1024 + co0 * 4 + r);
    }
#pragma unroll
    for (int i = 0; i < 4; i++) {
        int j = i * 256 + tid;
        int kkb = j >> 6, npair = (j & 63) * 2;
        cpa16(aBase + 4096 * 8 + (kkb * 132 + npair) * 8,
              xtb + (size_t)kkb * HW + npair);
    }
    cpa_commit();
    cpa_wait0();
    __syncthreads();

    for (int it = 0; it < 8; it++) {
        int cur = it & 1, nxt = cur ^ 1;
        if (it < 7) {
#pragma unroll
            for (int i = 0; i < 4; i++) {
                int j = i * 256 + tid;
                int u = j * 2, kbl = u >> 9, r = u & 511;
                cpa16(aBase + nxt * 16384 + u * 8,
                      g_Av + (size_t)((it + 1) * 4 + kbl) * 1024 + co0 * 4 + r);
            }
#pragma unroll
            for (int i = 0; i < 4; i++) {
                int j = i * 256 + tid;
                int kkb = j >> 6, npair = (j & 63) * 2;
                cpa16(aBase + 4096 * 8 + nxt * 16896 + (kkb * 132 + npair) * 8,
                      xtb + (size_t)((it + 1) * 16 + kkb) * HW + npair);
            }
            cpa_commit();
        }
        const uint2* Ac = Asm + cur * 2048;
        const uint2* Bc = Bsm + cur * 2112;
#pragma unroll
        for (int kb = 0; kb < 4; kb++) {
            uint2 a01[2], a13[2];
#pragma unroll
            for (int mt = 0; mt < 2; mt++) {
                a01[mt] = Ac[(kb * 128 + m0w + mt * 16 + g) * 4 + kk];
                a13[mt] = Ac[(kb * 128 + m0w + mt * 16 + 8 + g) * 4 + kk];
            }
#pragma unroll
            for (int nt = 0; nt < 8; nt++) {
                uint2 bb = Bc[(kb * 4 + kk) * 132 + n0w + nt * 8 + g];
                mma8(acc[0][nt], a01[0], a13[0], bb);
                mma8(acc[1][nt], a01[1], a13[1], bb);
            }
        }
        cpa_wait0();
        __syncthreads();
    }

    // epilogue: BN + ReLU, pack pixel pairs via shfl_xor 2 -> g_vt
#pragma unroll
    for (int mt = 0; mt < 2; mt++) {
        int co = co0 + m0w + mt * 16 + g;
        float sc0 = vs[co], sh0 = vb[co];
        float sc1 = vs[co + 8], sh1 = vb[co + 8];
#pragma unroll
        for (int nt = 0; nt < 8; nt++) {
            int c = n0w + nt * 8 + (lane & 3) * 2;
            float f0 = fmaxf(fmaf(acc[mt][nt][0], sc0, sh0), 0.f);
            float f1 = fmaxf(fmaf(acc[mt][nt][1], sc0, sh0), 0.f);
            float f2 = fmaxf(fmaf(acc[mt][nt][2], sc1, sh1), 0.f);
            float f3 = fmaxf(fmaf(acc[mt][nt][3], sc1, sh1), 0.f);
            float p0 = __shfl_xor_sync(0xffffffffu, f0, 2);
            float p1 = __shfl_xor_sync(0xffffffffu, f1, 2);
            float p2 = __shfl_xor_sync(0xffffffffu, f2, 2);
            float p3 = __shfl_xor_sync(0xffffffffu, f3, 2);
            if ((lane & 2) == 0) {
                size_t pb = (size_t)((n0 + c) >> 3) * 4 + (c & 3);
                *(uint4*)(g_vt + (size_t)(b * 256 + co) * 8192 + pb) =
                    make_uint4(f2tf(f0), f2tf(p0), f2tf(f1), f2tf(p1));
                *(uint4*)(g_vt + (size_t)(b * 256 + co + 8) * 8192 + pb) =
                    make_uint4(f2tf(f2), f2tf(p2), f2tf(f3), f2tf(p3));
            }
        }
    }
}

// ============ K3: partial sim = kn @ v^T (pre-packed, cp.async double-buffered) ============
// dyn smem: A 2x1152 + B 2x4608 uint2 = 92160 B
__global__ void __launch_bounds__(256, 2) k_sim_mma()
{
    extern __shared__ uint2 dynsm[];

    const int b = blockIdx.y, ch = blockIdx.x;
    const int p0 = ch * PIX_PER_CHUNK;
    const int tid = threadIdx.x, lane = tid & 31, w = tid >> 5;
    const int g = lane >> 2, kk = lane & 3;
    const int mg = w >> 2, ng = w & 3;
    const int m0w = mg * 32, n0w = ng * 64;
    const uint32_t smBase = (uint32_t)__cvta_generic_to_shared(dynsm);

    float acc[2][8][4];
#pragma unroll
    for (int mt = 0; mt < 2; mt++)
#pragma unroll
        for (int nt = 0; nt < 8; nt++)
#pragma unroll
            for (int i = 0; i < 4; i++) acc[mt][nt][i] = 0.f;

    auto fill = [&](int it, int stage) {
        int base = (p0 + it * 32) >> 1;        // pair idx base
#pragma unroll
        for (int i = 0; i < 2; i++) {
            int j = i * 256 + tid;
            int m = j >> 3, seg = j & 7;
            cpa16(smBase + (stage * 1152 + m * 18 + seg * 2) * 8,
                  g_knt + (size_t)(b * 64 + m) * 8192 + base + seg * 2);
        }
#pragma unroll
        for (int i = 0; i < 8; i++) {
            int j = i * 256 + tid;
            int n = j >> 3, seg = j & 7;
            cpa16(smBase + (2304 + stage * 4608 + n * 18 + seg * 2) * 8,
                  g_vt + (size_t)(b * 256 + n) * 8192 + base + seg * 2);
        }
    };

    fill(0, 0);
    cpa_commit();
    cpa_wait0();
    __syncthreads();

    for (int it = 0; it < 8; it++) {
        int cur = it & 1, nxt = cur ^ 1;
        if (it < 7) { fill(it + 1, nxt); cpa_commit(); }
        const uint2* Ac = dynsm + cur * 1152;
        const uint2* Bc = dynsm + 2304 + cur * 4608;
#pragma unroll
        for (int kb = 0; kb < 4; kb++) {
            uint2 a01[2], a13[2];
#pragma unroll
            for (int mt = 0; mt < 2; mt++) {
                a01[mt] = Ac[(m0w + mt * 16 + g) * 18 + kb * 4 + kk];
                a13[mt] = Ac[(m0w + mt * 16 + 8 + g) * 18 + kb * 4 + kk];
            }
#pragma unroll
            for (int nt = 0; nt < 8; nt++) {
                uint2 bb = Bc[(n0w + nt * 8 + g) * 18 + kb * 4 + kk];
                mma8(acc[0][nt], a01[0], a13[0], bb);
                mma8(acc[1][nt], a01[1], a13[1], bb);
            }
        }
        cpa_wait0();
        __syncthreads();
    }

    float* outp = g_simp + (size_t)(b * NCH + ch) * CQK * CIN;
#pragma unroll
    for (int mt = 0; mt < 2; mt++) {
        int r = m0w + mt * 16 + g;
#pragma unroll
        for (int nt = 0; nt < 8; nt++) {
            int c = n0w + nt * 8 + (lane & 3) * 2;
            *(float2*)&outp[(size_t)r * CIN + c] = make_float2(acc[mt][nt][0], acc[mt][nt][1]);
            *(float2*)&outp[(size_t)(r + 8) * CIN + c] = make_float2(acc[mt][nt][2], acc[mt][nt][3]);
        }
    }
}

// K3b: reduce partials
__global__ void k_simreduce()
{
    int o = blockIdx.x * 256 + threadIdx.x;
    int b = o / (CQK * CIN);
    int cv = o - b * (CQK * CIN);
    float s = 0.f;
#pragma unroll 8
    for (int ch = 0; ch < NCH; ch++)
        s += g_simp[((size_t)(b * NCH + ch)) * CQK * CIN + cv];
    g_sim[o] = s;
}

// K4a: M2 = oW @ sim^T, written directly as packed tf32 pairs g_AM2
__global__ void k_m2(const float* __restrict__ oW)
{
    __shared__ float ssm[CIN];
    const int b = blockIdx.x >> 6;
    const int c = blockIdx.x & 63;
    const int o = threadIdx.x;
    ssm[o] = g_sim[((size_t)b * CQK + c) * CIN + o];
    __syncthreads();
    float s = 0.f;
#pragma unroll 8
    for (int v = 0; v < CIN; v++) s = fmaf(oW[(size_t)o * CIN + v], ssm[v], s);
    int krow = c >> 3, rem = c & 7;
    int kkv = rem & 3;
    ((uint32_t*)g_AM2)[(size_t)b * 16384 + (krow * 256 + o) * 8 + kkv * 2 + (rem >> 2)] = f2tf(s);
}

// ============ K4: ctx mma: fuse = relu(BN(M2 @ qn)) + x + up -> packed g_ft ============
// dyn smem: Asm 4096 + Bsm 4224 uint2 + upH 8192 f32 = 99328 B
__global__ void __launch_bounds__(256, 2)
k_ctx_mma(const float* __restrict__ x, const float* __restrict__ up,
          const float* __restrict__ os, const float* __restrict__ ob)
{
    extern __shared__ uint2 dynsm[];
    uint2* Asm = dynsm;              // 4096
    uint2* Bsm = dynsm + 4096;       // 32 x 132
    float* upH = (float*)(dynsm + 8320);  // [128][64]

    const int b = blockIdx.z;
    const int co0 = blockIdx.y * 128;
    const int h = blockIdx.x;
    const int n0 = h * Ww;
    const int tid = threadIdx.x, lane = tid & 31, w = tid >> 5;
    const int g = lane >> 2, kk = lane & 3;
    const int mg = w >> 1, ng = w & 1;
    const int m0w = mg * 32, n0w = ng * 64;
    const uint32_t aBase = (uint32_t)__cvta_generic_to_shared(dynsm);

    // A: M2 co-half, B: qnt row tile
#pragma unroll
    for (int i = 0; i < 8; i++) {
        int jj = i * 256 + tid;           // < 2048
        int u = jj * 2;
        int kk2 = u & 3, m = (u >> 2) & 127, krow = u >> 9;
        cpa16(aBase + u * 8, g_AM2 + (size_t)b * 8192 + krow * 1024 + (co0 + m) * 4 + kk2);
    }
#pragma unroll
    for (int i = 0; i < 8; i++) {
        int jj = i * 256 + tid;           // < 2048
        int row = jj >> 6, colpair = (jj & 63) * 2;
        cpa16(aBase + 4096 * 8 + (row * 132 + colpair) * 8,
              g_qnt + (size_t)(b * 32 + row) * HW + n0 + colpair);
    }
    cpa_commit();

    // upsample row interp
    {
        float shf = 0.5f * h - 0.25f;
        int h0 = (int)floorf(shf);
        float wh1 = shf - (float)h0;
        int h0c = h0 < 0 ? 0 : h0;
        int h1c = (h0 + 1) > 63 ? 63 : (h0 + 1);
        const float* ub = up + ((size_t)(b * CIN + co0)) * 64 * 64;
#pragma unroll
        for (int i = 0; i < 32; i++) {
            int idx = i * 256 + tid;
            int r = idx >> 6, sw = idx & 63;
            upH[r * 64 + sw] = (1.f - wh1) * ub[(r * 64 + h0c) * 64 + sw]
                             + wh1 * ub[(r * 64 + h1c) * 64 + sw];
        }
    }
    cpa_wait0();
    __syncthreads();

    float acc[2][8][4];
#pragma unroll
    for (int mt = 0; mt < 2; mt++)
#pragma unroll
        for (int nt = 0; nt < 8; nt++)
#pragma unroll
            for (int i = 0; i < 4; i++) acc[mt][nt][i] = 0.f;

#pragma unroll
    for (int s = 0; s < 8; s++) {
        uint2 a01[2], a13[2];
#pragma unroll
        for (int mt = 0; mt < 2; mt++) {
            a01[mt] = Asm[(s * 128 + m0w + mt * 16 + g) * 4 + kk];
            a13[mt] = Asm[(s * 128 + m0w + mt * 16 + 8 + g) * 4 + kk];
        }
#pragma unroll
        for (int nt = 0; nt < 8; nt++) {
            uint2 bb = Bsm[(s * 4 + kk) * 132 + n0w + nt * 8 + g];
            mma8(acc[0][nt], a01[0], a13[0], bb);
            mma8(acc[1][nt], a01[1], a13[1], bb);
        }
    }

    // epilogue: BN+ReLU + residual + upsample, pack channel pairs -> g_ft
    const float* xb = x + ((size_t)b * CIN + co0) * HW + n0;
#pragma unroll
    for (int mt = 0; mt < 2; mt++) {
        int m = m0w + mt * 16 + g;
        int co = co0 + m;
        float sc0 = os[co], sh0 = ob[co];
        float sc1 = os[co + 8], sh1 = ob[co + 8];
#pragma unroll
        for (int nt = 0; nt < 8; nt++) {
            int c0 = n0w + nt * 8 + (lane & 3) * 2;
            int c1 = c0 + 1;
            float sw0 = 0.5f * c0 - 0.25f, sw1 = 0.5f * c1 - 0.25f;
            int wa0 = (int)floorf(sw0), wa1 = (int)floorf(sw1);
            float t0 = sw0 - (float)wa0, t1 = sw1 - (float)wa1;
            int w00 = wa0 < 0 ? 0 : wa0, w01 = (wa0 + 1) > 63 ? 63 : (wa0 + 1);
            int w10 = wa1 < 0 ? 0 : wa1, w11 = (wa1 + 1) > 63 ? 63 : (wa1 + 1);

            float u0a = (1.f - t0) * upH[m * 64 + w00] + t0 * upH[m * 64 + w01];
            float u1a = (1.f - t1) * upH[m * 64 + w10] + t1 * upH[m * 64 + w11];
            float u0b = (1.f - t0) * upH[(m + 8) * 64 + w00] + t0 * upH[(m + 8) * 64 + w01];
            float u1b = (1.f - t1) * upH[(m + 8) * 64 + w10] + t1 * upH[(m + 8) * 64 + w11];

            float f0 = fmaxf(fmaf(acc[mt][nt][0], sc0, sh0), 0.f) + xb[(size_t)m * HW + c0] + u0a;
            float f1 = fmaxf(fmaf(acc[mt][nt][1], sc0, sh0), 0.f) + xb[(size_t)m * HW + c1] + u1a;
            float f2 = fmaxf(fmaf(acc[mt][nt][2], sc1, sh1), 0.f) + xb[(size_t)(m + 8) * HW + c0] + u0b;
            float f3 = fmaxf(fmaf(acc[mt][nt][3], sc1, sh1), 0.f) + xb[(size_t)(m + 8) * HW + c1] + u1b;

            float p0 = __shfl_xor_sync(0xffffffffu, f0, 16);
            float p1 = __shfl_xor_sync(0xffffffffu, f1, 16);
            float p2 = __shfl_xor_sync(0xffffffffu, f2, 16);
            float p3 = __shfl_xor_sync(0xffffffffu, f3, 16);
            if (g < 4) {
                int ch16 = co >> 4;
                size_t rowA = (size_t)(b * 128 + ch16 * 8 + g);
                size_t rowB = rowA + 4;
                uint2* dA = g_ft + (rowA * 130 + h + 1) * 132 + 1 + c0;
                uint2* dB = g_ft + (rowB * 130 + h + 1) * 132 + 1 + c0;
                dA[0] = make_uint2(f2tf(f0), f2tf(p0));
                dA[1] = make_uint2(f2tf(f1), f2tf(p1));
                dB[0] = make_uint2(f2tf(f2), f2tf(p2));
                dB[1] = make_uint2(f2tf(f3), f2tf(p3));
            }
        }
    }
}

// ============ K5: 3x3 conv, 2 rows x 64 co x 128 w, 32-stage pipeline ============
// dyn smem: Ism 2x2112 + Wsm 2x2304 uint2 = 70656 B
__global__ void __launch_bounds__(256, 2)
k_conv_mma(const float* __restrict__ ss, const float* __restrict__ sb,
           float* __restrict__ out)
{
    extern __shared__ uint2 csm[];
    uint2* Ism = csm;            // 2 x 2112: [row4][kkbl4][132]
    uint2* Wsm = csm + 4224;     // 2 x 2304: [dh*3+tap][256]

    const int h0 = blockIdx.x * 2;
    const int co0 = blockIdx.y * 64;
    const int b = blockIdx.z;
    const int tid = threadIdx.x, lane = tid & 31, w = tid >> 5;
    const int g = lane >> 2, kk = lane & 3;
    const int mg = w >> 2, ng = w & 3;
    const int m0w = mg * 32, n0w = ng * 64;
    const uint32_t smBase = (uint32_t)__cvta_generic_to_shared(csm);

    float acc[2][8][4];
#pragma unroll
    for (int mt = 0; mt < 2; mt++)
#pragma unroll
        for (int nt = 0; nt < 8; nt++)
#pragma unroll
            for (int i = 0; i < 4; i++) acc[mt][nt][i] = 0.f;

    const uint2* ftb = g_ft + (size_t)b * 128 * 130 * 132;

    auto fill = [&](int it, int stage) {
        int ch = it >> 1, kbh = it & 1;
        for (int j = tid; j < 1056; j += 256) {
            int rowplane = j / 66;
            int colpair = (j - rowplane * 66) * 2;
            int row = rowplane >> 2, kkbl = rowplane & 3;
            cpa16(smBase + (stage * 2112 + (row * 4 + kkbl) * 132 + colpair) * 8,
                  ftb + ((size_t)(ch * 8 + kbh * 4 + kkbl) * 130 + h0 + row) * 132 + colpair);
        }
        for (int j = tid; j < 1152; j += 256) {
            int u = j * 2;
            int grp = u >> 8, off = u & 255;
            int dh = grp / 3, tap = grp - dh * 3;
            cpa16(smBase + (4224 + stage * 2304 + grp * 256 + off) * 8,
                  g_wp2 + (size_t)(dh * 48 + ch * 3 + tap) * 1024 + kbh * 512 + co0 * 4 + off);
        }
    };

    fill(0, 0);
    cpa_commit();
    cpa_wait0();
    __syncthreads();

    for (int it = 0; it < 32; it++) {
        int cur = it & 1, nxt = cur ^ 1;
        if (it < 31) { fill(it + 1, nxt); cpa_commit(); }

        const uint2* Ic = Ism + cur * 2112;
        const uint2* Wc = Wsm + cur * 2304;
#pragma unroll
        for (int dh = 0; dh < 3; dh++) {
#pragma unroll
            for (int tap = 0; tap < 3; tap++) {
                const uint2* wb = Wc + (dh * 3 + tap) * 256;
                uint2 a01[2], a13[2];
#pragma unroll
                for (int mt = 0; mt < 2; mt++) {
                    a01[mt] = wb[(m0w + mt * 16 + g) * 4 + kk];
                    a13[mt] = wb[(m0w + mt * 16 + 8 + g) * 4 + kk];
                }
#pragma unroll
                for (int nt = 0; nt < 8; nt++) {
                    int n = n0w + nt * 8 + g;
                    int rrow = n >> 7, wx = n & 127;
                    uint2 bb = Ic[((rrow + dh) * 4 + kk) * 132 + wx + tap];
                    mma8(acc[0][nt], a01[0], a13[0], bb);
                    mma8(acc[1][nt], a01[1], a13[1], bb);
                }
            }
        }
        cpa_wait0();
        __syncthreads();
    }

#pragma unroll
    for (int mt = 0; mt < 2; mt++) {
        int co = co0 + m0w + mt * 16 + g;
        float sc0 = ss[co], sh0 = sb[co];
        float sc1 = ss[co + 8], sh1 = sb[co + 8];
#pragma unroll
        for (int nt = 0; nt < 8; nt++) {
            int n = n0w + nt * 8 + (lane & 3) * 2;
            int r = n >> 7, wx = n & 127;
            float* o0p = out + (((size_t)b * CS + co) * Hh + h0 + r) * Ww + wx;
            float* o1p = out + (((size_t)b * CS + co + 8) * Hh + h0 + r) * Ww + wx;
            float2 o0 = make_float2(fmaxf(fmaf(acc[mt][nt][0], sc0, sh0), 0.f),
                                    fmaxf(fmaf(acc[mt][nt][1], sc0, sh0), 0.f));
            float2 o1 = make_float2(fmaxf(fmaf(acc[mt][nt][2], sc1, sh1), 0.f),
                                    fmaxf(fmaf(acc[mt][nt][3], sc1, sh1), 0.f));
            *(float2*)o0p = o0;
            *(float2*)o1p = o1;
        }
    }
}

// ============================================================
extern "C" void kernel_launch(void* const* d_in, const int* in_sizes, int n_in,
                              void* d_out, int out_size)
{
    (void)in_sizes; (void)n_in; (void)out_size;
    const float* x        = (const float*)d_in[0];
    const float* up       = (const float*)d_in[1];
    const float* qW       = (const float*)d_in[2];
    const float* q_scale  = (const float*)d_in[3];
    const float* q_shift  = (const float*)d_in[4];
    const float* kW       = (const float*)d_in[5];
    const float* k_scale  = (const float*)d_in[6];
    const float* k_shift  = (const float*)d_in[7];
    const float* vW       = (const float*)d_in[8];
    const float* v_scale  = (const float*)d_in[9];
    const float* v_shift  = (const float*)d_in[10];
    const float* oW       = (const float*)d_in[11];
    const float* o_scale  = (const float*)d_in[12];
    const float* o_shift  = (const float*)d_in[13];
    const float* sW       = (const float*)d_in[14];
    const float* s_scale  = (const float*)d_in[15];
    const float* s_shift  = (const float*)d_in[16];
    float* out = (float*)d_out;

    cudaFuncSetAttribute(k_qk_mma, cudaFuncAttributeMaxDynamicSharedMemorySize, 69632);
    cudaFuncSetAttribute(k_v_mma, cudaFuncAttributeMaxDynamicSharedMemorySize, 66560);
    cudaFuncSetAttribute(k_sim_mma, cudaFuncAttributeMaxDynamicSharedMemorySize, 92160);
    cudaFuncSetAttribute(k_ctx_mma, cudaFuncAttributeMaxDynamicSharedMemorySize, 99328);
    cudaFuncSetAttribute(k_conv_mma, cudaFuncAttributeMaxDynamicSharedMemorySize, 70656);

    k_pack_qk<<<64, 256>>>(qW, kW);
    k_pack_v<<<128, 256>>>(vW);
    k_pack_conv<<<576, 256>>>(sW);
    k_packx<<<8192, 256>>>(x);
    k_qk_mma<<<dim3(HW / 128, Bn), 256, 69632>>>(q_scale, q_shift, k_scale, k_shift);
    k_v_mma<<<dim3(HW / 128, 2, Bn), 256, 66560>>>(v_scale, v_shift);
    k_sim_mma<<<dim3(NCH, Bn), 256, 92160>>>();
    k_simreduce<<<256, 256>>>();
    k_m2<<<Bn * CQK, 256>>>(oW);
    k_ctx_mma<<<dim3(Hh, 2, Bn), 256, 99328>>>(x, up, o_scale, o_shift);
    k_conv_mma<<<dim3(Hh / 2, 2, Bn), 256, 70656>>>(s_scale, s_shift, out);
}

// round 8
// speedup vs baseline: 1.3191x; 1.3191x over previous
#include <cuda_runtime.h>
#include <math.h>
#include <stdint.h>

#define Bn   4
#define CIN  256
#define CQK  64
#define CS   128
#define Hh   128
#define Ww   128
#define HW   (Hh*Ww)
#define NCH  64
#define PIX_PER_CHUNK (HW/NCH)

__device__ float g_simp[Bn*NCH*CQK*CIN];
__device__ float g_sim [Bn*CQK*CIN];

__device__ __align__(16) uint2 g_Aqk[16384];
__device__ __align__(16) uint2 g_Av [32768];
__device__ __align__(16) uint2 g_AM2[Bn*8192];
__device__ __align__(16) uint2 g_xt [Bn*8*16*HW];
__device__ __align__(16) uint2 g_qnt[Bn*32*HW];
__device__ __align__(16) uint2 g_knt[Bn*64*(HW/2)];
__device__ __align__(16) uint2 g_vt [Bn*256*(HW/2)];
__device__ __align__(16) uint2 g_wph[73728];              // conv weights fp16: [(dh*48+ch*3+tap)*512 + co*4 + j]
__device__ __align__(16) uint2 g_fth[Bn*16*4*130*132];    // fuse fp16 pairs: [b][ch16][j][h+1][w+1]

__device__ __forceinline__ uint32_t f2tf(float f) {
    uint32_t u; asm("cvt.rna.tf32.f32 %0, %1;" : "=r"(u) : "f"(f)); return u;
}
__device__ __forceinline__ uint32_t pkh2(float lo, float hi) {
    uint32_t r; asm("cvt.rn.f16x2.f32 %0, %1, %2;" : "=r"(r) : "f"(hi), "f"(lo)); return r;
}
__device__ __forceinline__ void mma8(float* c, uint2 a01, uint2 a13, uint2 b) {
    asm volatile(
        "mma.sync.aligned.m16n8k8.row.col.f32.tf32.tf32.f32 "
        "{%0,%1,%2,%3}, {%4,%5,%6,%7}, {%8,%9}, {%0,%1,%2,%3};"
        : "+f"(c[0]), "+f"(c[1]), "+f"(c[2]), "+f"(c[3])
        : "r"(a01.x), "r"(a13.x), "r"(a01.y), "r"(a13.y), "r"(b.x), "r"(b.y));
}
__device__ __forceinline__ void mma16(float* c, uint2 alo, uint2 ahi, uint2 b) {
    asm volatile(
        "mma.sync.aligned.m16n8k16.row.col.f32.f16.f16.f32 "
        "{%0,%1,%2,%3}, {%4,%5,%6,%7}, {%8,%9}, {%0,%1,%2,%3};"
        : "+f"(c[0]), "+f"(c[1]), "+f"(c[2]), "+f"(c[3])
        : "r"(alo.x), "r"(ahi.x), "r"(alo.y), "r"(ahi.y), "r"(b.x), "r"(b.y));
}
__device__ __forceinline__ void cpa16(uint32_t saddr, const void* g) {
    asm volatile("cp.async.cg.shared.global [%0], [%1], 16;" :: "r"(saddr), "l"(g));
}
__device__ __forceinline__ void cpa_commit() { asm volatile("cp.async.commit_group;"); }
__device__ __forceinline__ void cpa_wait0()  { asm volatile("cp.async.wait_group 0;" ::: "memory"); }

// ============ pack kernels ============
__global__ void k_pack_qk(const float* __restrict__ qW, const float* __restrict__ kW)
{
    int idx = blockIdx.x * 256 + threadIdx.x;
    int kk = idx & 3, m = (idx >> 2) & 127, kb = idx >> 9;
    int k0 = kb * 8 + kk;
    const float* wr = (m < 64) ? (qW + (size_t)m * CIN) : (kW + (size_t)(m - 64) * CIN);
    g_Aqk[idx] = make_uint2(f2tf(wr[k0]), f2tf(wr[k0 + 4]));
}
__global__ void k_pack_v(const float* __restrict__ vW)
{
    int idx = blockIdx.x * 256 + threadIdx.x;
    int kk = idx & 3, m = (idx >> 2) & 255, kb = idx >> 10;
    int k0 = kb * 8 + kk;
    const float* wr = vW + (size_t)m * CIN;
    g_Av[idx] = make_uint2(f2tf(wr[k0]), f2tf(wr[k0 + 4]));
}
// conv weights -> fp16 pairs: uint2{h2(w[2j],w[2j+1]), h2(w[2j+8],w[2j+9])}
__global__ void k_pack_conv(const float* __restrict__ sW)
{
    int idx = blockIdx.x * 256 + threadIdx.x;   // < 73728
    int r = idx & 511, s = idx >> 9;
    int j = r & 3, co = r >> 2;
    int tap = s % 3, t2 = s / 3, ch = t2 & 15, dh = t2 >> 4;
    int ci = ch * 16 + j * 2;
    const float* wp = sW + ((size_t)co * CIN + ci) * 9 + dh * 3 + tap;
    float w0 = wp[0], w1 = wp[9], w8 = wp[8 * 9], w9 = wp[9 * 9];
    g_wph[idx] = make_uint2(pkh2(w0, w1), pkh2(w8, w9));
}
__global__ void k_packx(const float* __restrict__ x)
{
    int idx = blockIdx.x * 256 + threadIdx.x;
    int n4 = (idx & 4095) * 4;
    int kkb = (idx >> 12) & 15;
    int it = (idx >> 16) & 7;
    int b = idx >> 19;
    int k0 = it * 32 + ((kkb >> 2) << 3) + (kkb & 3);
    const float* xb = x + ((size_t)b * CIN + k0) * HW + n4;
    float4 lo = *(const float4*)xb;
    float4 hi = *(const float4*)(xb + 4 * HW);
    uint2* dst = g_xt + ((size_t)((b * 8 + it) * 16 + kkb)) * HW + n4;
    *(uint4*)dst = make_uint4(f2tf(lo.x), f2tf(hi.x), f2tf(lo.y), f2tf(hi.y));
    *(uint4*)(dst + 2) = make_uint4(f2tf(lo.z), f2tf(hi.z), f2tf(lo.w), f2tf(hi.w));
}

// ============ K1: q,k proj + BN + L2 norm ============
__global__ void __launch_bounds__(256, 2)
k_qk_mma(const float* __restrict__ qs, const float* __restrict__ qb,
         const float* __restrict__ kscale, const float* __restrict__ kshift)
{
    extern __shared__ uint2 dynsm[];
    uint2* Asm = dynsm;
    uint2* Bsm = dynsm + 4096;
    float* Sq  = (float*)(dynsm + 8320);
    float* Nn  = Sq + 512;

    const int b = blockIdx.y, n0 = blockIdx.x * 128;
    const int tid = threadIdx.x, lane = tid & 31, w = tid >> 5;
    const int g = lane >> 2, kk = lane & 3;
    const int mg = w >> 1, ng = w & 1;
    const int m0w = mg * 32, n0w = ng * 64;
    const uint32_t aBase = (uint32_t)__cvta_generic_to_shared(dynsm);
    const uint2* xtb = g_xt + (size_t)b * 8 * 16 * HW + n0;

    float acc[2][8][4];
#pragma unroll
    for (int mt = 0; mt < 2; mt++)
#pragma unroll
        for (int nt = 0; nt < 8; nt++)
#pragma unroll
            for (int i = 0; i < 4; i++) acc[mt][nt][i] = 0.f;

#pragma unroll
    for (int i = 0; i < 4; i++) { int j = i * 256 + tid; cpa16(aBase + j * 16, g_Aqk + j * 2); }
#pragma unroll
    for (int i = 0; i < 4; i++) {
        int j = i * 256 + tid;
        int kkb = j >> 6, npair = (j & 63) * 2;
        cpa16(aBase + 4096 * 8 + (kkb * 132 + npair) * 8, xtb + (size_t)kkb * HW + npair);
    }
    cpa_commit(); cpa_wait0(); __syncthreads();

    for (int it = 0; it < 8; it++) {
        int cur = it & 1, nxt = cur ^ 1;
        if (it < 7) {
#pragma unroll
            for (int i = 0; i < 4; i++) {
                int j = i * 256 + tid;
                cpa16(aBase + nxt * 16384 + j * 16, g_Aqk + (it + 1) * 2048 + j * 2);
            }
#pragma unroll
            for (int i = 0; i < 4; i++) {
                int j = i * 256 + tid;
                int kkb = j >> 6, npair = (j & 63) * 2;
                cpa16(aBase + 4096 * 8 + nxt * 16896 + (kkb * 132 + npair) * 8,
                      xtb + (size_t)((it + 1) * 16 + kkb) * HW + npair);
            }
            cpa_commit();
        }
        const uint2* Ac = Asm + cur * 2048;
        const uint2* Bc = Bsm + cur * 2112;
#pragma unroll
        for (int kb = 0; kb < 4; kb++) {
            uint2 a01[2], a13[2];
#pragma unroll
            for (int mt = 0; mt < 2; mt++) {
                a01[mt] = Ac[(kb * 128 + m0w + mt * 16 + g) * 4 + kk];
                a13[mt] = Ac[(kb * 128 + m0w + mt * 16 + 8 + g) * 4 + kk];
            }
#pragma unroll
            for (int nt = 0; nt < 8; nt++) {
                uint2 bb = Bc[(kb * 4 + kk) * 132 + n0w + nt * 8 + g];
                mma8(acc[0][nt], a01[0], a13[0], bb);
                mma8(acc[1][nt], a01[1], a13[1], bb);
            }
        }
        cpa_wait0(); __syncthreads();
    }

    float sq[8][2];
#pragma unroll
    for (int nt = 0; nt < 8; nt++) { sq[nt][0] = 0.f; sq[nt][1] = 0.f; }
#pragma unroll
    for (int mt = 0; mt < 2; mt++) {
        int r0 = m0w + mt * 16 + g, r1 = r0 + 8;
        bool isq = (r0 < 64);
        float sc0 = isq ? qs[r0] : kscale[r0 - 64];
        float sh0 = isq ? qb[r0] : kshift[r0 - 64];
        float sc1 = isq ? qs[r1] : kscale[r1 - 64];
        float sh1 = isq ? qb[r1] : kshift[r1 - 64];
#pragma unroll
        for (int nt = 0; nt < 8; nt++) {
            float v0 = fmaf(acc[mt][nt][0], sc0, sh0);
            float v1 = fmaf(acc[mt][nt][1], sc0, sh0);
            float v2 = fmaf(acc[mt][nt][2], sc1, sh1);
            float v3 = fmaf(acc[mt][nt][3], sc1, sh1);
            acc[mt][nt][0] = v0; acc[mt][nt][1] = v1;
            acc[mt][nt][2] = v2; acc[mt][nt][3] = v3;
            sq[nt][0] += v0 * v0 + v2 * v2;
            sq[nt][1] += v1 * v1 + v3 * v3;
        }
    }
#pragma unroll
    for (int nt = 0; nt < 8; nt++) {
#pragma unroll
        for (int o = 4; o < 32; o <<= 1) {
            sq[nt][0] += __shfl_xor_sync(0xffffffffu, sq[nt][0], o);
            sq[nt][1] += __shfl_xor_sync(0xffffffffu, sq[nt][1], o);
        }
    }
    if (lane < 4) {
#pragma unroll
        for (int nt = 0; nt < 8; nt++) {
            int c = n0w + nt * 8 + lane * 2;
            Sq[mg * 128 + c] = sq[nt][0];
            Sq[mg * 128 + c + 1] = sq[nt][1];
        }
    }
    __syncthreads();
    {
        int col = tid & 127, half = tid >> 7;
        float s = Sq[half * 256 + col] + Sq[half * 256 + 128 + col];
        Nn[half * 128 + col] = 1.f / fmaxf(sqrtf(s), 1e-12f);
    }
    __syncthreads();

    if (mg < 2) {
#pragma unroll
        for (int mt = 0; mt < 2; mt++) {
            int r0 = m0w + mt * 16 + g;
#pragma unroll
            for (int nt = 0; nt < 8; nt++) {
                int c = n0w + nt * 8 + (lane & 3) * 2;
                float i0 = Nn[c], i1 = Nn[c + 1];
                float v0 = acc[mt][nt][0] * i0, v1 = acc[mt][nt][1] * i1;
                float v2 = acc[mt][nt][2] * i0, v3 = acc[mt][nt][3] * i1;
                float p0 = __shfl_xor_sync(0xffffffffu, v0, 16);
                float p1 = __shfl_xor_sync(0xffffffffu, v1, 16);
                float p2 = __shfl_xor_sync(0xffffffffu, v2, 16);
                float p3 = __shfl_xor_sync(0xffffffffu, v3, 16);
                if (g < 4) {
                    int row0 = (r0 >> 3) * 4 + g;
                    int row1 = ((r0 + 8) >> 3) * 4 + g;
                    *(uint4*)(g_qnt + (size_t)(b * 32 + row0) * HW + n0 + c) =
                        make_uint4(f2tf(v0), f2tf(p0), f2tf(v1), f2tf(p1));
                    *(uint4*)(g_qnt + (size_t)(b * 32 + row1) * HW + n0 + c) =
                        make_uint4(f2tf(v2), f2tf(p2), f2tf(v3), f2tf(p3));
                }
            }
        }
    } else {
#pragma unroll
        for (int mt = 0; mt < 2; mt++) {
            int r0 = m0w + mt * 16 + g - 64;
#pragma unroll
            for (int nt = 0; nt < 8; nt++) {
                int c = n0w + nt * 8 + (lane & 3) * 2;
                float i0 = Nn[128 + c], i1 = Nn[128 + c + 1];
                float v0 = acc[mt][nt][0] * i0, v1 = acc[mt][nt][1] * i1;
                float v2 = acc[mt][nt][2] * i0, v3 = acc[mt][nt][3] * i1;
                float p0 = __shfl_xor_sync(0xffffffffu, v0, 2);
                float p1 = __shfl_xor_sync(0xffffffffu, v1, 2);
                float p2 = __shfl_xor_sync(0xffffffffu, v2, 2);
                float p3 = __shfl_xor_sync(0xffffffffu, v3, 2);
                if ((lane & 2) == 0) {
                    size_t pb = (size_t)((n0 + c) >> 3) * 4 + (c & 3);
                    *(uint4*)(g_knt + (size_t)(b * 64 + r0) * 8192 + pb) =
                        make_uint4(f2tf(v0), f2tf(p0), f2tf(v1), f2tf(p1));
                    *(uint4*)(g_knt + (size_t)(b * 64 + r0 + 8) * 8192 + pb) =
                        make_uint4(f2tf(v2), f2tf(p2), f2tf(v3), f2tf(p3));
                }
            }
        }
    }
}

// ============ K2: v proj + BN + ReLU ============
__global__ void __launch_bounds__(256, 2)
k_v_mma(const float* __restrict__ vs, const float* __restrict__ vb)
{
    extern __shared__ uint2 dynsm[];
    uint2* Asm = dynsm;
    uint2* Bsm = dynsm + 4096;

    const int b = blockIdx.z, co0 = blockIdx.y * 128, n0 = blockIdx.x * 128;
    const int tid = threadIdx.x, lane = tid & 31, w = tid >> 5;
    const int g = lane >> 2, kk = lane & 3;
    const int mg = w >> 1, ng = w & 1;
    const int m0w = mg * 32, n0w = ng * 64;
    const uint32_t aBase = (uint32_t)__cvta_generic_to_shared(dynsm);
    const uint2* xtb = g_xt + (size_t)b * 8 * 16 * HW + n0;

    float acc[2][8][4];
#pragma unroll
    for (int mt = 0; mt < 2; mt++)
#pragma unroll
        for (int nt = 0; nt < 8; nt++)
#pragma unroll
            for (int i = 0; i < 4; i++) acc[mt][nt][i] = 0.f;

#pragma unroll
    for (int i = 0; i < 4; i++) {
        int j = i * 256 + tid;
        int u = j * 2, kbl = u >> 9, r = u & 511;
        cpa16(aBase + u * 8, g_Av + (size_t)kbl * 1024 + co0 * 4 + r);
    }
#pragma unroll
    for (int i = 0; i < 4; i++) {
        int j = i * 256 + tid;
        int kkb = j >> 6, npair = (j & 63) * 2;
        cpa16(aBase + 4096 * 8 + (kkb * 132 + npair) * 8, xtb + (size_t)kkb * HW + npair);
    }
    cpa_commit(); cpa_wait0(); __syncthreads();

    for (int it = 0; it < 8; it++) {
        int cur = it & 1, nxt = cur ^ 1;
        if (it < 7) {
#pragma unroll
            for (int i = 0; i < 4; i++) {
                int j = i * 256 + tid;
                int u = j * 2, kbl = u >> 9, r = u & 511;
                cpa16(aBase + nxt * 16384 + u * 8,
                      g_Av + (size_t)((it + 1) * 4 + kbl) * 1024 + co0 * 4 + r);
            }
#pragma unroll
            for (int i = 0; i < 4; i++) {
                int j = i * 256 + tid;
                int kkb = j >> 6, npair = (j & 63) * 2;
                cpa16(aBase + 4096 * 8 + nxt * 16896 + (kkb * 132 + npair) * 8,
                      xtb + (size_t)((it + 1) * 16 + kkb) * HW + npair);
            }
            cpa_commit();
        }
        const uint2* Ac = Asm + cur * 2048;
        const uint2* Bc = Bsm + cur * 2112;
#pragma unroll
        for (int kb = 0; kb < 4; kb++) {
            uint2 a01[2], a13[2];
#pragma unroll
            for (int mt = 0; mt < 2; mt++) {
                a01[mt] = Ac[(kb * 128 + m0w + mt * 16 + g) * 4 + kk];
                a13[mt] = Ac[(kb * 128 + m0w + mt * 16 + 8 + g) * 4 + kk];
            }
#pragma unroll
            for (int nt = 0; nt < 8; nt++) {
                uint2 bb = Bc[(kb * 4 + kk) * 132 + n0w + nt * 8 + g];
                mma8(acc[0][nt], a01[0], a13[0], bb);
                mma8(acc[1][nt], a01[1], a13[1], bb);
            }
        }
        cpa_wait0(); __syncthreads();
    }

#pragma unroll
    for (int mt = 0; mt < 2; mt++) {
        int co = co0 + m0w + mt * 16 + g;
        float sc0 = vs[co], sh0 = vb[co];
        float sc1 = vs[co + 8], sh1 = vb[co + 8];
#pragma unroll
        for (int nt = 0; nt < 8; nt++) {
            int c = n0w + nt * 8 + (lane & 3) * 2;
            float f0 = fmaxf(fmaf(acc[mt][nt][0], sc0, sh0), 0.f);
            float f1 = fmaxf(fmaf(acc[mt][nt][1], sc0, sh0), 0.f);
            float f2 = fmaxf(fmaf(acc[mt][nt][2], sc1, sh1), 0.f);
            float f3 = fmaxf(fmaf(acc[mt][nt][3], sc1, sh1), 0.f);
            float p0 = __shfl_xor_sync(0xffffffffu, f0, 2);
            float p1 = __shfl_xor_sync(0xffffffffu, f1, 2);
            float p2 = __shfl_xor_sync(0xffffffffu, f2, 2);
            float p3 = __shfl_xor_sync(0xffffffffu, f3, 2);
            if ((lane & 2) == 0) {
                size_t pb = (size_t)((n0 + c) >> 3) * 4 + (c & 3);
                *(uint4*)(g_vt + (size_t)(b * 256 + co) * 8192 + pb) =
                    make_uint4(f2tf(f0), f2tf(p0), f2tf(f1), f2tf(p1));
                *(uint4*)(g_vt + (size_t)(b * 256 + co + 8) * 8192 + pb) =
                    make_uint4(f2tf(f2), f2tf(p2), f2tf(f3), f2tf(p3));
            }
        }
    }
}

// ============ K3: partial sim ============
__global__ void __launch_bounds__(256, 2) k_sim_mma()
{
    extern __shared__ uint2 dynsm[];
    const int b = blockIdx.y, ch = blockIdx.x;
    const int p0 = ch * PIX_PER_CHUNK;
    const int tid = threadIdx.x, lane = tid & 31, w = tid >> 5;
    const int g = lane >> 2, kk = lane & 3;
    const int mg = w >> 2, ng = w & 3;
    const int m0w = mg * 32, n0w = ng * 64;
    const uint32_t smBase = (uint32_t)__cvta_generic_to_shared(dynsm);

    float acc[2][8][4];
#pragma unroll
    for (int mt = 0; mt < 2; mt++)
#pragma unroll
        for (int nt = 0; nt < 8; nt++)
#pragma unroll
            for (int i = 0; i < 4; i++) acc[mt][nt][i] = 0.f;

    auto fill = [&](int it, int stage) {
        int base = (p0 + it * 32) >> 1;
#pragma unroll
        for (int i = 0; i < 2; i++) {
            int j = i * 256 + tid;
            int m = j >> 3, seg = j & 7;
            cpa16(smBase + (stage * 1152 + m * 18 + seg * 2) * 8,
                  g_knt + (size_t)(b * 64 + m) * 8192 + base + seg * 2);
        }
#pragma unroll
        for (int i = 0; i < 8; i++) {
            int j = i * 256 + tid;
            int n = j >> 3, seg = j & 7;
            cpa16(smBase + (2304 + stage * 4608 + n * 18 + seg * 2) * 8,
                  g_vt + (size_t)(b * 256 + n) * 8192 + base + seg * 2);
        }
    };

    fill(0, 0); cpa_commit(); cpa_wait0(); __syncthreads();

    for (int it = 0; it < 8; it++) {
        int cur = it & 1, nxt = cur ^ 1;
        if (it < 7) { fill(it + 1, nxt); cpa_commit(); }
        const uint2* Ac = dynsm + cur * 1152;
        const uint2* Bc = dynsm + 2304 + cur * 4608;
#pragma unroll
        for (int kb = 0; kb < 4; kb++) {
            uint2 a01[2], a13[2];
#pragma unroll
            for (int mt = 0; mt < 2; mt++) {
                a01[mt] = Ac[(m0w + mt * 16 + g) * 18 + kb * 4 + kk];
                a13[mt] = Ac[(m0w + mt * 16 + 8 + g) * 18 + kb * 4 + kk];
            }
#pragma unroll
            for (int nt = 0; nt < 8; nt++) {
                uint2 bb = Bc[(n0w + nt * 8 + g) * 18 + kb * 4 + kk];
                mma8(acc[0][nt], a01[0], a13[0], bb);
                mma8(acc[1][nt], a01[1], a13[1], bb);
            }
        }
        cpa_wait0(); __syncthreads();
    }

    float* outp = g_simp + (size_t)(b * NCH + ch) * CQK * CIN;
#pragma unroll
    for (int mt = 0; mt < 2; mt++) {
        int r = m0w + mt * 16 + g;
#pragma unroll
        for (int nt = 0; nt < 8; nt++) {
            int c = n0w + nt * 8 + (lane & 3) * 2;
            *(float2*)&outp[(size_t)r * CIN + c] = make_float2(acc[mt][nt][0], acc[mt][nt][1]);
            *(float2*)&outp[(size_t)(r + 8) * CIN + c] = make_float2(acc[mt][nt][2], acc[mt][nt][3]);
        }
    }
}

__global__ void k_simreduce()
{
    int o = blockIdx.x * 256 + threadIdx.x;
    int b = o / (CQK * CIN);
    int cv = o - b * (CQK * CIN);
    float s = 0.f;
#pragma unroll 8
    for (int ch = 0; ch < NCH; ch++)
        s += g_simp[((size_t)(b * NCH + ch)) * CQK * CIN + cv];
    g_sim[o] = s;
}

__global__ void k_m2(const float* __restrict__ oW)
{
    __shared__ float ssm[CIN];
    const int b = blockIdx.x >> 6;
    const int c = blockIdx.x & 63;
    const int o = threadIdx.x;
    ssm[o] = g_sim[((size_t)b * CQK + c) * CIN + o];
    __syncthreads();
    float s = 0.f;
#pragma unroll 8
    for (int v = 0; v < CIN; v++) s = fmaf(oW[(size_t)o * CIN + v], ssm[v], s);
    int krow = c >> 3, rem = c & 7;
    int kkv = rem & 3;
    ((uint32_t*)g_AM2)[(size_t)b * 16384 + (krow * 256 + o) * 8 + kkv * 2 + (rem >> 2)] = f2tf(s);
}

// ============ K4: ctx mma -> fuse -> fp16 pairs g_fth ============
__global__ void __launch_bounds__(256, 2)
k_ctx_mma(const float* __restrict__ x, const float* __restrict__ up,
          const float* __restrict__ os, const float* __restrict__ ob)
{
    extern __shared__ uint2 dynsm[];
    uint2* Asm = dynsm;
    uint2* Bsm = dynsm + 4096;
    float* upH = (float*)(dynsm + 8320);

    const int b = blockIdx.z;
    const int co0 = blockIdx.y * 128;
    const int h = blockIdx.x;
    const int n0 = h * Ww;
    const int tid = threadIdx.x, lane = tid & 31, w = tid >> 5;
    const int g = lane >> 2, kk = lane & 3;
    const int mg = w >> 1, ng = w & 1;
    const int m0w = mg * 32, n0w = ng * 64;
    const uint32_t aBase = (uint32_t)__cvta_generic_to_shared(dynsm);

#pragma unroll
    for (int i = 0; i < 8; i++) {
        int jj = i * 256 + tid;
        int u = jj * 2;
        int kk2 = u & 3, m = (u >> 2) & 127, krow = u >> 9;
        cpa16(aBase + u * 8, g_AM2 + (size_t)b * 8192 + krow * 1024 + (co0 + m) * 4 + kk2);
    }
#pragma unroll
    for (int i = 0; i < 8; i++) {
        int jj = i * 256 + tid;
        int row = jj >> 6, colpair = (jj & 63) * 2;
        cpa16(aBase + 4096 * 8 + (row * 132 + colpair) * 8,
              g_qnt + (size_t)(b * 32 + row) * HW + n0 + colpair);
    }
    cpa_commit();

    {
        float shf = 0.5f * h - 0.25f;
        int h0 = (int)floorf(shf);
        float wh1 = shf - (float)h0;
        int h0c = h0 < 0 ? 0 : h0;
        int h1c = (h0 + 1) > 63 ? 63 : (h0 + 1);
        const float* ub = up + ((size_t)(b * CIN + co0)) * 64 * 64;
#pragma unroll
        for (int i = 0; i < 32; i++) {
            int idx = i * 256 + tid;
            int r = idx >> 6, sw = idx & 63;
            upH[r * 64 + sw] = (1.f - wh1) * ub[(r * 64 + h0c) * 64 + sw]
                             + wh1 * ub[(r * 64 + h1c) * 64 + sw];
        }
    }
    cpa_wait0(); __syncthreads();

    float acc[2][8][4];
#pragma unroll
    for (int mt = 0; mt < 2; mt++)
#pragma unroll
        for (int nt = 0; nt < 8; nt++)
#pragma unroll
            for (int i = 0; i < 4; i++) acc[mt][nt][i] = 0.f;

#pragma unroll
    for (int s = 0; s < 8; s++) {
        uint2 a01[2], a13[2];
#pragma unroll
        for (int mt = 0; mt < 2; mt++) {
            a01[mt] = Asm[(s * 128 + m0w + mt * 16 + g) * 4 + kk];
            a13[mt] = Asm[(s * 128 + m0w + mt * 16 + 8 + g) * 4 + kk];
        }
#pragma unroll
        for (int nt = 0; nt < 8; nt++) {
            uint2 bb = Bsm[(s * 4 + kk) * 132 + n0w + nt * 8 + g];
            mma8(acc[0][nt], a01[0], a13[0], bb);
            mma8(acc[1][nt], a01[1], a13[1], bb);
        }
    }

    // epilogue: BN+ReLU + residual + upsample -> fp16 channel pairs in g_fth
    const float* xb = x + ((size_t)b * CIN + co0) * HW + n0;
#pragma unroll
    for (int mt = 0; mt < 2; mt++) {
        int m = m0w + mt * 16 + g;           // m & 15 == g
        int co = co0 + m;
        float sc0 = os[co], sh0 = ob[co];
        float sc1 = os[co + 8], sh1 = ob[co + 8];
        int ch16 = co >> 4;
        int jidx = g >> 1;
#pragma unroll
        for (int nt = 0; nt < 8; nt++) {
            int c0 = n0w + nt * 8 + (lane & 3) * 2;
            int c1 = c0 + 1;
            float sw0 = 0.5f * c0 - 0.25f, sw1 = 0.5f * c1 - 0.25f;
            int wa0 = (int)floorf(sw0), wa1 = (int)floorf(sw1);
            float t0 = sw0 - (float)wa0, t1 = sw1 - (float)wa1;
            int w00 = wa0 < 0 ? 0 : wa0, w01 = (wa0 + 1) > 63 ? 63 : (wa0 + 1);
            int w10 = wa1 < 0 ? 0 : wa1, w11 = (wa1 + 1) > 63 ? 63 : (wa1 + 1);

            float u0a = (1.f - t0) * upH[m * 64 + w00] + t0 * upH[m * 64 + w01];
            float u1a = (1.f - t1) * upH[m * 64 + w10] + t1 * upH[m * 64 + w11];
            float u0b = (1.f - t0) * upH[(m + 8) * 64 + w00] + t0 * upH[(m + 8) * 64 + w01];
            float u1b = (1.f - t1) * upH[(m + 8) * 64 + w10] + t1 * upH[(m + 8) * 64 + w11];

            float f0 = fmaxf(fmaf(acc[mt][nt][0], sc0, sh0), 0.f) + xb[(size_t)m * HW + c0] + u0a;
            float f1 = fmaxf(fmaf(acc[mt][nt][1], sc0, sh0), 0.f) + xb[(size_t)m * HW + c1] + u1a;
            float f2 = fmaxf(fmaf(acc[mt][nt][2], sc1, sh1), 0.f) + xb[(size_t)(m + 8) * HW + c0] + u0b;
            float f3 = fmaxf(fmaf(acc[mt][nt][3], sc1, sh1), 0.f) + xb[(size_t)(m + 8) * HW + c1] + u1b;

            // pair adjacent channels (g even keeps lo, partner g^1 supplies hi)
            float p0 = __shfl_xor_sync(0xffffffffu, f0, 4);
            float p1 = __shfl_xor_sync(0xffffffffu, f1, 4);
            float p2 = __shfl_xor_sync(0xffffffffu, f2, 4);
            float p3 = __shfl_xor_sync(0xffffffffu, f3, 4);
            if ((g & 1) == 0) {
                size_t base = (((size_t)(b * 16 + ch16) * 4 + jidx) * 130 + h + 1) * 132 + 1;
                g_fth[base + c0] = make_uint2(pkh2(f0, p0), pkh2(f2, p2));
                g_fth[base + c1] = make_uint2(pkh2(f1, p1), pkh2(f3, p3));
            }
        }
    }
}

// ============ K5: 3x3 conv, fp16 m16n8k16, 16-stage pipeline ============
// dyn smem: Ism 2x2112 + Wsm 2x2304 uint2 = 70656 B
__global__ void __launch_bounds__(256, 2)
k_conv_h(const float* __restrict__ ss, const float* __restrict__ sb,
         float* __restrict__ out)
{
    extern __shared__ uint2 csm[];
    uint2* Ism = csm;            // 2 x 2112: [row4][j4][132]
    uint2* Wsm = csm + 4224;     // 2 x 2304: [dh*3+tap][co64*4]

    const int h0 = blockIdx.x * 2;
    const int co0 = blockIdx.y * 64;
    const int b = blockIdx.z;
    const int tid = threadIdx.x, lane = tid & 31, w = tid >> 5;
    const int g = lane >> 2, kk = lane & 3;
    const int mg = w >> 2, ng = w & 3;
    const int m0w = mg * 32, n0w = ng * 64;
    const uint32_t smBase = (uint32_t)__cvta_generic_to_shared(csm);

    float acc[2][8][4];
#pragma unroll
    for (int mt = 0; mt < 2; mt++)
#pragma unroll
        for (int nt = 0; nt < 8; nt++)
#pragma unroll
            for (int i = 0; i < 4; i++) acc[mt][nt][i] = 0.f;

    const uint2* ftb = g_fth + (size_t)b * 16 * 4 * 130 * 132;

    auto fill = [&](int ch, int stage) {
        for (int j = tid; j < 1040; j += 256) {
            int rowplane = j / 65;             // row*4 + jj
            int colpair = (j - rowplane * 65) * 2;
            int row = rowplane >> 2, jj = rowplane & 3;
            cpa16(smBase + (stage * 2112 + (row * 4 + jj) * 132 + colpair) * 8,
                  ftb + ((size_t)(ch * 4 + jj) * 130 + h0 + row) * 132 + colpair);
        }
        for (int j = tid; j < 1152; j += 256) {
            int u = j * 2;
            int grp = u >> 8, off = u & 255;   // grp = dh*3+tap
            int dh = grp / 3, tap = grp - dh * 3;
            cpa16(smBase + (4224 + stage * 2304 + grp * 256 + off) * 8,
                  g_wph + (size_t)((dh * 16 + ch) * 3 + tap) * 512 + co0 * 4 + off);
        }
    };

    fill(0, 0);
    cpa_commit();
    cpa_wait0();
    __syncthreads();

    for (int it = 0; it < 16; it++) {
        int cur = it & 1, nxt = cur ^ 1;
        if (it < 15) { fill(it + 1, nxt); cpa_commit(); }

        const uint2* Ic = Ism + cur * 2112;
        const uint2* Wc = Wsm + cur * 2304;
#pragma unroll
        for (int dh = 0; dh < 3; dh++) {
#pragma unroll
            for (int tap = 0; tap < 3; tap++) {
                const uint2* wb = Wc + (dh * 3 + tap) * 256;
                uint2 alo[2], ahi[2];
#pragma unroll
                for (int mt = 0; mt < 2; mt++) {
                    alo[mt] = wb[(m0w + mt * 16 + g) * 4 + kk];
                    ahi[mt] = wb[(m0w + mt * 16 + 8 + g) * 4 + kk];
                }
#pragma unroll
                for (int nt = 0; nt < 8; nt++) {
                    int n = n0w + nt * 8 + g;
                    int rrow = n >> 7, wx = n & 127;
                    uint2 bb = Ic[((rrow + dh) * 4 + kk) * 132 + wx + tap];
                    mma16(acc[0][nt], alo[0], ahi[0], bb);
                    mma16(acc[1][nt], alo[1], ahi[1], bb);
                }
            }
        }
        cpa_wait0();
        __syncthreads();
    }

#pragma unroll
    for (int mt = 0; mt < 2; mt++) {
        int co = co0 + m0w + mt * 16 + g;
        float sc0 = ss[co], sh0 = sb[co];
        float sc1 = ss[co + 8], sh1 = sb[co + 8];
#pragma unroll
        for (int nt = 0; nt < 8; nt++) {
            int n = n0w + nt * 8 + (lane & 3) * 2;
            int r = n >> 7, wx = n & 127;
            float* o0p = out + (((size_t)b * CS + co) * Hh + h0 + r) * Ww + wx;
            float* o1p = out + (((size_t)b * CS + co + 8) * Hh + h0 + r) * Ww + wx;
            float2 o0 = make_float2(fmaxf(fmaf(acc[mt][nt][0], sc0, sh0), 0.f),
                                    fmaxf(fmaf(acc[mt][nt][1], sc0, sh0), 0.f));
            float2 o1 = make_float2(fmaxf(fmaf(acc[mt][nt][2], sc1, sh1), 0.f),
                                    fmaxf(fmaf(acc[mt][nt][3], sc1, sh1), 0.f));
            *(float2*)o0p = o0;
            *(float2*)o1p = o1;
        }
    }
}

// ============================================================
extern "C" void kernel_launch(void* const* d_in, const int* in_sizes, int n_in,
                              void* d_out, int out_size)
{
    (void)in_sizes; (void)n_in; (void)out_size;
    const float* x        = (const float*)d_in[0];
    const float* up       = (const float*)d_in[1];
    const float* qW       = (const float*)d_in[2];
    const float* q_scale  = (const float*)d_in[3];
    const float* q_shift  = (const float*)d_in[4];
    const float* kW       = (const float*)d_in[5];
    const float* k_scale  = (const float*)d_in[6];
    const float* k_shift  = (const float*)d_in[7];
    const float* vW       = (const float*)d_in[8];
    const float* v_scale  = (const float*)d_in[9];
    const float* v_shift  = (const float*)d_in[10];
    const float* oW       = (const float*)d_in[11];
    const float* o_scale  = (const float*)d_in[12];
    const float* o_shift  = (const float*)d_in[13];
    const float* sW       = (const float*)d_in[14];
    const float* s_scale  = (const float*)d_in[15];
    const float* s_shift  = (const float*)d_in[16];
    float* out = (float*)d_out;

    cudaFuncSetAttribute(k_qk_mma,  cudaFuncAttributeMaxDynamicSharedMemorySize, 69632);
    cudaFuncSetAttribute(k_v_mma,   cudaFuncAttributeMaxDynamicSharedMemorySize, 66560);
    cudaFuncSetAttribute(k_sim_mma, cudaFuncAttributeMaxDynamicSharedMemorySize, 92160);
    cudaFuncSetAttribute(k_ctx_mma, cudaFuncAttributeMaxDynamicSharedMemorySize, 99328);
    cudaFuncSetAttribute(k_conv_h,  cudaFuncAttributeMaxDynamicSharedMemorySize, 70656);

    k_pack_qk<<<64, 256>>>(qW, kW);
    k_pack_v<<<128, 256>>>(vW);
    k_pack_conv<<<288, 256>>>(sW);
    k_packx<<<8192, 256>>>(x);
    k_qk_mma<<<dim3(HW / 128, Bn), 256, 69632>>>(q_scale, q_shift, k_scale, k_shift);
    k_v_mma<<<dim3(HW / 128, 2, Bn), 256, 66560>>>(v_scale, v_shift);
    k_sim_mma<<<dim3(NCH, Bn), 256, 92160>>>();
    k_simreduce<<<256, 256>>>();
    k_m2<<<Bn * CQK, 256>>>(oW);
    k_ctx_mma<<<dim3(Hh, 2, Bn), 256, 99328>>>(x, up, o_scale, o_shift);
    k_conv_h<<<dim3(Hh / 2, 2, Bn), 256, 70656>>>(s_scale, s_shift, out);
}

// round 9
// speedup vs baseline: 1.5241x; 1.1554x over previous
#include <cuda_runtime.h>
#include <math.h>
#include <stdint.h>

#define Bn   4
#define CIN  256
#define CQK  64
#define CS   128
#define Hh   128
#define Ww   128
#define HW   (Hh*Ww)
#define NCH  64
#define PIX_PER_CHUNK (HW/NCH)

__device__ float g_simp[Bn*NCH*CQK*CIN];
__device__ float g_sim [Bn*CQK*CIN];

// fp16-pair operand buffers. entry uint2 = {h2(k0,k0+1), h2(k0+8,k0+9)}
__device__ __align__(16) uint2 g_Aqk[8192];               // [it8][kb2][m128][kk4]
__device__ __align__(16) uint2 g_Av [16384];              // [kb16 16][m256][kk4]
__device__ __align__(16) uint2 g_xt [Bn*8*8*HW];          // [(b*8+it)*8+kkb][n]
__device__ __align__(16) uint2 g_knt[Bn*64*1024*4];       // [b][m64][kb16 1024][kk4]
__device__ __align__(16) uint2 g_vt [Bn*1024*4*256];      // [b][kb16 1024][kk4][n256]
// tf32 pair buffers for ctx path
__device__ __align__(16) uint2 g_AM2[Bn*8192];
__device__ __align__(16) uint2 g_qnt[Bn*32*HW];
// fp16 conv path (unchanged from R8)
__device__ __align__(16) uint2 g_wph[73728];
__device__ __align__(16) uint2 g_fth[Bn*16*4*130*132];

__device__ __forceinline__ uint32_t f2tf(float f) {
    uint32_t u; asm("cvt.rna.tf32.f32 %0, %1;" : "=r"(u) : "f"(f)); return u;
}
__device__ __forceinline__ uint32_t pkh2(float lo, float hi) {
    uint32_t r; asm("cvt.rn.f16x2.f32 %0, %1, %2;" : "=r"(r) : "f"(hi), "f"(lo)); return r;
}
__device__ __forceinline__ void mma8(float* c, uint2 a01, uint2 a13, uint2 b) {
    asm volatile(
        "mma.sync.aligned.m16n8k8.row.col.f32.tf32.tf32.f32 "
        "{%0,%1,%2,%3}, {%4,%5,%6,%7}, {%8,%9}, {%0,%1,%2,%3};"
        : "+f"(c[0]), "+f"(c[1]), "+f"(c[2]), "+f"(c[3])
        : "r"(a01.x), "r"(a13.x), "r"(a01.y), "r"(a13.y), "r"(b.x), "r"(b.y));
}
__device__ __forceinline__ void mma16(float* c, uint2 alo, uint2 ahi, uint2 b) {
    asm volatile(
        "mma.sync.aligned.m16n8k16.row.col.f32.f16.f16.f32 "
        "{%0,%1,%2,%3}, {%4,%5,%6,%7}, {%8,%9}, {%0,%1,%2,%3};"
        : "+f"(c[0]), "+f"(c[1]), "+f"(c[2]), "+f"(c[3])
        : "r"(alo.x), "r"(ahi.x), "r"(alo.y), "r"(ahi.y), "r"(b.x), "r"(b.y));
}
__device__ __forceinline__ void cpa16(uint32_t saddr, const void* g) {
    asm volatile("cp.async.cg.shared.global [%0], [%1], 16;" :: "r"(saddr), "l"(g));
}
__device__ __forceinline__ void cpa_commit() { asm volatile("cp.async.commit_group;"); }
__device__ __forceinline__ void cpa_wait0()  { asm volatile("cp.async.wait_group 0;" ::: "memory"); }

// ============ pack kernels ============
__global__ void k_pack_qk(const float* __restrict__ qW, const float* __restrict__ kW)
{
    int idx = blockIdx.x * 256 + threadIdx.x;   // < 8192
    int kk = idx & 3, m = (idx >> 2) & 127, kb = (idx >> 9) & 1, it = idx >> 10;
    int K0 = it * 32 + kb * 16 + kk * 2;
    const float* wr = (m < 64) ? (qW + (size_t)m * CIN) : (kW + (size_t)(m - 64) * CIN);
    g_Aqk[idx] = make_uint2(pkh2(wr[K0], wr[K0 + 1]), pkh2(wr[K0 + 8], wr[K0 + 9]));
}
__global__ void k_pack_v(const float* __restrict__ vW)
{
    int idx = blockIdx.x * 256 + threadIdx.x;   // < 16384
    int kk = idx & 3, m = (idx >> 2) & 255, kb16 = idx >> 10;
    int K0 = kb16 * 16 + kk * 2;
    const float* wr = vW + (size_t)m * CIN;
    g_Av[idx] = make_uint2(pkh2(wr[K0], wr[K0 + 1]), pkh2(wr[K0 + 8], wr[K0 + 9]));
}
__global__ void k_pack_conv(const float* __restrict__ sW)
{
    int idx = blockIdx.x * 256 + threadIdx.x;   // < 73728
    int r = idx & 511, s = idx >> 9;
    int j = r & 3, co = r >> 2;
    int tap = s % 3, t2 = s / 3, ch = t2 & 15, dh = t2 >> 4;
    int ci = ch * 16 + j * 2;
    const float* wp = sW + ((size_t)co * CIN + ci) * 9 + dh * 3 + tap;
    g_wph[idx] = make_uint2(pkh2(wp[0], wp[9]), pkh2(wp[8 * 9], wp[9 * 9]));
}
// x -> fp16 pair layout
__global__ void k_packx(const float* __restrict__ x)
{
    int idx = blockIdx.x * 256 + threadIdx.x;   // < 1048576
    int n4 = (idx & 4095) * 4;
    int kkb = (idx >> 12) & 7;
    int it = (idx >> 15) & 7;
    int b = idx >> 18;
    int kb = kkb >> 2, kk = kkb & 3;
    int K0 = it * 32 + kb * 16 + kk * 2;
    const float* xb = x + ((size_t)b * CIN + K0) * HW + n4;
    float4 r0 = *(const float4*)xb;
    float4 r1 = *(const float4*)(xb + HW);
    float4 r8 = *(const float4*)(xb + 8 * HW);
    float4 r9 = *(const float4*)(xb + 9 * HW);
    uint2* dst = g_xt + ((size_t)((b * 8 + it) * 8 + kkb)) * HW + n4;
    *(uint4*)dst = make_uint4(pkh2(r0.x, r1.x), pkh2(r8.x, r9.x),
                              pkh2(r0.y, r1.y), pkh2(r8.y, r9.y));
    *(uint4*)(dst + 2) = make_uint4(pkh2(r0.z, r1.z), pkh2(r8.z, r9.z),
                                    pkh2(r0.w, r1.w), pkh2(r8.w, r9.w));
}

// ============ K1: q,k proj + BN + L2 norm (fp16 mainloop) ============
// dyn smem: A 2x1024 + B 2x1056 uint2 + Sq 512 f32 + Nn 256 f32 = 36352 B
__global__ void __launch_bounds__(256, 2)
k_qk_mma(const float* __restrict__ qs, const float* __restrict__ qb,
         const float* __restrict__ kscale, const float* __restrict__ kshift)
{
    extern __shared__ uint2 dynsm[];
    uint2* Asm = dynsm;                // 2 x 1024
    uint2* Bsm = dynsm + 2048;         // 2 x 1056
    float* Sq  = (float*)(dynsm + 4160);
    float* Nn  = Sq + 512;

    const int b = blockIdx.y, n0 = blockIdx.x * 128;
    const int tid = threadIdx.x, lane = tid & 31, w = tid >> 5;
    const int g = lane >> 2, kk = lane & 3;
    const int mg = w >> 1, ng = w & 1;
    const int m0w = mg * 32, n0w = ng * 64;
    const uint32_t aBase = (uint32_t)__cvta_generic_to_shared(dynsm);
    const uint2* xtb = g_xt + (size_t)b * 8 * 8 * HW + n0;

    float acc[2][8][4];
#pragma unroll
    for (int mt = 0; mt < 2; mt++)
#pragma unroll
        for (int nt = 0; nt < 8; nt++)
#pragma unroll
            for (int i = 0; i < 4; i++) acc[mt][nt][i] = 0.f;

    auto fill = [&](int it, int stage) {
#pragma unroll
        for (int i = 0; i < 2; i++) {
            int j = i * 256 + tid;             // < 512 chunks for A
            cpa16(aBase + (stage * 1024 + j * 2) * 8, g_Aqk + it * 1024 + j * 2);
        }
#pragma unroll
        for (int i = 0; i < 2; i++) {
            int j = i * 256 + tid;             // < 512 chunks for B
            int kkb = j >> 6, npair = (j & 63) * 2;
            cpa16(aBase + (2048 + stage * 1056 + kkb * 132 + npair) * 8,
                  xtb + (size_t)((it * 8) + kkb) * HW + npair);
        }
    };

    fill(0, 0); cpa_commit(); cpa_wait0(); __syncthreads();

    for (int it = 0; it < 8; it++) {
        int cur = it & 1, nxt = cur ^ 1;
        if (it < 7) { fill(it + 1, nxt); cpa_commit(); }
        const uint2* Ac = Asm + cur * 1024;
        const uint2* Bc = Bsm + cur * 1056;
#pragma unroll
        for (int kb = 0; kb < 2; kb++) {
            uint2 alo[2], ahi[2];
#pragma unroll
            for (int mt = 0; mt < 2; mt++) {
                alo[mt] = Ac[(kb * 128 + m0w + mt * 16 + g) * 4 + kk];
                ahi[mt] = Ac[(kb * 128 + m0w + mt * 16 + 8 + g) * 4 + kk];
            }
#pragma unroll
            for (int nt = 0; nt < 8; nt++) {
                uint2 bb = Bc[(kb * 4 + kk) * 132 + n0w + nt * 8 + g];
                mma16(acc[0][nt], alo[0], ahi[0], bb);
                mma16(acc[1][nt], alo[1], ahi[1], bb);
            }
        }
        cpa_wait0(); __syncthreads();
    }

    // BN + column sums of squares
    float sq[8][2];
#pragma unroll
    for (int nt = 0; nt < 8; nt++) { sq[nt][0] = 0.f; sq[nt][1] = 0.f; }
#pragma unroll
    for (int mt = 0; mt < 2; mt++) {
        int r0 = m0w + mt * 16 + g, r1 = r0 + 8;
        bool isq = (r0 < 64);
        float sc0 = isq ? qs[r0] : kscale[r0 - 64];
        float sh0 = isq ? qb[r0] : kshift[r0 - 64];
        float sc1 = isq ? qs[r1] : kscale[r1 - 64];
        float sh1 = isq ? qb[r1] : kshift[r1 - 64];
#pragma unroll
        for (int nt = 0; nt < 8; nt++) {
            float v0 = fmaf(acc[mt][nt][0], sc0, sh0);
            float v1 = fmaf(acc[mt][nt][1], sc0, sh0);
            float v2 = fmaf(acc[mt][nt][2], sc1, sh1);
            float v3 = fmaf(acc[mt][nt][3], sc1, sh1);
            acc[mt][nt][0] = v0; acc[mt][nt][1] = v1;
            acc[mt][nt][2] = v2; acc[mt][nt][3] = v3;
            sq[nt][0] += v0 * v0 + v2 * v2;
            sq[nt][1] += v1 * v1 + v3 * v3;
        }
    }
#pragma unroll
    for (int nt = 0; nt < 8; nt++) {
#pragma unroll
        for (int o = 4; o < 32; o <<= 1) {
            sq[nt][0] += __shfl_xor_sync(0xffffffffu, sq[nt][0], o);
            sq[nt][1] += __shfl_xor_sync(0xffffffffu, sq[nt][1], o);
        }
    }
    if (lane < 4) {
#pragma unroll
        for (int nt = 0; nt < 8; nt++) {
            int c = n0w + nt * 8 + lane * 2;
            Sq[mg * 128 + c] = sq[nt][0];
            Sq[mg * 128 + c + 1] = sq[nt][1];
        }
    }
    __syncthreads();
    {
        int col = tid & 127, half = tid >> 7;
        float s = Sq[half * 256 + col] + Sq[half * 256 + 128 + col];
        Nn[half * 128 + col] = 1.f / fmaxf(sqrtf(s), 1e-12f);
    }
    __syncthreads();

    if (mg < 2) {
        // q half -> g_qnt (tf32 channel pairs, for ctx)
#pragma unroll
        for (int mt = 0; mt < 2; mt++) {
            int r0 = m0w + mt * 16 + g;
#pragma unroll
            for (int nt = 0; nt < 8; nt++) {
                int c = n0w + nt * 8 + (lane & 3) * 2;
                float i0 = Nn[c], i1 = Nn[c + 1];
                float v0 = acc[mt][nt][0] * i0, v1 = acc[mt][nt][1] * i1;
                float v2 = acc[mt][nt][2] * i0, v3 = acc[mt][nt][3] * i1;
                float p0 = __shfl_xor_sync(0xffffffffu, v0, 16);
                float p1 = __shfl_xor_sync(0xffffffffu, v1, 16);
                float p2 = __shfl_xor_sync(0xffffffffu, v2, 16);
                float p3 = __shfl_xor_sync(0xffffffffu, v3, 16);
                if (g < 4) {
                    int row0 = (r0 >> 3) * 4 + g;
                    int row1 = ((r0 + 8) >> 3) * 4 + g;
                    *(uint4*)(g_qnt + (size_t)(b * 32 + row0) * HW + n0 + c) =
                        make_uint4(f2tf(v0), f2tf(p0), f2tf(v1), f2tf(p1));
                    *(uint4*)(g_qnt + (size_t)(b * 32 + row1) * HW + n0 + c) =
                        make_uint4(f2tf(v2), f2tf(p2), f2tf(v3), f2tf(p3));
                }
            }
        }
    } else {
        // k half -> g_knt fp16 pairs, all in-thread
#pragma unroll
        for (int mt = 0; mt < 2; mt++) {
            int r0 = m0w + mt * 16 + g - 64;
#pragma unroll
            for (int nt = 0; nt < 8; nt += 2) {
                int c0 = n0w + nt * 8 + (lane & 3) * 2;
                int kbpix = (n0 + c0) >> 4, kkp = lane & 3;
                float i0 = Nn[128 + c0], i1 = Nn[128 + c0 + 1];
                float i8 = Nn[128 + c0 + 8], i9 = Nn[128 + c0 + 9];
                float a0 = acc[mt][nt][0] * i0,     a1 = acc[mt][nt][1] * i1;
                float b0 = acc[mt][nt + 1][0] * i8, b1 = acc[mt][nt + 1][1] * i9;
                float a2 = acc[mt][nt][2] * i0,     a3 = acc[mt][nt][3] * i1;
                float b2 = acc[mt][nt + 1][2] * i8, b3 = acc[mt][nt + 1][3] * i9;
                g_knt[((size_t)(b * 64 + r0) * 1024 + kbpix) * 4 + kkp] =
                    make_uint2(pkh2(a0, a1), pkh2(b0, b1));
                g_knt[((size_t)(b * 64 + r0 + 8) * 1024 + kbpix) * 4 + kkp] =
                    make_uint2(pkh2(a2, a3), pkh2(b2, b3));
            }
        }
    }
}

// ============ K2: v proj + BN + ReLU (fp16 mainloop) -> g_vt fp16 ============
// dyn smem: A 2x1024 + B 2x1056 uint2 = 33280 B
__global__ void __launch_bounds__(256, 2)
k_v_mma(const float* __restrict__ vs, const float* __restrict__ vb)
{
    extern __shared__ uint2 dynsm[];
    uint2* Asm = dynsm;
    uint2* Bsm = dynsm + 2048;

    const int b = blockIdx.z, co0 = blockIdx.y * 128, n0 = blockIdx.x * 128;
    const int tid = threadIdx.x, lane = tid & 31, w = tid >> 5;
    const int g = lane >> 2, kk = lane & 3;
    const int mg = w >> 1, ng = w & 1;
    const int m0w = mg * 32, n0w = ng * 64;
    const uint32_t aBase = (uint32_t)__cvta_generic_to_shared(dynsm);
    const uint2* xtb = g_xt + (size_t)b * 8 * 8 * HW + n0;

    float acc[2][8][4];
#pragma unroll
    for (int mt = 0; mt < 2; mt++)
#pragma unroll
        for (int nt = 0; nt < 8; nt++)
#pragma unroll
            for (int i = 0; i < 4; i++) acc[mt][nt][i] = 0.f;

    auto fill = [&](int it, int stage) {
#pragma unroll
        for (int i = 0; i < 2; i++) {
            int j = i * 256 + tid;
            int kb = j >> 8, r = (j & 255) * 2;
            cpa16(aBase + (stage * 1024 + kb * 512 + r) * 8,
                  g_Av + (size_t)(it * 2 + kb) * 1024 + co0 * 4 + r);
        }
#pragma unroll
        for (int i = 0; i < 2; i++) {
            int j = i * 256 + tid;
            int kkb = j >> 6, npair = (j & 63) * 2;
            cpa16(aBase + (2048 + stage * 1056 + kkb * 132 + npair) * 8,
                  xtb + (size_t)((it * 8) + kkb) * HW + npair);
        }
    };

    fill(0, 0); cpa_commit(); cpa_wait0(); __syncthreads();

    for (int it = 0; it < 8; it++) {
        int cur = it & 1, nxt = cur ^ 1;
        if (it < 7) { fill(it + 1, nxt); cpa_commit(); }
        const uint2* Ac = Asm + cur * 1024;
        const uint2* Bc = Bsm + cur * 1056;
#pragma unroll
        for (int kb = 0; kb < 2; kb++) {
            uint2 alo[2], ahi[2];
#pragma unroll
            for (int mt = 0; mt < 2; mt++) {
                alo[mt] = Ac[(kb * 128 + m0w + mt * 16 + g) * 4 + kk];
                ahi[mt] = Ac[(kb * 128 + m0w + mt * 16 + 8 + g) * 4 + kk];
            }
#pragma unroll
            for (int nt = 0; nt < 8; nt++) {
                uint2 bb = Bc[(kb * 4 + kk) * 132 + n0w + nt * 8 + g];
                mma16(acc[0][nt], alo[0], ahi[0], bb);
                mma16(acc[1][nt], alo[1], ahi[1], bb);
            }
        }
        cpa_wait0(); __syncthreads();
    }

    // epilogue: BN+ReLU -> fp16 pixel pairs, all in-thread
#pragma unroll
    for (int mt = 0; mt < 2; mt++) {
        int co = co0 + m0w + mt * 16 + g;
        float sc0 = vs[co], sh0 = vb[co];
        float sc1 = vs[co + 8], sh1 = vb[co + 8];
#pragma unroll
        for (int nt = 0; nt < 8; nt += 2) {
            int c0 = n0w + nt * 8 + (lane & 3) * 2;
            int kbpix = (n0 + c0) >> 4, kkp = lane & 3;
            float a0 = fmaxf(fmaf(acc[mt][nt][0], sc0, sh0), 0.f);
            float a1 = fmaxf(fmaf(acc[mt][nt][1], sc0, sh0), 0.f);
            float b0 = fmaxf(fmaf(acc[mt][nt + 1][0], sc0, sh0), 0.f);
            float b1 = fmaxf(fmaf(acc[mt][nt + 1][1], sc0, sh0), 0.f);
            float a2 = fmaxf(fmaf(acc[mt][nt][2], sc1, sh1), 0.f);
            float a3 = fmaxf(fmaf(acc[mt][nt][3], sc1, sh1), 0.f);
            float b2 = fmaxf(fmaf(acc[mt][nt + 1][2], sc1, sh1), 0.f);
            float b3 = fmaxf(fmaf(acc[mt][nt + 1][3], sc1, sh1), 0.f);
            g_vt[(((size_t)b * 1024 + kbpix) * 4 + kkp) * 256 + co] =
                make_uint2(pkh2(a0, a1), pkh2(b0, b1));
            g_vt[(((size_t)b * 1024 + kbpix) * 4 + kkp) * 256 + co + 8] =
                make_uint2(pkh2(a2, a3), pkh2(b2, b3));
        }
    }
}

// ============ K3: partial sim = kn @ v^T (fp16) ============
// dyn smem: A 2x512 + B 2x2080 uint2 = 41472 B
__global__ void __launch_bounds__(256, 2) k_sim_mma()
{
    extern __shared__ uint2 dynsm[];
    const int b = blockIdx.y, ch = blockIdx.x;
    const int kbp0 = (ch * PIX_PER_CHUNK) >> 4;
    const int tid = threadIdx.x, lane = tid & 31, w = tid >> 5;
    const int g = lane >> 2, kk = lane & 3;
    const int mg = w >> 2, ng = w & 3;
    const int m0w = mg * 32, n0w = ng * 64;
    const uint32_t smBase = (uint32_t)__cvta_generic_to_shared(dynsm);

    float acc[2][8][4];
#pragma unroll
    for (int mt = 0; mt < 2; mt++)
#pragma unroll
        for (int nt = 0; nt < 8; nt++)
#pragma unroll
            for (int i = 0; i < 4; i++) acc[mt][nt][i] = 0.f;

    auto fill = [&](int it, int stage) {
        int kbpix = kbp0 + it * 2;
        {   // A: 256 cpa16 (64 m x 2 kb x 2 kkpair)
            int j = tid;                       // 0..255
            int m = j >> 2, kb = (j >> 1) & 1, kp = j & 1;
            cpa16(smBase + (stage * 512 + (kb * 64 + m) * 4 + kp * 2) * 8,
                  g_knt + ((size_t)(b * 64 + m) * 1024 + kbpix + kb) * 4 + kp * 2);
        }
#pragma unroll
        for (int i = 0; i < 4; i++) {          // B: 1024 cpa16 (8 rows x 128 npairs)
            int j = i * 256 + tid;
            int row = j >> 7, npair = (j & 127) * 2;
            int kb = row >> 2, kkr = row & 3;
            cpa16(smBase + (1024 + stage * 2080 + row * 260 + npair) * 8,
                  g_vt + (((size_t)b * 1024 + kbpix + kb) * 4 + kkr) * 256 + npair);
        }
    };

    fill(0, 0); cpa_commit(); cpa_wait0(); __syncthreads();

    for (int it = 0; it < 8; it++) {
        int cur = it & 1, nxt = cur ^ 1;
        if (it < 7) { fill(it + 1, nxt); cpa_commit(); }
        const uint2* Ac = dynsm + cur * 512;
        const uint2* Bc = dynsm + 1024 + cur * 2080;
#pragma unroll
        for (int kb = 0; kb < 2; kb++) {
            uint2 alo[2], ahi[2];
#pragma unroll
            for (int mt = 0; mt < 2; mt++) {
                alo[mt] = Ac[(kb * 64 + m0w + mt * 16 + g) * 4 + kk];
                ahi[mt] = Ac[(kb * 64 + m0w + mt * 16 + 8 + g) * 4 + kk];
            }
#pragma unroll
            for (int nt = 0; nt < 8; nt++) {
                uint2 bb = Bc[(kb * 4 + kk) * 260 + n0w + nt * 8 + g];
                mma16(acc[0][nt], alo[0], ahi[0], bb);
                mma16(acc[1][nt], alo[1], ahi[1], bb);
            }
        }
        cpa_wait0(); __syncthreads();
    }

    float* outp = g_simp + (size_t)(b * NCH + ch) * CQK * CIN;
#pragma unroll
    for (int mt = 0; mt < 2; mt++) {
        int r = m0w + mt * 16 + g;
#pragma unroll
        for (int nt = 0; nt < 8; nt++) {
            int c = n0w + nt * 8 + (lane & 3) * 2;
            *(float2*)&outp[(size_t)r * CIN + c] = make_float2(acc[mt][nt][0], acc[mt][nt][1]);
            *(float2*)&outp[(size_t)(r + 8) * CIN + c] = make_float2(acc[mt][nt][2], acc[mt][nt][3]);
        }
    }
}

__global__ void k_simreduce()
{
    int o = blockIdx.x * 256 + threadIdx.x;
    int b = o / (CQK * CIN);
    int cv = o - b * (CQK * CIN);
    float s = 0.f;
#pragma unroll 8
    for (int ch = 0; ch < NCH; ch++)
        s += g_simp[((size_t)(b * NCH + ch)) * CQK * CIN + cv];
    g_sim[o] = s;
}

__global__ void k_m2(const float* __restrict__ oW)
{
    __shared__ float ssm[CIN];
    const int b = blockIdx.x >> 6;
    const int c = blockIdx.x & 63;
    const int o = threadIdx.x;
    ssm[o] = g_sim[((size_t)b * CQK + c) * CIN + o];
    __syncthreads();
    float s = 0.f;
#pragma unroll 8
    for (int v = 0; v < CIN; v++) s = fmaf(oW[(size_t)o * CIN + v], ssm[v], s);
    int krow = c >> 3, rem = c & 7;
    int kkv = rem & 3;
    ((uint32_t*)g_AM2)[(size_t)b * 16384 + (krow * 256 + o) * 8 + kkv * 2 + (rem >> 2)] = f2tf(s);
}

// ============ K4: ctx mma (tf32) -> fuse -> fp16 pairs g_fth ============
__global__ void __launch_bounds__(256, 2)
k_ctx_mma(const float* __restrict__ x, const float* __restrict__ up,
          const float* __restrict__ os, const float* __restrict__ ob)
{
    extern __shared__ uint2 dynsm[];
    uint2* Asm = dynsm;
    uint2* Bsm = dynsm + 4096;
    float* upH = (float*)(dynsm + 8320);

    const int b = blockIdx.z;
    const int co0 = blockIdx.y * 128;
    const int h = blockIdx.x;
    const int n0 = h * Ww;
    const int tid = threadIdx.x, lane = tid & 31, w = tid >> 5;
    const int g = lane >> 2, kk = lane & 3;
    const int mg = w >> 1, ng = w & 1;
    const int m0w = mg * 32, n0w = ng * 64;
    const uint32_t aBase = (uint32_t)__cvta_generic_to_shared(dynsm);

#pragma unroll
    for (int i = 0; i < 8; i++) {
        int jj = i * 256 + tid;
        int u = jj * 2;
        int kk2 = u & 3, m = (u >> 2) & 127, krow = u >> 9;
        cpa16(aBase + u * 8, g_AM2 + (size_t)b * 8192 + krow * 1024 + (co0 + m) * 4 + kk2);
    }
#pragma unroll
    for (int i = 0; i < 8; i++) {
        int jj = i * 256 + tid;
        int row = jj >> 6, colpair = (jj & 63) * 2;
        cpa16(aBase + 4096 * 8 + (row * 132 + colpair) * 8,
              g_qnt + (size_t)(b * 32 + row) * HW + n0 + colpair);
    }
    cpa_commit();

    {
        float shf = 0.5f * h - 0.25f;
        int h0 = (int)floorf(shf);
        float wh1 = shf - (float)h0;
        int h0c = h0 < 0 ? 0 : h0;
        int h1c = (h0 + 1) > 63 ? 63 : (h0 + 1);
        const float* ub = up + ((size_t)(b * CIN + co0)) * 64 * 64;
#pragma unroll
        for (int i = 0; i < 32; i++) {
            int idx = i * 256 + tid;
            int r = idx >> 6, sw = idx & 63;
            upH[r * 64 + sw] = (1.f - wh1) * ub[(r * 64 + h0c) * 64 + sw]
                             + wh1 * ub[(r * 64 + h1c) * 64 + sw];
        }
    }
    cpa_wait0(); __syncthreads();

    float acc[2][8][4];
#pragma unroll
    for (int mt = 0; mt < 2; mt++)
#pragma unroll
        for (int nt = 0; nt < 8; nt++)
#pragma unroll
            for (int i = 0; i < 4; i++) acc[mt][nt][i] = 0.f;

#pragma unroll
    for (int s = 0; s < 8; s++) {
        uint2 a01[2], a13[2];
#pragma unroll
        for (int mt = 0; mt < 2; mt++) {
            a01[mt] = Asm[(s * 128 + m0w + mt * 16 + g) * 4 + kk];
            a13[mt] = Asm[(s * 128 + m0w + mt * 16 + 8 + g) * 4 + kk];
        }
#pragma unroll
        for (int nt = 0; nt < 8; nt++) {
            uint2 bb = Bsm[(s * 4 + kk) * 132 + n0w + nt * 8 + g];
            mma8(acc[0][nt], a01[0], a13[0], bb);
            mma8(acc[1][nt], a01[1], a13[1], bb);
        }
    }

    const float* xb = x + ((size_t)b * CIN + co0) * HW + n0;
#pragma unroll
    for (int mt = 0; mt < 2; mt++) {
        int m = m0w + mt * 16 + g;
        int co = co0 + m;
        float sc0 = os[co], sh0 = ob[co];
        float sc1 = os[co + 8], sh1 = ob[co + 8];
        int ch16 = co >> 4;
        int jidx = g >> 1;
#pragma unroll
        for (int nt = 0; nt < 8; nt++) {
            int c0 = n0w + nt * 8 + (lane & 3) * 2;
            int c1 = c0 + 1;
            float sw0 = 0.5f * c0 - 0.25f, sw1 = 0.5f * c1 - 0.25f;
            int wa0 = (int)floorf(sw0), wa1 = (int)floorf(sw1);
            float t0 = sw0 - (float)wa0, t1 = sw1 - (float)wa1;
            int w00 = wa0 < 0 ? 0 : wa0, w01 = (wa0 + 1) > 63 ? 63 : (wa0 + 1);
            int w10 = wa1 < 0 ? 0 : wa1, w11 = (wa1 + 1) > 63 ? 63 : (wa1 + 1);

            float u0a = (1.f - t0) * upH[m * 64 + w00] + t0 * upH[m * 64 + w01];
            float u1a = (1.f - t1) * upH[m * 64 + w10] + t1 * upH[m * 64 + w11];
            float u0b = (1.f - t0) * upH[(m + 8) * 64 + w00] + t0 * upH[(m + 8) * 64 + w01];
            float u1b = (1.f - t1) * upH[(m + 8) * 64 + w10] + t1 * upH[(m + 8) * 64 + w11];

            float f0 = fmaxf(fmaf(acc[mt][nt][0], sc0, sh0), 0.f) + xb[(size_t)m * HW + c0] + u0a;
            float f1 = fmaxf(fmaf(acc[mt][nt][1], sc0, sh0), 0.f) + xb[(size_t)m * HW + c1] + u1a;
            float f2 = fmaxf(fmaf(acc[mt][nt][2], sc1, sh1), 0.f) + xb[(size_t)(m + 8) * HW + c0] + u0b;
            float f3 = fmaxf(fmaf(acc[mt][nt][3], sc1, sh1), 0.f) + xb[(size_t)(m + 8) * HW + c1] + u1b;

            float p0 = __shfl_xor_sync(0xffffffffu, f0, 4);
            float p1 = __shfl_xor_sync(0xffffffffu, f1, 4);
            float p2 = __shfl_xor_sync(0xffffffffu, f2, 4);
            float p3 = __shfl_xor_sync(0xffffffffu, f3, 4);
            if ((g & 1) == 0) {
                size_t base = (((size_t)(b * 16 + ch16) * 4 + jidx) * 130 + h + 1) * 132 + 1;
                g_fth[base + c0] = make_uint2(pkh2(f0, p0), pkh2(f2, p2));
                g_fth[base + c1] = make_uint2(pkh2(f1, p1), pkh2(f3, p3));
            }
        }
    }
}

// ============ K5: 3x3 conv, fp16 m16n8k16 (unchanged from R8) ============
__global__ void __launch_bounds__(256, 2)
k_conv_h(const float* __restrict__ ss, const float* __restrict__ sb,
         float* __restrict__ out)
{
    extern __shared__ uint2 csm[];
    uint2* Ism = csm;
    uint2* Wsm = csm + 4224;

    const int h0 = blockIdx.x * 2;
    const int co0 = blockIdx.y * 64;
    const int b = blockIdx.z;
    const int tid = threadIdx.x, lane = tid & 31, w = tid >> 5;
    const int g = lane >> 2, kk = lane & 3;
    const int mg = w >> 2, ng = w & 3;
    const int m0w = mg * 32, n0w = ng * 64;
    const uint32_t smBase = (uint32_t)__cvta_generic_to_shared(csm);

    float acc[2][8][4];
#pragma unroll
    for (int mt = 0; mt < 2; mt++)
#pragma unroll
        for (int nt = 0; nt < 8; nt++)
#pragma unroll
            for (int i = 0; i < 4; i++) acc[mt][nt][i] = 0.f;

    const uint2* ftb = g_fth + (size_t)b * 16 * 4 * 130 * 132;

    auto fill = [&](int ch, int stage) {
        for (int j = tid; j < 1040; j += 256) {
            int rowplane = j / 65;
            int colpair = (j - rowplane * 65) * 2;
            int row = rowplane >> 2, jj = rowplane & 3;
            cpa16(smBase + (stage * 2112 + (row * 4 + jj) * 132 + colpair) * 8,
                  ftb + ((size_t)(ch * 4 + jj) * 130 + h0 + row) * 132 + colpair);
        }
        for (int j = tid; j < 1152; j += 256) {
            int u = j * 2;
            int grp = u >> 8, off = u & 255;
            int dh = grp / 3, tap = grp - dh * 3;
            cpa16(smBase + (4224 + stage * 2304 + grp * 256 + off) * 8,
                  g_wph + (size_t)((dh * 16 + ch) * 3 + tap) * 512 + co0 * 4 + off);
        }
    };

    fill(0, 0); cpa_commit(); cpa_wait0(); __syncthreads();

    for (int it = 0; it < 16; it++) {
        int cur = it & 1, nxt = cur ^ 1;
        if (it < 15) { fill(it + 1, nxt); cpa_commit(); }

        const uint2* Ic = Ism + cur * 2112;
        const uint2* Wc = Wsm + cur * 2304;
#pragma unroll
        for (int dh = 0; dh < 3; dh++) {
#pragma unroll
            for (int tap = 0; tap < 3; tap++) {
                const uint2* wb = Wc + (dh * 3 + tap) * 256;
                uint2 alo[2], ahi[2];
#pragma unroll
                for (int mt = 0; mt < 2; mt++) {
                    alo[mt] = wb[(m0w + mt * 16 + g) * 4 + kk];
                    ahi[mt] = wb[(m0w + mt * 16 + 8 + g) * 4 + kk];
                }
#pragma unroll
                for (int nt = 0; nt < 8; nt++) {
                    int n = n0w + nt * 8 + g;
                    int rrow = n >> 7, wx = n & 127;
                    uint2 bb = Ic[((rrow + dh) * 4 + kk) * 132 + wx + tap];
                    mma16(acc[0][nt], alo[0], ahi[0], bb);
                    mma16(acc[1][nt], alo[1], ahi[1], bb);
                }
            }
        }
        cpa_wait0(); __syncthreads();
    }

#pragma unroll
    for (int mt = 0; mt < 2; mt++) {
        int co = co0 + m0w + mt * 16 + g;
        float sc0 = ss[co], sh0 = sb[co];
        float sc1 = ss[co + 8], sh1 = sb[co + 8];
#pragma unroll
        for (int nt = 0; nt < 8; nt++) {
            int n = n0w + nt * 8 + (lane & 3) * 2;
            int r = n >> 7, wx = n & 127;
            float* o0p = out + (((size_t)b * CS + co) * Hh + h0 + r) * Ww + wx;
            float* o1p = out + (((size_t)b * CS + co + 8) * Hh + h0 + r) * Ww + wx;
            float2 o0 = make_float2(fmaxf(fmaf(acc[mt][nt][0], sc0, sh0), 0.f),
                                    fmaxf(fmaf(acc[mt][nt][1], sc0, sh0), 0.f));
            float2 o1 = make_float2(fmaxf(fmaf(acc[mt][nt][2], sc1, sh1), 0.f),
                                    fmaxf(fmaf(acc[mt][nt][3], sc1, sh1), 0.f));
            *(float2*)o0p = o0;
            *(float2*)o1p = o1;
        }
    }
}

// ============================================================
extern "C" void kernel_launch(void* const* d_in, const int* in_sizes, int n_in,
                              void* d_out, int out_size)
{
    (void)in_sizes; (void)n_in; (void)out_size;
    const float* x        = (const float*)d_in[0];
    const float* up       = (const float*)d_in[1];
    const float* qW       = (const float*)d_in[2];
    const float* q_scale  = (const float*)d_in[3];
    const float* q_shift  = (const float*)d_in[4];
    const float* kW       = (const float*)d_in[5];
    const float* k_scale  = (const float*)d_in[6];
    const float* k_shift  = (const float*)d_in[7];
    const float* vW       = (const float*)d_in[8];
    const float* v_scale  = (const float*)d_in[9];
    const float* v_shift  = (const float*)d_in[10];
    const float* oW       = (const float*)d_in[11];
    const float* o_scale  = (const float*)d_in[12];
    const float* o_shift  = (const float*)d_in[13];
    const float* sW       = (const float*)d_in[14];
    const float* s_scale  = (const float*)d_in[15];
    const float* s_shift  = (const float*)d_in[16];
    float* out = (float*)d_out;

    cudaFuncSetAttribute(k_qk_mma,  cudaFuncAttributeMaxDynamicSharedMemorySize, 36352);
    cudaFuncSetAttribute(k_v_mma,   cudaFuncAttributeMaxDynamicSharedMemorySize, 33280);
    cudaFuncSetAttribute(k_sim_mma, cudaFuncAttributeMaxDynamicSharedMemorySize, 41472);
    cudaFuncSetAttribute(k_ctx_mma, cudaFuncAttributeMaxDynamicSharedMemorySize, 99328);
    cudaFuncSetAttribute(k_conv_h,  cudaFuncAttributeMaxDynamicSharedMemorySize, 70656);

    k_pack_qk<<<32, 256>>>(qW, kW);
    k_pack_v<<<64, 256>>>(vW);
    k_pack_conv<<<288, 256>>>(sW);
    k_packx<<<4096, 256>>>(x);
    k_qk_mma<<<dim3(HW / 128, Bn), 256, 36352>>>(q_scale, q_shift, k_scale, k_shift);
    k_v_mma<<<dim3(HW / 128, 2, Bn), 256, 33280>>>(v_scale, v_shift);
    k_sim_mma<<<dim3(NCH, Bn), 256, 41472>>>();
    k_simreduce<<<256, 256>>>();
    k_m2<<<Bn * CQK, 256>>>(oW);
    k_ctx_mma<<<dim3(Hh, 2, Bn), 256, 99328>>>(x, up, o_scale, o_shift);
    k_conv_h<<<dim3(Hh / 2, 2, Bn), 256, 70656>>>(s_scale, s_shift, out);
}

// round 10
// speedup vs baseline: 1.5750x; 1.0334x over previous
#include <cuda_runtime.h>
#include <cuda_fp16.h>
#include <math.h>
#include <stdint.h>

#define Bn   4
#define CIN  256
#define CQK  64
#define CS   128
#define Hh   128
#define Ww   128
#define HW   (Hh*Ww)
#define NCH  64
#define PIX_PER_CHUNK (HW/NCH)

__device__ float g_simp[Bn*NCH*CQK*CIN];

// fp16-pair operand buffers. entry uint2 = {h2(k0,k0+1), h2(k0+8,k0+9)}
__device__ __align__(16) uint2 g_Aqk[8192];               // [it8][kb2][m128][kk4]
__device__ __align__(16) uint2 g_Av [16384];              // [kb16 16][m256][kk4]
__device__ __align__(16) uint2 g_xt [Bn*8*8*HW];          // [(b*8+it)*8+kkb][n]
__device__ __align__(16) uint2 g_knt[Bn*64*1024*4];       // [b][m64][kb16 1024][kk4]
__device__ __align__(16) uint2 g_vt [Bn*1024*4*256];      // [b][kb16 1024][kk4][n256]
__device__ __align__(16) uint2 g_AM2h[Bn*4096];           // M2 fp16: [b][kb4][co256][kk4]
__device__ __align__(16) uint2 g_qnth[Bn*16*HW];          // qn fp16: [b][row16][n]
__device__ __align__(16) uint2 g_wph[73728];
__device__ __align__(16) uint2 g_fth[Bn*16*4*130*132];

__device__ __forceinline__ uint32_t pkh2(float lo, float hi) {
    uint32_t r; asm("cvt.rn.f16x2.f32 %0, %1, %2;" : "=r"(r) : "f"(hi), "f"(lo)); return r;
}
__device__ __forceinline__ void mma16(float* c, uint2 alo, uint2 ahi, uint2 b) {
    asm volatile(
        "mma.sync.aligned.m16n8k16.row.col.f32.f16.f16.f32 "
        "{%0,%1,%2,%3}, {%4,%5,%6,%7}, {%8,%9}, {%0,%1,%2,%3};"
        : "+f"(c[0]), "+f"(c[1]), "+f"(c[2]), "+f"(c[3])
        : "r"(alo.x), "r"(ahi.x), "r"(alo.y), "r"(ahi.y), "r"(b.x), "r"(b.y));
}
__device__ __forceinline__ void cpa16(uint32_t saddr, const void* g) {
    asm volatile("cp.async.cg.shared.global [%0], [%1], 16;" :: "r"(saddr), "l"(g));
}
__device__ __forceinline__ void cpa_commit() { asm volatile("cp.async.commit_group;"); }
__device__ __forceinline__ void cpa_wait0()  { asm volatile("cp.async.wait_group 0;" ::: "memory"); }

// ============ pack kernels ============
__global__ void k_pack_qk(const float* __restrict__ qW, const float* __restrict__ kW)
{
    int idx = blockIdx.x * 256 + threadIdx.x;
    int kk = idx & 3, m = (idx >> 2) & 127, kb = (idx >> 9) & 1, it = idx >> 10;
    int K0 = it * 32 + kb * 16 + kk * 2;
    const float* wr = (m < 64) ? (qW + (size_t)m * CIN) : (kW + (size_t)(m - 64) * CIN);
    g_Aqk[idx] = make_uint2(pkh2(wr[K0], wr[K0 + 1]), pkh2(wr[K0 + 8], wr[K0 + 9]));
}
__global__ void k_pack_v(const float* __restrict__ vW)
{
    int idx = blockIdx.x * 256 + threadIdx.x;
    int kk = idx & 3, m = (idx >> 2) & 255, kb16 = idx >> 10;
    int K0 = kb16 * 16 + kk * 2;
    const float* wr = vW + (size_t)m * CIN;
    g_Av[idx] = make_uint2(pkh2(wr[K0], wr[K0 + 1]), pkh2(wr[K0 + 8], wr[K0 + 9]));
}
__global__ void k_pack_conv(const float* __restrict__ sW)
{
    int idx = blockIdx.x * 256 + threadIdx.x;
    int r = idx & 511, s = idx >> 9;
    int j = r & 3, co = r >> 2;
    int tap = s % 3, t2 = s / 3, ch = t2 & 15, dh = t2 >> 4;
    int ci = ch * 16 + j * 2;
    const float* wp = sW + ((size_t)co * CIN + ci) * 9 + dh * 3 + tap;
    g_wph[idx] = make_uint2(pkh2(wp[0], wp[9]), pkh2(wp[8 * 9], wp[9 * 9]));
}
__global__ void k_packx(const float* __restrict__ x)
{
    int idx = blockIdx.x * 256 + threadIdx.x;
    int n4 = (idx & 4095) * 4;
    int kkb = (idx >> 12) & 7;
    int it = (idx >> 15) & 7;
    int b = idx >> 18;
    int kb = kkb >> 2, kk = kkb & 3;
    int K0 = it * 32 + kb * 16 + kk * 2;
    const float* xb = x + ((size_t)b * CIN + K0) * HW + n4;
    float4 r0 = *(const float4*)xb;
    float4 r1 = *(const float4*)(xb + HW);
    float4 r8 = *(const float4*)(xb + 8 * HW);
    float4 r9 = *(const float4*)(xb + 9 * HW);
    uint2* dst = g_xt + ((size_t)((b * 8 + it) * 8 + kkb)) * HW + n4;
    *(uint4*)dst = make_uint4(pkh2(r0.x, r1.x), pkh2(r8.x, r9.x),
                              pkh2(r0.y, r1.y), pkh2(r8.y, r9.y));
    *(uint4*)(dst + 2) = make_uint4(pkh2(r0.z, r1.z), pkh2(r8.z, r9.z),
                                    pkh2(r0.w, r1.w), pkh2(r8.w, r9.w));
}

// ============ K1: q,k proj + BN + L2 norm (fp16) ============
// dyn smem: A 2x1024 + B 2x1056 uint2 + Sq 512 f32 + Nn 256 f32 = 36352 B
__global__ void __launch_bounds__(256, 2)
k_qk_mma(const float* __restrict__ qs, const float* __restrict__ qb,
         const float* __restrict__ kscale, const float* __restrict__ kshift)
{
    extern __shared__ uint2 dynsm[];
    uint2* Asm = dynsm;
    uint2* Bsm = dynsm + 2048;
    float* Sq  = (float*)(dynsm + 4160);
    float* Nn  = Sq + 512;

    const int b = blockIdx.y, n0 = blockIdx.x * 128;
    const int tid = threadIdx.x, lane = tid & 31, w = tid >> 5;
    const int g = lane >> 2, kk = lane & 3;
    const int mg = w >> 1, ng = w & 1;
    const int m0w = mg * 32, n0w = ng * 64;
    const uint32_t aBase = (uint32_t)__cvta_generic_to_shared(dynsm);
    const uint2* xtb = g_xt + (size_t)b * 8 * 8 * HW + n0;

    float acc[2][8][4];
#pragma unroll
    for (int mt = 0; mt < 2; mt++)
#pragma unroll
        for (int nt = 0; nt < 8; nt++)
#pragma unroll
            for (int i = 0; i < 4; i++) acc[mt][nt][i] = 0.f;

    auto fill = [&](int it, int stage) {
#pragma unroll
        for (int i = 0; i < 2; i++) {
            int j = i * 256 + tid;
            cpa16(aBase + (stage * 1024 + j * 2) * 8, g_Aqk + it * 1024 + j * 2);
        }
#pragma unroll
        for (int i = 0; i < 2; i++) {
            int j = i * 256 + tid;
            int kkb = j >> 6, npair = (j & 63) * 2;
            cpa16(aBase + (2048 + stage * 1056 + kkb * 132 + npair) * 8,
                  xtb + (size_t)((it * 8) + kkb) * HW + npair);
        }
    };

    fill(0, 0); cpa_commit(); cpa_wait0(); __syncthreads();

    for (int it = 0; it < 8; it++) {
        int cur = it & 1, nxt = cur ^ 1;
        if (it < 7) { fill(it + 1, nxt); cpa_commit(); }
        const uint2* Ac = Asm + cur * 1024;
        const uint2* Bc = Bsm + cur * 1056;
#pragma unroll
        for (int kb = 0; kb < 2; kb++) {
            uint2 alo[2], ahi[2];
#pragma unroll
            for (int mt = 0; mt < 2; mt++) {
                alo[mt] = Ac[(kb * 128 + m0w + mt * 16 + g) * 4 + kk];
                ahi[mt] = Ac[(kb * 128 + m0w + mt * 16 + 8 + g) * 4 + kk];
            }
#pragma unroll
            for (int nt = 0; nt < 8; nt++) {
                uint2 bb = Bc[(kb * 4 + kk) * 132 + n0w + nt * 8 + g];
                mma16(acc[0][nt], alo[0], ahi[0], bb);
                mma16(acc[1][nt], alo[1], ahi[1], bb);
            }
        }
        cpa_wait0(); __syncthreads();
    }

    float sq[8][2];
#pragma unroll
    for (int nt = 0; nt < 8; nt++) { sq[nt][0] = 0.f; sq[nt][1] = 0.f; }
#pragma unroll
    for (int mt = 0; mt < 2; mt++) {
        int r0 = m0w + mt * 16 + g, r1 = r0 + 8;
        bool isq = (r0 < 64);
        float sc0 = isq ? qs[r0] : kscale[r0 - 64];
        float sh0 = isq ? qb[r0] : kshift[r0 - 64];
        float sc1 = isq ? qs[r1] : kscale[r1 - 64];
        float sh1 = isq ? qb[r1] : kshift[r1 - 64];
#pragma unroll
        for (int nt = 0; nt < 8; nt++) {
            float v0 = fmaf(acc[mt][nt][0], sc0, sh0);
            float v1 = fmaf(acc[mt][nt][1], sc0, sh0);
            float v2 = fmaf(acc[mt][nt][2], sc1, sh1);
            float v3 = fmaf(acc[mt][nt][3], sc1, sh1);
            acc[mt][nt][0] = v0; acc[mt][nt][1] = v1;
            acc[mt][nt][2] = v2; acc[mt][nt][3] = v3;
            sq[nt][0] += v0 * v0 + v2 * v2;
            sq[nt][1] += v1 * v1 + v3 * v3;
        }
    }
#pragma unroll
    for (int nt = 0; nt < 8; nt++) {
#pragma unroll
        for (int o = 4; o < 32; o <<= 1) {
            sq[nt][0] += __shfl_xor_sync(0xffffffffu, sq[nt][0], o);
            sq[nt][1] += __shfl_xor_sync(0xffffffffu, sq[nt][1], o);
        }
    }
    if (lane < 4) {
#pragma unroll
        for (int nt = 0; nt < 8; nt++) {
            int c = n0w + nt * 8 + lane * 2;
            Sq[mg * 128 + c] = sq[nt][0];
            Sq[mg * 128 + c + 1] = sq[nt][1];
        }
    }
    __syncthreads();
    {
        int col = tid & 127, half = tid >> 7;
        float s = Sq[half * 256 + col] + Sq[half * 256 + 128 + col];
        Nn[half * 128 + col] = 1.f / fmaxf(sqrtf(s), 1e-12f);
    }
    __syncthreads();

    if (mg < 2) {
        // q half -> g_qnth fp16 k-pairs (rows of CQK paired via shfl_xor 4)
#pragma unroll
        for (int mt = 0; mt < 2; mt++) {
            int r0 = m0w + mt * 16 + g;
            int row = (r0 >> 4) * 4 + (g >> 1);
#pragma unroll
            for (int nt = 0; nt < 8; nt++) {
                int c = n0w + nt * 8 + (lane & 3) * 2;
                float i0 = Nn[c], i1 = Nn[c + 1];
                float v0 = acc[mt][nt][0] * i0, v1 = acc[mt][nt][1] * i1;
                float v2 = acc[mt][nt][2] * i0, v3 = acc[mt][nt][3] * i1;
                float p0 = __shfl_xor_sync(0xffffffffu, v0, 4);
                float p1 = __shfl_xor_sync(0xffffffffu, v1, 4);
                float p2 = __shfl_xor_sync(0xffffffffu, v2, 4);
                float p3 = __shfl_xor_sync(0xffffffffu, v3, 4);
                if ((g & 1) == 0) {
                    uint2* dst = g_qnth + (size_t)(b * 16 + row) * HW + n0 + c;
                    dst[0] = make_uint2(pkh2(v0, p0), pkh2(v2, p2));
                    dst[1] = make_uint2(pkh2(v1, p1), pkh2(v3, p3));
                }
            }
        }
    } else {
        // k half -> g_knt fp16 pixel pairs, in-thread
#pragma unroll
        for (int mt = 0; mt < 2; mt++) {
            int r0 = m0w + mt * 16 + g - 64;
#pragma unroll
            for (int nt = 0; nt < 8; nt += 2) {
                int c0 = n0w + nt * 8 + (lane & 3) * 2;
                int kbpix = (n0 + c0) >> 4, kkp = lane & 3;
                float i0 = Nn[128 + c0], i1 = Nn[128 + c0 + 1];
                float i8 = Nn[128 + c0 + 8], i9 = Nn[128 + c0 + 9];
                float a0 = acc[mt][nt][0] * i0,     a1 = acc[mt][nt][1] * i1;
                float b0 = acc[mt][nt + 1][0] * i8, b1 = acc[mt][nt + 1][1] * i9;
                float a2 = acc[mt][nt][2] * i0,     a3 = acc[mt][nt][3] * i1;
                float b2 = acc[mt][nt + 1][2] * i8, b3 = acc[mt][nt + 1][3] * i9;
                g_knt[((size_t)(b * 64 + r0) * 1024 + kbpix) * 4 + kkp] =
                    make_uint2(pkh2(a0, a1), pkh2(b0, b1));
                g_knt[((size_t)(b * 64 + r0 + 8) * 1024 + kbpix) * 4 + kkp] =
                    make_uint2(pkh2(a2, a3), pkh2(b2, b3));
            }
        }
    }
}

// ============ K2: v proj + BN + ReLU (fp16) ============
__global__ void __launch_bounds__(256, 2)
k_v_mma(const float* __restrict__ vs, const float* __restrict__ vb)
{
    extern __shared__ uint2 dynsm[];
    uint2* Asm = dynsm;
    uint2* Bsm = dynsm + 2048;

    const int b = blockIdx.z, co0 = blockIdx.y * 128, n0 = blockIdx.x * 128;
    const int tid = threadIdx.x, lane = tid & 31, w = tid >> 5;
    const int g = lane >> 2, kk = lane & 3;
    const int mg = w >> 1, ng = w & 1;
    const int m0w = mg * 32, n0w = ng * 64;
    const uint32_t aBase = (uint32_t)__cvta_generic_to_shared(dynsm);
    const uint2* xtb = g_xt + (size_t)b * 8 * 8 * HW + n0;

    float acc[2][8][4];
#pragma unroll
    for (int mt = 0; mt < 2; mt++)
#pragma unroll
        for (int nt = 0; nt < 8; nt++)
#pragma unroll
            for (int i = 0; i < 4; i++) acc[mt][nt][i] = 0.f;

    auto fill = [&](int it, int stage) {
#pragma unroll
        for (int i = 0; i < 2; i++) {
            int j = i * 256 + tid;
            int kb = j >> 8, r = (j & 255) * 2;
            cpa16(aBase + (stage * 1024 + kb * 512 + r) * 8,
                  g_Av + (size_t)(it * 2 + kb) * 1024 + co0 * 4 + r);
        }
#pragma unroll
        for (int i = 0; i < 2; i++) {
            int j = i * 256 + tid;
            int kkb = j >> 6, npair = (j & 63) * 2;
            cpa16(aBase + (2048 + stage * 1056 + kkb * 132 + npair) * 8,
                  xtb + (size_t)((it * 8) + kkb) * HW + npair);
        }
    };

    fill(0, 0); cpa_commit(); cpa_wait0(); __syncthreads();

    for (int it = 0; it < 8; it++) {
        int cur = it & 1, nxt = cur ^ 1;
        if (it < 7) { fill(it + 1, nxt); cpa_commit(); }
        const uint2* Ac = Asm + cur * 1024;
        const uint2* Bc = Bsm + cur * 1056;
#pragma unroll
        for (int kb = 0; kb < 2; kb++) {
            uint2 alo[2], ahi[2];
#pragma unroll
            for (int mt = 0; mt < 2; mt++) {
                alo[mt] = Ac[(kb * 128 + m0w + mt * 16 + g) * 4 + kk];
                ahi[mt] = Ac[(kb * 128 + m0w + mt * 16 + 8 + g) * 4 + kk];
            }
#pragma unroll
            for (int nt = 0; nt < 8; nt++) {
                uint2 bb = Bc[(kb * 4 + kk) * 132 + n0w + nt * 8 + g];
                mma16(acc[0][nt], alo[0], ahi[0], bb);
                mma16(acc[1][nt], alo[1], ahi[1], bb);
            }
        }
        cpa_wait0(); __syncthreads();
    }

#pragma unroll
    for (int mt = 0; mt < 2; mt++) {
        int co = co0 + m0w + mt * 16 + g;
        float sc0 = vs[co], sh0 = vb[co];
        float sc1 = vs[co + 8], sh1 = vb[co + 8];
#pragma unroll
        for (int nt = 0; nt < 8; nt += 2) {
            int c0 = n0w + nt * 8 + (lane & 3) * 2;
            int kbpix = (n0 + c0) >> 4, kkp = lane & 3;
            float a0 = fmaxf(fmaf(acc[mt][nt][0], sc0, sh0), 0.f);
            float a1 = fmaxf(fmaf(acc[mt][nt][1], sc0, sh0), 0.f);
            float b0 = fmaxf(fmaf(acc[mt][nt + 1][0], sc0, sh0), 0.f);
            float b1 = fmaxf(fmaf(acc[mt][nt + 1][1], sc0, sh0), 0.f);
            float a2 = fmaxf(fmaf(acc[mt][nt][2], sc1, sh1), 0.f);
            float a3 = fmaxf(fmaf(acc[mt][nt][3], sc1, sh1), 0.f);
            float b2 = fmaxf(fmaf(acc[mt][nt + 1][2], sc1, sh1), 0.f);
            float b3 = fmaxf(fmaf(acc[mt][nt + 1][3], sc1, sh1), 0.f);
            g_vt[(((size_t)b * 1024 + kbpix) * 4 + kkp) * 256 + co] =
                make_uint2(pkh2(a0, a1), pkh2(b0, b1));
            g_vt[(((size_t)b * 1024 + kbpix) * 4 + kkp) * 256 + co + 8] =
                make_uint2(pkh2(a2, a3), pkh2(b2, b3));
        }
    }
}

// ============ K3: partial sim = kn @ v^T (fp16) ============
__global__ void __launch_bounds__(256, 2) k_sim_mma()
{
    extern __shared__ uint2 dynsm[];
    const int b = blockIdx.y, ch = blockIdx.x;
    const int kbp0 = (ch * PIX_PER_CHUNK) >> 4;
    const int tid = threadIdx.x, lane = tid & 31, w = tid >> 5;
    const int g = lane >> 2, kk = lane & 3;
    const int mg = w >> 2, ng = w & 3;
    const int m0w = mg * 32, n0w = ng * 64;
    const uint32_t smBase = (uint32_t)__cvta_generic_to_shared(dynsm);

    float acc[2][8][4];
#pragma unroll
    for (int mt = 0; mt < 2; mt++)
#pragma unroll
        for (int nt = 0; nt < 8; nt++)
#pragma unroll
            for (int i = 0; i < 4; i++) acc[mt][nt][i] = 0.f;

    auto fill = [&](int it, int stage) {
        int kbpix = kbp0 + it * 2;
        {
            int j = tid;
            int m = j >> 2, kb = (j >> 1) & 1, kp = j & 1;
            cpa16(smBase + (stage * 512 + (kb * 64 + m) * 4 + kp * 2) * 8,
                  g_knt + ((size_t)(b * 64 + m) * 1024 + kbpix + kb) * 4 + kp * 2);
        }
#pragma unroll
        for (int i = 0; i < 4; i++) {
            int j = i * 256 + tid;
            int row = j >> 7, npair = (j & 127) * 2;
            int kb = row >> 2, kkr = row & 3;
            cpa16(smBase + (1024 + stage * 2080 + row * 260 + npair) * 8,
                  g_vt + (((size_t)b * 1024 + kbpix + kb) * 4 + kkr) * 256 + npair);
        }
    };

    fill(0, 0); cpa_commit(); cpa_wait0(); __syncthreads();

    for (int it = 0; it < 8; it++) {
        int cur = it & 1, nxt = cur ^ 1;
        if (it < 7) { fill(it + 1, nxt); cpa_commit(); }
        const uint2* Ac = dynsm + cur * 512;
        const uint2* Bc = dynsm + 1024 + cur * 2080;
#pragma unroll
        for (int kb = 0; kb < 2; kb++) {
            uint2 alo[2], ahi[2];
#pragma unroll
            for (int mt = 0; mt < 2; mt++) {
                alo[mt] = Ac[(kb * 64 + m0w + mt * 16 + g) * 4 + kk];
                ahi[mt] = Ac[(kb * 64 + m0w + mt * 16 + 8 + g) * 4 + kk];
            }
#pragma unroll
            for (int nt = 0; nt < 8; nt++) {
                uint2 bb = Bc[(kb * 4 + kk) * 260 + n0w + nt * 8 + g];
                mma16(acc[0][nt], alo[0], ahi[0], bb);
                mma16(acc[1][nt], alo[1], ahi[1], bb);
            }
        }
        cpa_wait0(); __syncthreads();
    }

    float* outp = g_simp + (size_t)(b * NCH + ch) * CQK * CIN;
#pragma unroll
    for (int mt = 0; mt < 2; mt++) {
        int r = m0w + mt * 16 + g;
#pragma unroll
        for (int nt = 0; nt < 8; nt++) {
            int c = n0w + nt * 8 + (lane & 3) * 2;
            *(float2*)&outp[(size_t)r * CIN + c] = make_float2(acc[mt][nt][0], acc[mt][nt][1]);
            *(float2*)&outp[(size_t)(r + 8) * CIN + c] = make_float2(acc[mt][nt][2], acc[mt][nt][3]);
        }
    }
}

// ============ K3b+K4a fused: reduce partials + M2 = oW @ sim^T -> fp16 g_AM2h ============
__global__ void k_m2(const float* __restrict__ oW)
{
    __shared__ float ssm[CIN];
    const int b = blockIdx.x >> 6;
    const int c = blockIdx.x & 63;
    const int o = threadIdx.x;
    const float* sp = g_simp + (size_t)b * NCH * CQK * CIN + (size_t)c * CIN + o;
    float s0 = 0.f;
#pragma unroll 8
    for (int ch = 0; ch < NCH; ch++)
        s0 += sp[(size_t)ch * CQK * CIN];
    ssm[o] = s0;
    __syncthreads();
    float s = 0.f;
#pragma unroll 8
    for (int v = 0; v < CIN; v++) s = fmaf(oW[(size_t)o * CIN + v], ssm[v], s);
    int kb = c >> 4, rem = c & 15;
    int hi = rem >> 3, kkv = (rem & 7) >> 1, low = rem & 1;
    __half* hp = (__half*)g_AM2h;
    hp[((((size_t)(b * 4 + kb) * 256 + o) * 4 + kkv) << 2) + hi * 2 + low] = __float2half(s);
}

// ============ K4: ctx mma (fp16) -> fuse -> fp16 pairs g_fth ============
// dyn smem: A 2048 + B 2112 uint2 (33280 B) + upH 32768 B = 66048 B
__global__ void __launch_bounds__(256, 2)
k_ctx_mma(const float* __restrict__ x, const float* __restrict__ up,
          const float* __restrict__ os, const float* __restrict__ ob)
{
    extern __shared__ uint2 dynsm[];
    uint2* Asm = dynsm;                  // [kb4][m128][kk4]
    uint2* Bsm = dynsm + 2048;           // [row16][132]
    float* upH = (float*)(dynsm + 4160);

    const int b = blockIdx.z;
    const int co0 = blockIdx.y * 128;
    const int h = blockIdx.x;
    const int n0 = h * Ww;
    const int tid = threadIdx.x, lane = tid & 31, w = tid >> 5;
    const int g = lane >> 2, kk = lane & 3;
    const int mg = w >> 1, ng = w & 1;
    const int m0w = mg * 32, n0w = ng * 64;
    const uint32_t aBase = (uint32_t)__cvta_generic_to_shared(dynsm);

#pragma unroll
    for (int i = 0; i < 4; i++) {
        int j = i * 256 + tid;              // < 1024 chunks
        int kb = j >> 8, r = j & 255;
        int m = r >> 1, kp = r & 1;
        cpa16(aBase + (kb * 512 + m * 4 + kp * 2) * 8,
              g_AM2h + ((size_t)(b * 4 + kb) * 256 + co0 + m) * 4 + kp * 2);
    }
#pragma unroll
    for (int i = 0; i < 4; i++) {
        int j = i * 256 + tid;              // < 1024 chunks
        int row = j >> 6, npair = (j & 63) * 2;
        cpa16(aBase + (2048 + row * 132 + npair) * 8,
              g_qnth + (size_t)(b * 16 + row) * HW + n0 + npair);
    }
    cpa_commit();

    {
        float shf = 0.5f * h - 0.25f;
        int h0 = (int)floorf(shf);
        float wh1 = shf - (float)h0;
        int h0c = h0 < 0 ? 0 : h0;
        int h1c = (h0 + 1) > 63 ? 63 : (h0 + 1);
        const float* ub = up + ((size_t)(b * CIN + co0)) * 64 * 64;
#pragma unroll
        for (int i = 0; i < 32; i++) {
            int idx = i * 256 + tid;
            int r = idx >> 6, sw = idx & 63;
            upH[r * 64 + sw] = (1.f - wh1) * ub[(r * 64 + h0c) * 64 + sw]
                             + wh1 * ub[(r * 64 + h1c) * 64 + sw];
        }
    }
    cpa_wait0(); __syncthreads();

    float acc[2][8][4];
#pragma unroll
    for (int mt = 0; mt < 2; mt++)
#pragma unroll
        for (int nt = 0; nt < 8; nt++)
#pragma unroll
            for (int i = 0; i < 4; i++) acc[mt][nt][i] = 0.f;

#pragma unroll
    for (int kb = 0; kb < 4; kb++) {
        uint2 alo[2], ahi[2];
#pragma unroll
        for (int mt = 0; mt < 2; mt++) {
            alo[mt] = Asm[kb * 512 + (m0w + mt * 16 + g) * 4 + kk];
            ahi[mt] = Asm[kb * 512 + (m0w + mt * 16 + 8 + g) * 4 + kk];
        }
#pragma unroll
        for (int nt = 0; nt < 8; nt++) {
            uint2 bb = Bsm[(kb * 4 + kk) * 132 + n0w + nt * 8 + g];
            mma16(acc[0][nt], alo[0], ahi[0], bb);
            mma16(acc[1][nt], alo[1], ahi[1], bb);
        }
    }

    const float* xb = x + ((size_t)b * CIN + co0) * HW + n0;
#pragma unroll
    for (int mt = 0; mt < 2; mt++) {
        int m = m0w + mt * 16 + g;
        int co = co0 + m;
        float sc0 = os[co], sh0 = ob[co];
        float sc1 = os[co + 8], sh1 = ob[co + 8];
        int ch16 = co >> 4;
        int jidx = g >> 1;
#pragma unroll
        for (int nt = 0; nt < 8; nt++) {
            int c0 = n0w + nt * 8 + (lane & 3) * 2;
            int c1 = c0 + 1;
            float sw0 = 0.5f * c0 - 0.25f, sw1 = 0.5f * c1 - 0.25f;
            int wa0 = (int)floorf(sw0), wa1 = (int)floorf(sw1);
            float t0 = sw0 - (float)wa0, t1 = sw1 - (float)wa1;
            int w00 = wa0 < 0 ? 0 : wa0, w01 = (wa0 + 1) > 63 ? 63 : (wa0 + 1);
            int w10 = wa1 < 0 ? 0 : wa1, w11 = (wa1 + 1) > 63 ? 63 : (wa1 + 1);

            float u0a = (1.f - t0) * upH[m * 64 + w00] + t0 * upH[m * 64 + w01];
            float u1a = (1.f - t1) * upH[m * 64 + w10] + t1 * upH[m * 64 + w11];
            float u0b = (1.f - t0) * upH[(m + 8) * 64 + w00] + t0 * upH[(m + 8) * 64 + w01];
            float u1b = (1.f - t1) * upH[(m + 8) * 64 + w10] + t1 * upH[(m + 8) * 64 + w11];

            float f0 = fmaxf(fmaf(acc[mt][nt][0], sc0, sh0), 0.f) + xb[(size_t)m * HW + c0] + u0a;
            float f1 = fmaxf(fmaf(acc[mt][nt][1], sc0, sh0), 0.f) + xb[(size_t)m * HW + c1] + u1a;
            float f2 = fmaxf(fmaf(acc[mt][nt][2], sc1, sh1), 0.f) + xb[(size_t)(m + 8) * HW + c0] + u0b;
            float f3 = fmaxf(fmaf(acc[mt][nt][3], sc1, sh1), 0.f) + xb[(size_t)(m + 8) * HW + c1] + u1b;

            float p0 = __shfl_xor_sync(0xffffffffu, f0, 4);
            float p1 = __shfl_xor_sync(0xffffffffu, f1, 4);
            float p2 = __shfl_xor_sync(0xffffffffu, f2, 4);
            float p3 = __shfl_xor_sync(0xffffffffu, f3, 4);
            if ((g & 1) == 0) {
                size_t base = (((size_t)(b * 16 + ch16) * 4 + jidx) * 130 + h + 1) * 132 + 1;
                g_fth[base + c0] = make_uint2(pkh2(f0, p0), pkh2(f2, p2));
                g_fth[base + c1] = make_uint2(pkh2(f1, p1), pkh2(f3, p3));
            }
        }
    }
}

// ============ K5: 3x3 conv, fp16 m16n8k16 (unchanged) ============
__global__ void __launch_bounds__(256, 2)
k_conv_h(const float* __restrict__ ss, const float* __restrict__ sb,
         float* __restrict__ out)
{
    extern __shared__ uint2 csm[];
    uint2* Ism = csm;
    uint2* Wsm = csm + 4224;

    const int h0 = blockIdx.x * 2;
    const int co0 = blockIdx.y * 64;
    const int b = blockIdx.z;
    const int tid = threadIdx.x, lane = tid & 31, w = tid >> 5;
    const int g = lane >> 2, kk = lane & 3;
    const int mg = w >> 2, ng = w & 3;
    const int m0w = mg * 32, n0w = ng * 64;
    const uint32_t smBase = (uint32_t)__cvta_generic_to_shared(csm);

    float acc[2][8][4];
#pragma unroll
    for (int mt = 0; mt < 2; mt++)
#pragma unroll
        for (int nt = 0; nt < 8; nt++)
#pragma unroll
            for (int i = 0; i < 4; i++) acc[mt][nt][i] = 0.f;

    const uint2* ftb = g_fth + (size_t)b * 16 * 4 * 130 * 132;

    auto fill = [&](int ch, int stage) {
        for (int j = tid; j < 1040; j += 256) {
            int rowplane = j / 65;
            int colpair = (j - rowplane * 65) * 2;
            int row = rowplane >> 2, jj = rowplane & 3;
            cpa16(smBase + (stage * 2112 + (row * 4 + jj) * 132 + colpair) * 8,
                  ftb + ((size_t)(ch * 4 + jj) * 130 + h0 + row) * 132 + colpair);
        }
        for (int j = tid; j < 1152; j += 256) {
            int u = j * 2;
            int grp = u >> 8, off = u & 255;
            int dh = grp / 3, tap = grp - dh * 3;
            cpa16(smBase + (4224 + stage * 2304 + grp * 256 + off) * 8,
                  g_wph + (size_t)((dh * 16 + ch) * 3 + tap) * 512 + co0 * 4 + off);
        }
    };

    fill(0, 0); cpa_commit(); cpa_wait0(); __syncthreads();

    for (int it = 0; it < 16; it++) {
        int cur = it & 1, nxt = cur ^ 1;
        if (it < 15) { fill(it + 1, nxt); cpa_commit(); }

        const uint2* Ic = Ism + cur * 2112;
        const uint2* Wc = Wsm + cur * 2304;
#pragma unroll
        for (int dh = 0; dh < 3; dh++) {
#pragma unroll
            for (int tap = 0; tap < 3; tap++) {
                const uint2* wb = Wc + (dh * 3 + tap) * 256;
                uint2 alo[2], ahi[2];
#pragma unroll
                for (int mt = 0; mt < 2; mt++) {
                    alo[mt] = wb[(m0w + mt * 16 + g) * 4 + kk];
                    ahi[mt] = wb[(m0w + mt * 16 + 8 + g) * 4 + kk];
                }
#pragma unroll
                for (int nt = 0; nt < 8; nt++) {
                    int n = n0w + nt * 8 + g;
                    int rrow = n >> 7, wx = n & 127;
                    uint2 bb = Ic[((rrow + dh) * 4 + kk) * 132 + wx + tap];
                    mma16(acc[0][nt], alo[0], ahi[0], bb);
                    mma16(acc[1][nt], alo[1], ahi[1], bb);
                }
            }
        }
        cpa_wait0(); __syncthreads();
    }

#pragma unroll
    for (int mt = 0; mt < 2; mt++) {
        int co = co0 + m0w + mt * 16 + g;
        float sc0 = ss[co], sh0 = sb[co];
        float sc1 = ss[co + 8], sh1 = sb[co + 8];
#pragma unroll
        for (int nt = 0; nt < 8; nt++) {
            int n = n0w + nt * 8 + (lane & 3) * 2;
            int r = n >> 7, wx = n & 127;
            float* o0p = out + (((size_t)b * CS + co) * Hh + h0 + r) * Ww + wx;
            float* o1p = out + (((size_t)b * CS + co + 8) * Hh + h0 + r) * Ww + wx;
            float2 o0 = make_float2(fmaxf(fmaf(acc[mt][nt][0], sc0, sh0), 0.f),
                                    fmaxf(fmaf(acc[mt][nt][1], sc0, sh0), 0.f));
            float2 o1 = make_float2(fmaxf(fmaf(acc[mt][nt][2], sc1, sh1), 0.f),
                                    fmaxf(fmaf(acc[mt][nt][3], sc1, sh1), 0.f));
            *(float2*)o0p = o0;
            *(float2*)o1p = o1;
        }
    }
}

// ============================================================
extern "C" void kernel_launch(void* const* d_in, const int* in_sizes, int n_in,
                              void* d_out, int out_size)
{
    (void)in_sizes; (void)n_in; (void)out_size;
    const float* x        = (const float*)d_in[0];
    const float* up       = (const float*)d_in[1];
    const float* qW       = (const float*)d_in[2];
    const float* q_scale  = (const float*)d_in[3];
    const float* q_shift  = (const float*)d_in[4];
    const float* kW       = (const float*)d_in[5];
    const float* k_scale  = (const float*)d_in[6];
    const float* k_shift  = (const float*)d_in[7];
    const float* vW       = (const float*)d_in[8];
    const float* v_scale  = (const float*)d_in[9];
    const float* v_shift  = (const float*)d_in[10];
    const float* oW       = (const float*)d_in[11];
    const float* o_scale  = (const float*)d_in[12];
    const float* o_shift  = (const float*)d_in[13];
    const float* sW       = (const float*)d_in[14];
    const float* s_scale  = (const float*)d_in[15];
    const float* s_shift  = (const float*)d_in[16];
    float* out = (float*)d_out;

    cudaFuncSetAttribute(k_qk_mma,  cudaFuncAttributeMaxDynamicSharedMemorySize, 36352);
    cudaFuncSetAttribute(k_v_mma,   cudaFuncAttributeMaxDynamicSharedMemorySize, 33280);
    cudaFuncSetAttribute(k_sim_mma, cudaFuncAttributeMaxDynamicSharedMemorySize, 41472);
    cudaFuncSetAttribute(k_ctx_mma, cudaFuncAttributeMaxDynamicSharedMemorySize, 66048);
    cudaFuncSetAttribute(k_conv_h,  cudaFuncAttributeMaxDynamicSharedMemorySize, 70656);

    k_pack_qk<<<32, 256>>>(qW, kW);
    k_pack_v<<<64, 256>>>(vW);
    k_pack_conv<<<288, 256>>>(sW);
    k_packx<<<4096, 256>>>(x);
    k_qk_mma<<<dim3(HW / 128, Bn), 256, 36352>>>(q_scale, q_shift, k_scale, k_shift);
    k_v_mma<<<dim3(HW / 128, 2, Bn), 256, 33280>>>(v_scale, v_shift);
    k_sim_mma<<<dim3(NCH, Bn), 256, 41472>>>();
    k_m2<<<Bn * CQK, 256>>>(oW);
    k_ctx_mma<<<dim3(Hh, 2, Bn), 256, 66048>>>(x, up, o_scale, o_shift);
    k_conv_h<<<dim3(Hh / 2, 2, Bn), 256, 70656>>>(s_scale, s_shift, out);
}

// round 11
// speedup vs baseline: 1.5811x; 1.0038x over previous
#include <cuda_runtime.h>
#include <cuda_fp16.h>
#include <math.h>
#include <stdint.h>

#define Bn   4
#define CIN  256
#define CQK  64
#define CS   128
#define Hh   128
#define Ww   128
#define HW   (Hh*Ww)
#define NCH  64
#define PIX_PER_CHUNK (HW/NCH)

__device__ float g_simp[Bn*NCH*CQK*CIN];

// fp16-pair operand buffers. entry uint2 = {h2(k0,k0+1), h2(k0+8,k0+9)}
__device__ __align__(16) uint2 g_Aqk[8192];
__device__ __align__(16) uint2 g_Av [16384];
__device__ __align__(16) uint2 g_xt [Bn*8*8*HW];
__device__ __align__(16) uint2 g_knt[Bn*64*1024*4];
__device__ __align__(16) uint2 g_vt [Bn*1024*4*256];
__device__ __align__(16) uint2 g_AM2h[Bn*4096];
__device__ __align__(16) uint2 g_qnth[Bn*16*HW];
__device__ __align__(16) uint2 g_wph[73728];
__device__ __align__(16) uint2 g_fth[Bn*16*4*130*132];

__device__ __forceinline__ uint32_t pkh2(float lo, float hi) {
    uint32_t r; asm("cvt.rn.f16x2.f32 %0, %1, %2;" : "=r"(r) : "f"(hi), "f"(lo)); return r;
}
__device__ __forceinline__ void mma16(float* c, uint2 alo, uint2 ahi, uint2 b) {
    asm volatile(
        "mma.sync.aligned.m16n8k16.row.col.f32.f16.f16.f32 "
        "{%0,%1,%2,%3}, {%4,%5,%6,%7}, {%8,%9}, {%0,%1,%2,%3};"
        : "+f"(c[0]), "+f"(c[1]), "+f"(c[2]), "+f"(c[3])
        : "r"(alo.x), "r"(ahi.x), "r"(alo.y), "r"(ahi.y), "r"(b.x), "r"(b.y));
}
__device__ __forceinline__ void cpa16(uint32_t saddr, const void* g) {
    asm volatile("cp.async.cg.shared.global [%0], [%1], 16;" :: "r"(saddr), "l"(g));
}
__device__ __forceinline__ void cpa_commit() { asm volatile("cp.async.commit_group;"); }
__device__ __forceinline__ void cpa_wait0()  { asm volatile("cp.async.wait_group 0;" ::: "memory"); }

// ============ pack kernels ============
__global__ void k_pack_qk(const float* __restrict__ qW, const float* __restrict__ kW)
{
    int idx = blockIdx.x * 256 + threadIdx.x;
    int kk = idx & 3, m = (idx >> 2) & 127, kb = (idx >> 9) & 1, it = idx >> 10;
    int K0 = it * 32 + kb * 16 + kk * 2;
    const float* wr = (m < 64) ? (qW + (size_t)m * CIN) : (kW + (size_t)(m - 64) * CIN);
    g_Aqk[idx] = make_uint2(pkh2(wr[K0], wr[K0 + 1]), pkh2(wr[K0 + 8], wr[K0 + 9]));
}
__global__ void k_pack_v(const float* __restrict__ vW)
{
    int idx = blockIdx.x * 256 + threadIdx.x;
    int kk = idx & 3, m = (idx >> 2) & 255, kb16 = idx >> 10;
    int K0 = kb16 * 16 + kk * 2;
    const float* wr = vW + (size_t)m * CIN;
    g_Av[idx] = make_uint2(pkh2(wr[K0], wr[K0 + 1]), pkh2(wr[K0 + 8], wr[K0 + 9]));
}
__global__ void k_pack_conv(const float* __restrict__ sW)
{
    int idx = blockIdx.x * 256 + threadIdx.x;
    int r = idx & 511, s = idx >> 9;
    int j = r & 3, co = r >> 2;
    int tap = s % 3, t2 = s / 3, ch = t2 & 15, dh = t2 >> 4;
    int ci = ch * 16 + j * 2;
    const float* wp = sW + ((size_t)co * CIN + ci) * 9 + dh * 3 + tap;
    g_wph[idx] = make_uint2(pkh2(wp[0], wp[9]), pkh2(wp[8 * 9], wp[9 * 9]));
}
__global__ void k_packx(const float* __restrict__ x)
{
    int idx = blockIdx.x * 256 + threadIdx.x;
    int n4 = (idx & 4095) * 4;
    int kkb = (idx >> 12) & 7;
    int it = (idx >> 15) & 7;
    int b = idx >> 18;
    int kb = kkb >> 2, kk = kkb & 3;
    int K0 = it * 32 + kb * 16 + kk * 2;
    const float* xb = x + ((size_t)b * CIN + K0) * HW + n4;
    float4 r0 = *(const float4*)xb;
    float4 r1 = *(const float4*)(xb + HW);
    float4 r8 = *(const float4*)(xb + 8 * HW);
    float4 r9 = *(const float4*)(xb + 9 * HW);
    uint2* dst = g_xt + ((size_t)((b * 8 + it) * 8 + kkb)) * HW + n4;
    *(uint4*)dst = make_uint4(pkh2(r0.x, r1.x), pkh2(r8.x, r9.x),
                              pkh2(r0.y, r1.y), pkh2(r8.y, r9.y));
    *(uint4*)(dst + 2) = make_uint4(pkh2(r0.z, r1.z), pkh2(r8.z, r9.z),
                                    pkh2(r0.w, r1.w), pkh2(r8.w, r9.w));
}

// ============ K1: q,k proj + BN + L2 norm (fp16) ============
__global__ void __launch_bounds__(256, 2)
k_qk_mma(const float* __restrict__ qs, const float* __restrict__ qb,
         const float* __restrict__ kscale, const float* __restrict__ kshift)
{
    extern __shared__ uint2 dynsm[];
    uint2* Asm = dynsm;
    uint2* Bsm = dynsm + 2048;
    float* Sq  = (float*)(dynsm + 4160);
    float* Nn  = Sq + 512;

    const int b = blockIdx.y, n0 = blockIdx.x * 128;
    const int tid = threadIdx.x, lane = tid & 31, w = tid >> 5;
    const int g = lane >> 2, kk = lane & 3;
    const int mg = w >> 1, ng = w & 1;
    const int m0w = mg * 32, n0w = ng * 64;
    const uint32_t aBase = (uint32_t)__cvta_generic_to_shared(dynsm);
    const uint2* xtb = g_xt + (size_t)b * 8 * 8 * HW + n0;

    float acc[2][8][4];
#pragma unroll
    for (int mt = 0; mt < 2; mt++)
#pragma unroll
        for (int nt = 0; nt < 8; nt++)
#pragma unroll
            for (int i = 0; i < 4; i++) acc[mt][nt][i] = 0.f;

    auto fill = [&](int it, int stage) {
#pragma unroll
        for (int i = 0; i < 2; i++) {
            int j = i * 256 + tid;
            cpa16(aBase + (stage * 1024 + j * 2) * 8, g_Aqk + it * 1024 + j * 2);
        }
#pragma unroll
        for (int i = 0; i < 2; i++) {
            int j = i * 256 + tid;
            int kkb = j >> 6, npair = (j & 63) * 2;
            cpa16(aBase + (2048 + stage * 1056 + kkb * 132 + npair) * 8,
                  xtb + (size_t)((it * 8) + kkb) * HW + npair);
        }
    };

    fill(0, 0); cpa_commit(); cpa_wait0(); __syncthreads();

    for (int it = 0; it < 8; it++) {
        int cur = it & 1, nxt = cur ^ 1;
        if (it < 7) { fill(it + 1, nxt); cpa_commit(); }
        const uint2* Ac = Asm + cur * 1024;
        const uint2* Bc = Bsm + cur * 1056;
#pragma unroll
        for (int kb = 0; kb < 2; kb++) {
            uint2 alo[2], ahi[2];
#pragma unroll
            for (int mt = 0; mt < 2; mt++) {
                alo[mt] = Ac[(kb * 128 + m0w + mt * 16 + g) * 4 + kk];
                ahi[mt] = Ac[(kb * 128 + m0w + mt * 16 + 8 + g) * 4 + kk];
            }
#pragma unroll
            for (int nt = 0; nt < 8; nt++) {
                uint2 bb = Bc[(kb * 4 + kk) * 132 + n0w + nt * 8 + g];
                mma16(acc[0][nt], alo[0], ahi[0], bb);
                mma16(acc[1][nt], alo[1], ahi[1], bb);
            }
        }
        cpa_wait0(); __syncthreads();
    }

    float sq[8][2];
#pragma unroll
    for (int nt = 0; nt < 8; nt++) { sq[nt][0] = 0.f; sq[nt][1] = 0.f; }
#pragma unroll
    for (int mt = 0; mt < 2; mt++) {
        int r0 = m0w + mt * 16 + g, r1 = r0 + 8;
        bool isq = (r0 < 64);
        float sc0 = isq ? qs[r0] : kscale[r0 - 64];
        float sh0 = isq ? qb[r0] : kshift[r0 - 64];
        float sc1 = isq ? qs[r1] : kscale[r1 - 64];
        float sh1 = isq ? qb[r1] : kshift[r1 - 64];
#pragma unroll
        for (int nt = 0; nt < 8; nt++) {
            float v0 = fmaf(acc[mt][nt][0], sc0, sh0);
            float v1 = fmaf(acc[mt][nt][1], sc0, sh0);
            float v2 = fmaf(acc[mt][nt][2], sc1, sh1);
            float v3 = fmaf(acc[mt][nt][3], sc1, sh1);
            acc[mt][nt][0] = v0; acc[mt][nt][1] = v1;
            acc[mt][nt][2] = v2; acc[mt][nt][3] = v3;
            sq[nt][0] += v0 * v0 + v2 * v2;
            sq[nt][1] += v1 * v1 + v3 * v3;
        }
    }
#pragma unroll
    for (int nt = 0; nt < 8; nt++) {
#pragma unroll
        for (int o = 4; o < 32; o <<= 1) {
            sq[nt][0] += __shfl_xor_sync(0xffffffffu, sq[nt][0], o);
            sq[nt][1] += __shfl_xor_sync(0xffffffffu, sq[nt][1], o);
        }
    }
    if (lane < 4) {
#pragma unroll
        for (int nt = 0; nt < 8; nt++) {
            int c = n0w + nt * 8 + lane * 2;
            Sq[mg * 128 + c] = sq[nt][0];
            Sq[mg * 128 + c + 1] = sq[nt][1];
        }
    }
    __syncthreads();
    {
        int col = tid & 127, half = tid >> 7;
        float s = Sq[half * 256 + col] + Sq[half * 256 + 128 + col];
        Nn[half * 128 + col] = 1.f / fmaxf(sqrtf(s), 1e-12f);
    }
    __syncthreads();

    if (mg < 2) {
#pragma unroll
        for (int mt = 0; mt < 2; mt++) {
            int r0 = m0w + mt * 16 + g;
            int row = (r0 >> 4) * 4 + (g >> 1);
#pragma unroll
            for (int nt = 0; nt < 8; nt++) {
                int c = n0w + nt * 8 + (lane & 3) * 2;
                float i0 = Nn[c], i1 = Nn[c + 1];
                float v0 = acc[mt][nt][0] * i0, v1 = acc[mt][nt][1] * i1;
                float v2 = acc[mt][nt][2] * i0, v3 = acc[mt][nt][3] * i1;
                float p0 = __shfl_xor_sync(0xffffffffu, v0, 4);
                float p1 = __shfl_xor_sync(0xffffffffu, v1, 4);
                float p2 = __shfl_xor_sync(0xffffffffu, v2, 4);
                float p3 = __shfl_xor_sync(0xffffffffu, v3, 4);
                if ((g & 1) == 0) {
                    uint2* dst = g_qnth + (size_t)(b * 16 + row) * HW + n0 + c;
                    dst[0] = make_uint2(pkh2(v0, p0), pkh2(v2, p2));
                    dst[1] = make_uint2(pkh2(v1, p1), pkh2(v3, p3));
                }
            }
        }
    } else {
#pragma unroll
        for (int mt = 0; mt < 2; mt++) {
            int r0 = m0w + mt * 16 + g - 64;
#pragma unroll
            for (int nt = 0; nt < 8; nt += 2) {
                int c0 = n0w + nt * 8 + (lane & 3) * 2;
                int kbpix = (n0 + c0) >> 4, kkp = lane & 3;
                float i0 = Nn[128 + c0], i1 = Nn[128 + c0 + 1];
                float i8 = Nn[128 + c0 + 8], i9 = Nn[128 + c0 + 9];
                float a0 = acc[mt][nt][0] * i0,     a1 = acc[mt][nt][1] * i1;
                float b0 = acc[mt][nt + 1][0] * i8, b1 = acc[mt][nt + 1][1] * i9;
                float a2 = acc[mt][nt][2] * i0,     a3 = acc[mt][nt][3] * i1;
                float b2 = acc[mt][nt + 1][2] * i8, b3 = acc[mt][nt + 1][3] * i9;
                g_knt[((size_t)(b * 64 + r0) * 1024 + kbpix) * 4 + kkp] =
                    make_uint2(pkh2(a0, a1), pkh2(b0, b1));
                g_knt[((size_t)(b * 64 + r0 + 8) * 1024 + kbpix) * 4 + kkp] =
                    make_uint2(pkh2(a2, a3), pkh2(b2, b3));
            }
        }
    }
}

// ============ K2: v proj + BN + ReLU (fp16) ============
__global__ void __launch_bounds__(256, 2)
k_v_mma(const float* __restrict__ vs, const float* __restrict__ vb)
{
    extern __shared__ uint2 dynsm[];
    uint2* Asm = dynsm;
    uint2* Bsm = dynsm + 2048;

    const int b = blockIdx.z, co0 = blockIdx.y * 128, n0 = blockIdx.x * 128;
    const int tid = threadIdx.x, lane = tid & 31, w = tid >> 5;
    const int g = lane >> 2, kk = lane & 3;
    const int mg = w >> 1, ng = w & 1;
    const int m0w = mg * 32, n0w = ng * 64;
    const uint32_t aBase = (uint32_t)__cvta_generic_to_shared(dynsm);
    const uint2* xtb = g_xt + (size_t)b * 8 * 8 * HW + n0;

    float acc[2][8][4];
#pragma unroll
    for (int mt = 0; mt < 2; mt++)
#pragma unroll
        for (int nt = 0; nt < 8; nt++)
#pragma unroll
            for (int i = 0; i < 4; i++) acc[mt][nt][i] = 0.f;

    auto fill = [&](int it, int stage) {
#pragma unroll
        for (int i = 0; i < 2; i++) {
            int j = i * 256 + tid;
            int kb = j >> 8, r = (j & 255) * 2;
            cpa16(aBase + (stage * 1024 + kb * 512 + r) * 8,
                  g_Av + (size_t)(it * 2 + kb) * 1024 + co0 * 4 + r);
        }
#pragma unroll
        for (int i = 0; i < 2; i++) {
            int j = i * 256 + tid;
            int kkb = j >> 6, npair = (j & 63) * 2;
            cpa16(aBase + (2048 + stage * 1056 + kkb * 132 + npair) * 8,
                  xtb + (size_t)((it * 8) + kkb) * HW + npair);
        }
    };

    fill(0, 0); cpa_commit(); cpa_wait0(); __syncthreads();

    for (int it = 0; it < 8; it++) {
        int cur = it & 1, nxt = cur ^ 1;
        if (it < 7) { fill(it + 1, nxt); cpa_commit(); }
        const uint2* Ac = Asm + cur * 1024;
        const uint2* Bc = Bsm + cur * 1056;
#pragma unroll
        for (int kb = 0; kb < 2; kb++) {
            uint2 alo[2], ahi[2];
#pragma unroll
            for (int mt = 0; mt < 2; mt++) {
                alo[mt] = Ac[(kb * 128 + m0w + mt * 16 + g) * 4 + kk];
                ahi[mt] = Ac[(kb * 128 + m0w + mt * 16 + 8 + g) * 4 + kk];
            }
#pragma unroll
            for (int nt = 0; nt < 8; nt++) {
                uint2 bb = Bc[(kb * 4 + kk) * 132 + n0w + nt * 8 + g];
                mma16(acc[0][nt], alo[0], ahi[0], bb);
                mma16(acc[1][nt], alo[1], ahi[1], bb);
            }
        }
        cpa_wait0(); __syncthreads();
    }

#pragma unroll
    for (int mt = 0; mt < 2; mt++) {
        int co = co0 + m0w + mt * 16 + g;
        float sc0 = vs[co], sh0 = vb[co];
        float sc1 = vs[co + 8], sh1 = vb[co + 8];
#pragma unroll
        for (int nt = 0; nt < 8; nt += 2) {
            int c0 = n0w + nt * 8 + (lane & 3) * 2;
            int kbpix = (n0 + c0) >> 4, kkp = lane & 3;
            float a0 = fmaxf(fmaf(acc[mt][nt][0], sc0, sh0), 0.f);
            float a1 = fmaxf(fmaf(acc[mt][nt][1], sc0, sh0), 0.f);
            float b0 = fmaxf(fmaf(acc[mt][nt + 1][0], sc0, sh0), 0.f);
            float b1 = fmaxf(fmaf(acc[mt][nt + 1][1], sc0, sh0), 0.f);
            float a2 = fmaxf(fmaf(acc[mt][nt][2], sc1, sh1), 0.f);
            float a3 = fmaxf(fmaf(acc[mt][nt][3], sc1, sh1), 0.f);
            float b2 = fmaxf(fmaf(acc[mt][nt + 1][2], sc1, sh1), 0.f);
            float b3 = fmaxf(fmaf(acc[mt][nt + 1][3], sc1, sh1), 0.f);
            g_vt[(((size_t)b * 1024 + kbpix) * 4 + kkp) * 256 + co] =
                make_uint2(pkh2(a0, a1), pkh2(b0, b1));
            g_vt[(((size_t)b * 1024 + kbpix) * 4 + kkp) * 256 + co + 8] =
                make_uint2(pkh2(a2, a3), pkh2(b2, b3));
        }
    }
}

// ============ K3: partial sim = kn @ v^T (fp16) ============
__global__ void __launch_bounds__(256, 2) k_sim_mma()
{
    extern __shared__ uint2 dynsm[];
    const int b = blockIdx.y, ch = blockIdx.x;
    const int kbp0 = (ch * PIX_PER_CHUNK) >> 4;
    const int tid = threadIdx.x, lane = tid & 31, w = tid >> 5;
    const int g = lane >> 2, kk = lane & 3;
    const int mg = w >> 2, ng = w & 3;
    const int m0w = mg * 32, n0w = ng * 64;
    const uint32_t smBase = (uint32_t)__cvta_generic_to_shared(dynsm);

    float acc[2][8][4];
#pragma unroll
    for (int mt = 0; mt < 2; mt++)
#pragma unroll
        for (int nt = 0; nt < 8; nt++)
#pragma unroll
            for (int i = 0; i < 4; i++) acc[mt][nt][i] = 0.f;

    auto fill = [&](int it, int stage) {
        int kbpix = kbp0 + it * 2;
        {
            int j = tid;
            int m = j >> 2, kb = (j >> 1) & 1, kp = j & 1;
            cpa16(smBase + (stage * 512 + (kb * 64 + m) * 4 + kp * 2) * 8,
                  g_knt + ((size_t)(b * 64 + m) * 1024 + kbpix + kb) * 4 + kp * 2);
        }
#pragma unroll
        for (int i = 0; i < 4; i++) {
            int j = i * 256 + tid;
            int row = j >> 7, npair = (j & 127) * 2;
            int kb = row >> 2, kkr = row & 3;
            cpa16(smBase + (1024 + stage * 2080 + row * 260 + npair) * 8,
                  g_vt + (((size_t)b * 1024 + kbpix + kb) * 4 + kkr) * 256 + npair);
        }
    };

    fill(0, 0); cpa_commit(); cpa_wait0(); __syncthreads();

    for (int it = 0; it < 8; it++) {
        int cur = it & 1, nxt = cur ^ 1;
        if (it < 7) { fill(it + 1, nxt); cpa_commit(); }
        const uint2* Ac = dynsm + cur * 512;
        const uint2* Bc = dynsm + 1024 + cur * 2080;
#pragma unroll
        for (int kb = 0; kb < 2; kb++) {
            uint2 alo[2], ahi[2];
#pragma unroll
            for (int mt = 0; mt < 2; mt++) {
                alo[mt] = Ac[(kb * 64 + m0w + mt * 16 + g) * 4 + kk];
                ahi[mt] = Ac[(kb * 64 + m0w + mt * 16 + 8 + g) * 4 + kk];
            }
#pragma unroll
            for (int nt = 0; nt < 8; nt++) {
                uint2 bb = Bc[(kb * 4 + kk) * 260 + n0w + nt * 8 + g];
                mma16(acc[0][nt], alo[0], ahi[0], bb);
                mma16(acc[1][nt], alo[1], ahi[1], bb);
            }
        }
        cpa_wait0(); __syncthreads();
    }

    float* outp = g_simp + (size_t)(b * NCH + ch) * CQK * CIN;
#pragma unroll
    for (int mt = 0; mt < 2; mt++) {
        int r = m0w + mt * 16 + g;
#pragma unroll
        for (int nt = 0; nt < 8; nt++) {
            int c = n0w + nt * 8 + (lane & 3) * 2;
            *(float2*)&outp[(size_t)r * CIN + c] = make_float2(acc[mt][nt][0], acc[mt][nt][1]);
            *(float2*)&outp[(size_t)(r + 8) * CIN + c] = make_float2(acc[mt][nt][2], acc[mt][nt][3]);
        }
    }
}

// ============ fused reduce + M2 -> fp16 g_AM2h ============
__global__ void k_m2(const float* __restrict__ oW)
{
    __shared__ float ssm[CIN];
    const int b = blockIdx.x >> 6;
    const int c = blockIdx.x & 63;
    const int o = threadIdx.x;
    const float* sp = g_simp + (size_t)b * NCH * CQK * CIN + (size_t)c * CIN + o;
    float s0 = 0.f;
#pragma unroll 8
    for (int ch = 0; ch < NCH; ch++)
        s0 += sp[(size_t)ch * CQK * CIN];
    ssm[o] = s0;
    __syncthreads();
    float s = 0.f;
#pragma unroll 8
    for (int v = 0; v < CIN; v++) s = fmaf(oW[(size_t)o * CIN + v], ssm[v], s);
    int kb = c >> 4, rem = c & 15;
    int hi = rem >> 3, kkv = (rem & 7) >> 1, low = rem & 1;
    __half* hp = (__half*)g_AM2h;
    hp[((((size_t)(b * 4 + kb) * 256 + o) * 4 + kkv) << 2) + hi * 2 + low] = __float2half(s);
}

// ============ K4: ctx mma (fp16) -> fuse -> fp16 pairs g_fth ============
__global__ void __launch_bounds__(256, 2)
k_ctx_mma(const float* __restrict__ x, const float* __restrict__ up,
          const float* __restrict__ os, const float* __restrict__ ob)
{
    extern __shared__ uint2 dynsm[];
    uint2* Asm = dynsm;
    uint2* Bsm = dynsm + 2048;
    float* upH = (float*)(dynsm + 4160);

    const int b = blockIdx.z;
    const int co0 = blockIdx.y * 128;
    const int h = blockIdx.x;
    const int n0 = h * Ww;
    const int tid = threadIdx.x, lane = tid & 31, w = tid >> 5;
    const int g = lane >> 2, kk = lane & 3;
    const int mg = w >> 1, ng = w & 1;
    const int m0w = mg * 32, n0w = ng * 64;
    const uint32_t aBase = (uint32_t)__cvta_generic_to_shared(dynsm);

#pragma unroll
    for (int i = 0; i < 4; i++) {
        int j = i * 256 + tid;
        int kb = j >> 8, r = j & 255;
        int m = r >> 1, kp = r & 1;
        cpa16(aBase + (kb * 512 + m * 4 + kp * 2) * 8,
              g_AM2h + ((size_t)(b * 4 + kb) * 256 + co0 + m) * 4 + kp * 2);
    }
#pragma unroll
    for (int i = 0; i < 4; i++) {
        int j = i * 256 + tid;
        int row = j >> 6, npair = (j & 63) * 2;
        cpa16(aBase + (2048 + row * 132 + npair) * 8,
              g_qnth + (size_t)(b * 16 + row) * HW + n0 + npair);
    }
    cpa_commit();

    {
        float shf = 0.5f * h - 0.25f;
        int h0 = (int)floorf(shf);
        float wh1 = shf - (float)h0;
        int h0c = h0 < 0 ? 0 : h0;
        int h1c = (h0 + 1) > 63 ? 63 : (h0 + 1);
        const float* ub = up + ((size_t)(b * CIN + co0)) * 64 * 64;
#pragma unroll
        for (int i = 0; i < 32; i++) {
            int idx = i * 256 + tid;
            int r = idx >> 6, sw = idx & 63;
            upH[r * 64 + sw] = (1.f - wh1) * ub[(r * 64 + h0c) * 64 + sw]
                             + wh1 * ub[(r * 64 + h1c) * 64 + sw];
        }
    }
    cpa_wait0(); __syncthreads();

    float acc[2][8][4];
#pragma unroll
    for (int mt = 0; mt < 2; mt++)
#pragma unroll
        for (int nt = 0; nt < 8; nt++)
#pragma unroll
            for (int i = 0; i < 4; i++) acc[mt][nt][i] = 0.f;

#pragma unroll
    for (int kb = 0; kb < 4; kb++) {
        uint2 alo[2], ahi[2];
#pragma unroll
        for (int mt = 0; mt < 2; mt++) {
            alo[mt] = Asm[kb * 512 + (m0w + mt * 16 + g) * 4 + kk];
            ahi[mt] = Asm[kb * 512 + (m0w + mt * 16 + 8 + g) * 4 + kk];
        }
#pragma unroll
        for (int nt = 0; nt < 8; nt++) {
            uint2 bb = Bsm[(kb * 4 + kk) * 132 + n0w + nt * 8 + g];
            mma16(acc[0][nt], alo[0], ahi[0], bb);
            mma16(acc[1][nt], alo[1], ahi[1], bb);
        }
    }

    const float* xb = x + ((size_t)b * CIN + co0) * HW + n0;
#pragma unroll
    for (int mt = 0; mt < 2; mt++) {
        int m = m0w + mt * 16 + g;
        int co = co0 + m;
        float sc0 = os[co], sh0 = ob[co];
        float sc1 = os[co + 8], sh1 = ob[co + 8];
        int ch16 = co >> 4;
        int jidx = g >> 1;
#pragma unroll
        for (int nt = 0; nt < 8; nt++) {
            int c0 = n0w + nt * 8 + (lane & 3) * 2;
            int c1 = c0 + 1;
            float sw0 = 0.5f * c0 - 0.25f, sw1 = 0.5f * c1 - 0.25f;
            int wa0 = (int)floorf(sw0), wa1 = (int)floorf(sw1);
            float t0 = sw0 - (float)wa0, t1 = sw1 - (float)wa1;
            int w00 = wa0 < 0 ? 0 : wa0, w01 = (wa0 + 1) > 63 ? 63 : (wa0 + 1);
            int w10 = wa1 < 0 ? 0 : wa1, w11 = (wa1 + 1) > 63 ? 63 : (wa1 + 1);

            float u0a = (1.f - t0) * upH[m * 64 + w00] + t0 * upH[m * 64 + w01];
            float u1a = (1.f - t1) * upH[m * 64 + w10] + t1 * upH[m * 64 + w11];
            float u0b = (1.f - t0) * upH[(m + 8) * 64 + w00] + t0 * upH[(m + 8) * 64 + w01];
            float u1b = (1.f - t1) * upH[(m + 8) * 64 + w10] + t1 * upH[(m + 8) * 64 + w11];

            float f0 = fmaxf(fmaf(acc[mt][nt][0], sc0, sh0), 0.f) + xb[(size_t)m * HW + c0] + u0a;
            float f1 = fmaxf(fmaf(acc[mt][nt][1], sc0, sh0), 0.f) + xb[(size_t)m * HW + c1] + u1a;
            float f2 = fmaxf(fmaf(acc[mt][nt][2], sc1, sh1), 0.f) + xb[(size_t)(m + 8) * HW + c0] + u0b;
            float f3 = fmaxf(fmaf(acc[mt][nt][3], sc1, sh1), 0.f) + xb[(size_t)(m + 8) * HW + c1] + u1b;

            float p0 = __shfl_xor_sync(0xffffffffu, f0, 4);
            float p1 = __shfl_xor_sync(0xffffffffu, f1, 4);
            float p2 = __shfl_xor_sync(0xffffffffu, f2, 4);
            float p3 = __shfl_xor_sync(0xffffffffu, f3, 4);
            if ((g & 1) == 0) {
                size_t base = (((size_t)(b * 16 + ch16) * 4 + jidx) * 130 + h + 1) * 132 + 1;
                g_fth[base + c0] = make_uint2(pkh2(f0, p0), pkh2(f2, p2));
                g_fth[base + c1] = make_uint2(pkh2(f1, p1), pkh2(f3, p3));
            }
        }
    }
}

// ============ K5: 3x3 conv, fp16, 4 rows x 64 co x 128 w per block ============
// dyn smem: Ism 2x3168 + Wsm 2x2304 uint2 = 87552 B
__global__ void __launch_bounds__(512, 1)
k_conv_h(const float* __restrict__ ss, const float* __restrict__ sb,
         float* __restrict__ out)
{
    extern __shared__ uint2 csm[];
    uint2* Ism = csm;            // 2 x 3168: [row6][jj4][132]
    uint2* Wsm = csm + 6336;     // 2 x 2304: [dh*3+tap][co64*4]

    const int h0 = blockIdx.x * 4;
    const int co0 = blockIdx.y * 64;
    const int b = blockIdx.z;
    const int tid = threadIdx.x, lane = tid & 31, w = tid >> 5;
    const int g = lane >> 2, kk = lane & 3;
    const int mg = w >> 3, ng = w & 7;
    const int m0w = mg * 32, n0w = ng * 64;
    const uint32_t smBase = (uint32_t)__cvta_generic_to_shared(csm);

    float acc[2][8][4];
#pragma unroll
    for (int mt = 0; mt < 2; mt++)
#pragma unroll
        for (int nt = 0; nt < 8; nt++)
#pragma unroll
            for (int i = 0; i < 4; i++) acc[mt][nt][i] = 0.f;

    const uint2* ftb = g_fth + (size_t)b * 16 * 4 * 130 * 132;

    auto fill = [&](int ch, int stage) {
        for (int j = tid; j < 1560; j += 512) {            // 6 rows x 4 jj x 65 colpairs
            int rowplane = j / 65;
            int colpair = (j - rowplane * 65) * 2;
            int row = rowplane >> 2, jj = rowplane & 3;
            cpa16(smBase + (stage * 3168 + (row * 4 + jj) * 132 + colpair) * 8,
                  ftb + ((size_t)(ch * 4 + jj) * 130 + h0 + row) * 132 + colpair);
        }
        for (int j = tid; j < 1152; j += 512) {
            int u = j * 2;
            int grp = u >> 8, off = u & 255;
            int dh = grp / 3, tap = grp - dh * 3;
            cpa16(smBase + (6336 + stage * 2304 + grp * 256 + off) * 8,
                  g_wph + (size_t)((dh * 16 + ch) * 3 + tap) * 512 + co0 * 4 + off);
        }
    };

    fill(0, 0); cpa_commit(); cpa_wait0(); __syncthreads();

    for (int it = 0; it < 16; it++) {
        int cur = it & 1, nxt = cur ^ 1;
        if (it < 15) { fill(it + 1, nxt); cpa_commit(); }

        const uint2* Ic = Ism + cur * 3168;
        const uint2* Wc = Wsm + cur * 2304;
#pragma unroll
        for (int dh = 0; dh < 3; dh++) {
#pragma unroll
            for (int tap = 0; tap < 3; tap++) {
                const uint2* wb = Wc + (dh * 3 + tap) * 256;
                uint2 alo[2], ahi[2];
#pragma unroll
                for (int mt = 0; mt < 2; mt++) {
                    alo[mt] = wb[(m0w + mt * 16 + g) * 4 + kk];
                    ahi[mt] = wb[(m0w + mt * 16 + 8 + g) * 4 + kk];
                }
#pragma unroll
                for (int nt = 0; nt < 8; nt++) {
                    int n = n0w + nt * 8 + g;
                    int rrow = n >> 7, wx = n & 127;
                    uint2 bb = Ic[((rrow + dh) * 4 + kk) * 132 + wx + tap];
                    mma16(acc[0][nt], alo[0], ahi[0], bb);
                    mma16(acc[1][nt], alo[1], ahi[1], bb);
                }
            }
        }
        cpa_wait0(); __syncthreads();
    }

#pragma unroll
    for (int mt = 0; mt < 2; mt++) {
        int co = co0 + m0w + mt * 16 + g;
        float sc0 = ss[co], sh0 = sb[co];
        float sc1 = ss[co + 8], sh1 = sb[co + 8];
#pragma unroll
        for (int nt = 0; nt < 8; nt++) {
            int n = n0w + nt * 8 + (lane & 3) * 2;
            int r = n >> 7, wx = n & 127;
            float* o0p = out + (((size_t)b * CS + co) * Hh + h0 + r) * Ww + wx;
            float* o1p = out + (((size_t)b * CS + co + 8) * Hh + h0 + r) * Ww + wx;
            float2 o0 = make_float2(fmaxf(fmaf(acc[mt][nt][0], sc0, sh0), 0.f),
                                    fmaxf(fmaf(acc[mt][nt][1], sc0, sh0), 0.f));
            float2 o1 = make_float2(fmaxf(fmaf(acc[mt][nt][2], sc1, sh1), 0.f),
                                    fmaxf(fmaf(acc[mt][nt][3], sc1, sh1), 0.f));
            *(float2*)o0p = o0;
            *(float2*)o1p = o1;
        }
    }
}

// ============================================================
extern "C" void kernel_launch(void* const* d_in, const int* in_sizes, int n_in,
                              void* d_out, int out_size)
{
    (void)in_sizes; (void)n_in; (void)out_size;
    const float* x        = (const float*)d_in[0];
    const float* up       = (const float*)d_in[1];
    const float* qW       = (const float*)d_in[2];
    const float* q_scale  = (const float*)d_in[3];
    const float* q_shift  = (const float*)d_in[4];
    const float* kW       = (const float*)d_in[5];
    const float* k_scale  = (const float*)d_in[6];
    const float* k_shift  = (const float*)d_in[7];
    const float* vW       = (const float*)d_in[8];
    const float* v_scale  = (const float*)d_in[9];
    const float* v_shift  = (const float*)d_in[10];
    const float* oW       = (const float*)d_in[11];
    const float* o_scale  = (const float*)d_in[12];
    const float* o_shift  = (const float*)d_in[13];
    const float* sW       = (const float*)d_in[14];
    const float* s_scale  = (const float*)d_in[15];
    const float* s_shift  = (const float*)d_in[16];
    float* out = (float*)d_out;

    cudaFuncSetAttribute(k_qk_mma,  cudaFuncAttributeMaxDynamicSharedMemorySize, 36352);
    cudaFuncSetAttribute(k_v_mma,   cudaFuncAttributeMaxDynamicSharedMemorySize, 33280);
    cudaFuncSetAttribute(k_sim_mma, cudaFuncAttributeMaxDynamicSharedMemorySize, 41472);
    cudaFuncSetAttribute(k_ctx_mma, cudaFuncAttributeMaxDynamicSharedMemorySize, 66048);
    cudaFuncSetAttribute(k_conv_h,  cudaFuncAttributeMaxDynamicSharedMemorySize, 87552);

    k_pack_qk<<<32, 256>>>(qW, kW);
    k_pack_v<<<64, 256>>>(vW);
    k_pack_conv<<<288, 256>>>(sW);
    k_packx<<<4096, 256>>>(x);
    k_qk_mma<<<dim3(HW / 128, Bn), 256, 36352>>>(q_scale, q_shift, k_scale, k_shift);
    k_v_mma<<<dim3(HW / 128, 2, Bn), 256, 33280>>>(v_scale, v_shift);
    k_sim_mma<<<dim3(NCH, Bn), 256, 41472>>>();
    k_m2<<<Bn * CQK, 256>>>(oW);
    k_ctx_mma<<<dim3(Hh, 2, Bn), 256, 66048>>>(x, up, o_scale, o_shift);
    k_conv_h<<<dim3(Hh / 4, 2, Bn), 512, 87552>>>(s_scale, s_shift, out);
}

// round 12
// speedup vs baseline: 1.6127x; 1.0200x over previous
#include <cuda_runtime.h>
#include <cuda_fp16.h>
#include <math.h>
#include <stdint.h>

#define Bn   4
#define CIN  256
#define CQK  64
#define CS   128
#define Hh   128
#define Ww   128
#define HW   (Hh*Ww)
#define NCH  64
#define PIX_PER_CHUNK (HW/NCH)

__device__ float g_simp[Bn*NCH*CQK*CIN];

__device__ __align__(16) uint2 g_Aqk[8192];
__device__ __align__(16) uint2 g_Av [16384];
__device__ __align__(16) uint2 g_xt [Bn*8*8*HW];
__device__ __align__(16) uint2 g_knt[Bn*64*1024*4];
__device__ __align__(16) uint2 g_vt [Bn*1024*4*256];
__device__ __align__(16) uint2 g_AM2h[Bn*4096];
__device__ __align__(16) uint2 g_qnth[Bn*16*HW];
__device__ __align__(16) uint2 g_wph[73728];
__device__ __align__(16) uint2 g_fth[Bn*16*4*130*132];

__device__ __forceinline__ uint32_t pkh2(float lo, float hi) {
    uint32_t r; asm("cvt.rn.f16x2.f32 %0, %1, %2;" : "=r"(r) : "f"(hi), "f"(lo)); return r;
}
__device__ __forceinline__ void mma16(float* c, uint2 alo, uint2 ahi, uint2 b) {
    asm volatile(
        "mma.sync.aligned.m16n8k16.row.col.f32.f16.f16.f32 "
        "{%0,%1,%2,%3}, {%4,%5,%6,%7}, {%8,%9}, {%0,%1,%2,%3};"
        : "+f"(c[0]), "+f"(c[1]), "+f"(c[2]), "+f"(c[3])
        : "r"(alo.x), "r"(ahi.x), "r"(alo.y), "r"(ahi.y), "r"(b.x), "r"(b.y));
}
__device__ __forceinline__ void cpa16(uint32_t saddr, const void* g) {
    asm volatile("cp.async.cg.shared.global [%0], [%1], 16;" :: "r"(saddr), "l"(g));
}
__device__ __forceinline__ void cpa_commit() { asm volatile("cp.async.commit_group;"); }
__device__ __forceinline__ void cpa_wait0()  { asm volatile("cp.async.wait_group 0;" ::: "memory"); }

// ============ merged pack kernel ============
// blocks: [0,4096) packx | [4096,4384) conv | [4384,4448) v | [4448,4480) qk
__global__ void k_pack_all(const float* __restrict__ x,  const float* __restrict__ sW,
                           const float* __restrict__ vW, const float* __restrict__ qW,
                           const float* __restrict__ kW)
{
    int bx = blockIdx.x;
    if (bx < 4096) {
        int idx = bx * 256 + threadIdx.x;
        int n4 = (idx & 4095) * 4;
        int kkb = (idx >> 12) & 7;
        int it = (idx >> 15) & 7;
        int b = idx >> 18;
        int kb = kkb >> 2, kk = kkb & 3;
        int K0 = it * 32 + kb * 16 + kk * 2;
        const float* xb = x + ((size_t)b * CIN + K0) * HW + n4;
        float4 r0 = *(const float4*)xb;
        float4 r1 = *(const float4*)(xb + HW);
        float4 r8 = *(const float4*)(xb + 8 * HW);
        float4 r9 = *(const float4*)(xb + 9 * HW);
        uint2* dst = g_xt + ((size_t)((b * 8 + it) * 8 + kkb)) * HW + n4;
        *(uint4*)dst = make_uint4(pkh2(r0.x, r1.x), pkh2(r8.x, r9.x),
                                  pkh2(r0.y, r1.y), pkh2(r8.y, r9.y));
        *(uint4*)(dst + 2) = make_uint4(pkh2(r0.z, r1.z), pkh2(r8.z, r9.z),
                                        pkh2(r0.w, r1.w), pkh2(r8.w, r9.w));
    } else if (bx < 4384) {
        int idx = (bx - 4096) * 256 + threadIdx.x;   // < 73728
        int r = idx & 511, s = idx >> 9;
        int j = r & 3, co = r >> 2;
        int tap = s % 3, t2 = s / 3, ch = t2 & 15, dh = t2 >> 4;
        int ci = ch * 16 + j * 2;
        const float* wp = sW + ((size_t)co * CIN + ci) * 9 + dh * 3 + tap;
        g_wph[idx] = make_uint2(pkh2(wp[0], wp[9]), pkh2(wp[8 * 9], wp[9 * 9]));
    } else if (bx < 4448) {
        int idx = (bx - 4384) * 256 + threadIdx.x;   // < 16384
        int kk = idx & 3, m = (idx >> 2) & 255, kb16 = idx >> 10;
        int K0 = kb16 * 16 + kk * 2;
        const float* wr = vW + (size_t)m * CIN;
        g_Av[idx] = make_uint2(pkh2(wr[K0], wr[K0 + 1]), pkh2(wr[K0 + 8], wr[K0 + 9]));
    } else {
        int idx = (bx - 4448) * 256 + threadIdx.x;   // < 8192
        int kk = idx & 3, m = (idx >> 2) & 127, kb = (idx >> 9) & 1, it = idx >> 10;
        int K0 = it * 32 + kb * 16 + kk * 2;
        const float* wr = (m < 64) ? (qW + (size_t)m * CIN) : (kW + (size_t)(m - 64) * CIN);
        g_Aqk[idx] = make_uint2(pkh2(wr[K0], wr[K0 + 1]), pkh2(wr[K0 + 8], wr[K0 + 9]));
    }
}

// ============ qk body ============
__device__ __forceinline__ void qk_body(
    int b, int n0, uint2* dynsm,
    const float* __restrict__ qs, const float* __restrict__ qb,
    const float* __restrict__ kscale, const float* __restrict__ kshift)
{
    uint2* Asm = dynsm;
    uint2* Bsm = dynsm + 2048;
    float* Sq  = (float*)(dynsm + 4160);
    float* Nn  = Sq + 512;

    const int tid = threadIdx.x, lane = tid & 31, w = tid >> 5;
    const int g = lane >> 2, kk = lane & 3;
    const int mg = w >> 1, ng = w & 1;
    const int m0w = mg * 32, n0w = ng * 64;
    const uint32_t aBase = (uint32_t)__cvta_generic_to_shared(dynsm);
    const uint2* xtb = g_xt + (size_t)b * 8 * 8 * HW + n0;

    float acc[2][8][4];
#pragma unroll
    for (int mt = 0; mt < 2; mt++)
#pragma unroll
        for (int nt = 0; nt < 8; nt++)
#pragma unroll
            for (int i = 0; i < 4; i++) acc[mt][nt][i] = 0.f;

    auto fill = [&](int it, int stage) {
#pragma unroll
        for (int i = 0; i < 2; i++) {
            int j = i * 256 + tid;
            cpa16(aBase + (stage * 1024 + j * 2) * 8, g_Aqk + it * 1024 + j * 2);
        }
#pragma unroll
        for (int i = 0; i < 2; i++) {
            int j = i * 256 + tid;
            int kkb = j >> 6, npair = (j & 63) * 2;
            cpa16(aBase + (2048 + stage * 1056 + kkb * 132 + npair) * 8,
                  xtb + (size_t)((it * 8) + kkb) * HW + npair);
        }
    };

    fill(0, 0); cpa_commit(); cpa_wait0(); __syncthreads();

    for (int it = 0; it < 8; it++) {
        int cur = it & 1, nxt = cur ^ 1;
        if (it < 7) { fill(it + 1, nxt); cpa_commit(); }
        const uint2* Ac = Asm + cur * 1024;
        const uint2* Bc = Bsm + cur * 1056;
#pragma unroll
        for (int kb = 0; kb < 2; kb++) {
            uint2 alo[2], ahi[2];
#pragma unroll
            for (int mt = 0; mt < 2; mt++) {
                alo[mt] = Ac[(kb * 128 + m0w + mt * 16 + g) * 4 + kk];
                ahi[mt] = Ac[(kb * 128 + m0w + mt * 16 + 8 + g) * 4 + kk];
            }
#pragma unroll
            for (int nt = 0; nt < 8; nt++) {
                uint2 bb = Bc[(kb * 4 + kk) * 132 + n0w + nt * 8 + g];
                mma16(acc[0][nt], alo[0], ahi[0], bb);
                mma16(acc[1][nt], alo[1], ahi[1], bb);
            }
        }
        cpa_wait0(); __syncthreads();
    }

    float sq[8][2];
#pragma unroll
    for (int nt = 0; nt < 8; nt++) { sq[nt][0] = 0.f; sq[nt][1] = 0.f; }
#pragma unroll
    for (int mt = 0; mt < 2; mt++) {
        int r0 = m0w + mt * 16 + g, r1 = r0 + 8;
        bool isq = (r0 < 64);
        float sc0 = isq ? qs[r0] : kscale[r0 - 64];
        float sh0 = isq ? qb[r0] : kshift[r0 - 64];
        float sc1 = isq ? qs[r1] : kscale[r1 - 64];
        float sh1 = isq ? qb[r1] : kshift[r1 - 64];
#pragma unroll
        for (int nt = 0; nt < 8; nt++) {
            float v0 = fmaf(acc[mt][nt][0], sc0, sh0);
            float v1 = fmaf(acc[mt][nt][1], sc0, sh0);
            float v2 = fmaf(acc[mt][nt][2], sc1, sh1);
            float v3 = fmaf(acc[mt][nt][3], sc1, sh1);
            acc[mt][nt][0] = v0; acc[mt][nt][1] = v1;
            acc[mt][nt][2] = v2; acc[mt][nt][3] = v3;
            sq[nt][0] += v0 * v0 + v2 * v2;
            sq[nt][1] += v1 * v1 + v3 * v3;
        }
    }
#pragma unroll
    for (int nt = 0; nt < 8; nt++) {
#pragma unroll
        for (int o = 4; o < 32; o <<= 1) {
            sq[nt][0] += __shfl_xor_sync(0xffffffffu, sq[nt][0], o);
            sq[nt][1] += __shfl_xor_sync(0xffffffffu, sq[nt][1], o);
        }
    }
    if (lane < 4) {
#pragma unroll
        for (int nt = 0; nt < 8; nt++) {
            int c = n0w + nt * 8 + lane * 2;
            Sq[mg * 128 + c] = sq[nt][0];
            Sq[mg * 128 + c + 1] = sq[nt][1];
        }
    }
    __syncthreads();
    {
        int col = tid & 127, half = tid >> 7;
        float s = Sq[half * 256 + col] + Sq[half * 256 + 128 + col];
        Nn[half * 128 + col] = 1.f / fmaxf(sqrtf(s), 1e-12f);
    }
    __syncthreads();

    if (mg < 2) {
#pragma unroll
        for (int mt = 0; mt < 2; mt++) {
            int r0 = m0w + mt * 16 + g;
            int row = (r0 >> 4) * 4 + (g >> 1);
#pragma unroll
            for (int nt = 0; nt < 8; nt++) {
                int c = n0w + nt * 8 + (lane & 3) * 2;
                float i0 = Nn[c], i1 = Nn[c + 1];
                float v0 = acc[mt][nt][0] * i0, v1 = acc[mt][nt][1] * i1;
                float v2 = acc[mt][nt][2] * i0, v3 = acc[mt][nt][3] * i1;
                float p0 = __shfl_xor_sync(0xffffffffu, v0, 4);
                float p1 = __shfl_xor_sync(0xffffffffu, v1, 4);
                float p2 = __shfl_xor_sync(0xffffffffu, v2, 4);
                float p3 = __shfl_xor_sync(0xffffffffu, v3, 4);
                if ((g & 1) == 0) {
                    uint2* dst = g_qnth + (size_t)(b * 16 + row) * HW + n0 + c;
                    dst[0] = make_uint2(pkh2(v0, p0), pkh2(v2, p2));
                    dst[1] = make_uint2(pkh2(v1, p1), pkh2(v3, p3));
                }
            }
        }
    } else {
#pragma unroll
        for (int mt = 0; mt < 2; mt++) {
            int r0 = m0w + mt * 16 + g - 64;
#pragma unroll
            for (int nt = 0; nt < 8; nt += 2) {
                int c0 = n0w + nt * 8 + (lane & 3) * 2;
                int kbpix = (n0 + c0) >> 4, kkp = lane & 3;
                float i0 = Nn[128 + c0], i1 = Nn[128 + c0 + 1];
                float i8 = Nn[128 + c0 + 8], i9 = Nn[128 + c0 + 9];
                float a0 = acc[mt][nt][0] * i0,     a1 = acc[mt][nt][1] * i1;
                float b0 = acc[mt][nt + 1][0] * i8, b1 = acc[mt][nt + 1][1] * i9;
                float a2 = acc[mt][nt][2] * i0,     a3 = acc[mt][nt][3] * i1;
                float b2 = acc[mt][nt + 1][2] * i8, b3 = acc[mt][nt + 1][3] * i9;
                g_knt[((size_t)(b * 64 + r0) * 1024 + kbpix) * 4 + kkp] =
                    make_uint2(pkh2(a0, a1), pkh2(b0, b1));
                g_knt[((size_t)(b * 64 + r0 + 8) * 1024 + kbpix) * 4 + kkp] =
                    make_uint2(pkh2(a2, a3), pkh2(b2, b3));
            }
        }
    }
}

// ============ v body ============
__device__ __forceinline__ void v_body(
    int b, int co0, int n0, uint2* dynsm,
    const float* __restrict__ vs, const float* __restrict__ vb)
{
    uint2* Asm = dynsm;
    uint2* Bsm = dynsm + 2048;

    const int tid = threadIdx.x, lane = tid & 31, w = tid >> 5;
    const int g = lane >> 2, kk = lane & 3;
    const int mg = w >> 1, ng = w & 1;
    const int m0w = mg * 32, n0w = ng * 64;
    const uint32_t aBase = (uint32_t)__cvta_generic_to_shared(dynsm);
    const uint2* xtb = g_xt + (size_t)b * 8 * 8 * HW + n0;

    float acc[2][8][4];
#pragma unroll
    for (int mt = 0; mt < 2; mt++)
#pragma unroll
        for (int nt = 0; nt < 8; nt++)
#pragma unroll
            for (int i = 0; i < 4; i++) acc[mt][nt][i] = 0.f;

    auto fill = [&](int it, int stage) {
#pragma unroll
        for (int i = 0; i < 2; i++) {
            int j = i * 256 + tid;
            int kb = j >> 8, r = (j & 255) * 2;
            cpa16(aBase + (stage * 1024 + kb * 512 + r) * 8,
                  g_Av + (size_t)(it * 2 + kb) * 1024 + co0 * 4 + r);
        }
#pragma unroll
        for (int i = 0; i < 2; i++) {
            int j = i * 256 + tid;
            int kkb = j >> 6, npair = (j & 63) * 2;
            cpa16(aBase + (2048 + stage * 1056 + kkb * 132 + npair) * 8,
                  xtb + (size_t)((it * 8) + kkb) * HW + npair);
        }
    };

    fill(0, 0); cpa_commit(); cpa_wait0(); __syncthreads();

    for (int it = 0; it < 8; it++) {
        int cur = it & 1, nxt = cur ^ 1;
        if (it < 7) { fill(it + 1, nxt); cpa_commit(); }
        const uint2* Ac = Asm + cur * 1024;
        const uint2* Bc = Bsm + cur * 1056;
#pragma unroll
        for (int kb = 0; kb < 2; kb++) {
            uint2 alo[2], ahi[2];
#pragma unroll
            for (int mt = 0; mt < 2; mt++) {
                alo[mt] = Ac[(kb * 128 + m0w + mt * 16 + g) * 4 + kk];
                ahi[mt] = Ac[(kb * 128 + m0w + mt * 16 + 8 + g) * 4 + kk];
            }
#pragma unroll
            for (int nt = 0; nt < 8; nt++) {
                uint2 bb = Bc[(kb * 4 + kk) * 132 + n0w + nt * 8 + g];
                mma16(acc[0][nt], alo[0], ahi[0], bb);
                mma16(acc[1][nt], alo[1], ahi[1], bb);
            }
        }
        cpa_wait0(); __syncthreads();
    }

#pragma unroll
    for (int mt = 0; mt < 2; mt++) {
        int co = co0 + m0w + mt * 16 + g;
        float sc0 = vs[co], sh0 = vb[co];
        float sc1 = vs[co + 8], sh1 = vb[co + 8];
#pragma unroll
        for (int nt = 0; nt < 8; nt += 2) {
            int c0 = n0w + nt * 8 + (lane & 3) * 2;
            int kbpix = (n0 + c0) >> 4, kkp = lane & 3;
            float a0 = fmaxf(fmaf(acc[mt][nt][0], sc0, sh0), 0.f);
            float a1 = fmaxf(fmaf(acc[mt][nt][1], sc0, sh0), 0.f);
            float b0 = fmaxf(fmaf(acc[mt][nt + 1][0], sc0, sh0), 0.f);
            float b1 = fmaxf(fmaf(acc[mt][nt + 1][1], sc0, sh0), 0.f);
            float a2 = fmaxf(fmaf(acc[mt][nt][2], sc1, sh1), 0.f);
            float a3 = fmaxf(fmaf(acc[mt][nt][3], sc1, sh1), 0.f);
            float b2 = fmaxf(fmaf(acc[mt][nt + 1][2], sc1, sh1), 0.f);
            float b3 = fmaxf(fmaf(acc[mt][nt + 1][3], sc1, sh1), 0.f);
            g_vt[(((size_t)b * 1024 + kbpix) * 4 + kkp) * 256 + co] =
                make_uint2(pkh2(a0, a1), pkh2(b0, b1));
            g_vt[(((size_t)b * 1024 + kbpix) * 4 + kkp) * 256 + co + 8] =
                make_uint2(pkh2(a2, a3), pkh2(b2, b3));
        }
    }
}

// ============ merged K1+K2: blocks [0,512) qk, [512,1536) v ============
__global__ void __launch_bounds__(256, 2)
k_qkv(const float* __restrict__ qs, const float* __restrict__ qb,
      const float* __restrict__ kscale, const float* __restrict__ kshift,
      const float* __restrict__ vs, const float* __restrict__ vb)
{
    extern __shared__ uint2 dynsm[];
    int bx = blockIdx.x;
    if (bx < 512) {
        qk_body(bx >> 7, (bx & 127) * 128, dynsm, qs, qb, kscale, kshift);
    } else {
        int t = bx - 512;
        v_body(t >> 8, ((t >> 7) & 1) * 128, (t & 127) * 128, dynsm, vs, vb);
    }
}

// ============ K3: partial sim = kn @ v^T (fp16) ============
__global__ void __launch_bounds__(256, 2) k_sim_mma()
{
    extern __shared__ uint2 dynsm[];
    const int b = blockIdx.y, ch = blockIdx.x;
    const int kbp0 = (ch * PIX_PER_CHUNK) >> 4;
    const int tid = threadIdx.x, lane = tid & 31, w = tid >> 5;
    const int g = lane >> 2, kk = lane & 3;
    const int mg = w >> 2, ng = w & 3;
    const int m0w = mg * 32, n0w = ng * 64;
    const uint32_t smBase = (uint32_t)__cvta_generic_to_shared(dynsm);

    float acc[2][8][4];
#pragma unroll
    for (int mt = 0; mt < 2; mt++)
#pragma unroll
        for (int nt = 0; nt < 8; nt++)
#pragma unroll
            for (int i = 0; i < 4; i++) acc[mt][nt][i] = 0.f;

    auto fill = [&](int it, int stage) {
        int kbpix = kbp0 + it * 2;
        {
            int j = tid;
            int m = j >> 2, kb = (j >> 1) & 1, kp = j & 1;
            cpa16(smBase + (stage * 512 + (kb * 64 + m) * 4 + kp * 2) * 8,
                  g_knt + ((size_t)(b * 64 + m) * 1024 + kbpix + kb) * 4 + kp * 2);
        }
#pragma unroll
        for (int i = 0; i < 4; i++) {
            int j = i * 256 + tid;
            int row = j >> 7, npair = (j & 127) * 2;
            int kb = row >> 2, kkr = row & 3;
            cpa16(smBase + (1024 + stage * 2080 + row * 260 + npair) * 8,
                  g_vt + (((size_t)b * 1024 + kbpix + kb) * 4 + kkr) * 256 + npair);
        }
    };

    fill(0, 0); cpa_commit(); cpa_wait0(); __syncthreads();

    for (int it = 0; it < 8; it++) {
        int cur = it & 1, nxt = cur ^ 1;
        if (it < 7) { fill(it + 1, nxt); cpa_commit(); }
        const uint2* Ac = dynsm + cur * 512;
        const uint2* Bc = dynsm + 1024 + cur * 2080;
#pragma unroll
        for (int kb = 0; kb < 2; kb++) {
            uint2 alo[2], ahi[2];
#pragma unroll
            for (int mt = 0; mt < 2; mt++) {
                alo[mt] = Ac[(kb * 64 + m0w + mt * 16 + g) * 4 + kk];
                ahi[mt] = Ac[(kb * 64 + m0w + mt * 16 + 8 + g) * 4 + kk];
            }
#pragma unroll
            for (int nt = 0; nt < 8; nt++) {
                uint2 bb = Bc[(kb * 4 + kk) * 260 + n0w + nt * 8 + g];
                mma16(acc[0][nt], alo[0], ahi[0], bb);
                mma16(acc[1][nt], alo[1], ahi[1], bb);
            }
        }
        cpa_wait0(); __syncthreads();
    }

    float* outp = g_simp + (size_t)(b * NCH + ch) * CQK * CIN;
#pragma unroll
    for (int mt = 0; mt < 2; mt++) {
        int r = m0w + mt * 16 + g;
#pragma unroll
        for (int nt = 0; nt < 8; nt++) {
            int c = n0w + nt * 8 + (lane & 3) * 2;
            *(float2*)&outp[(size_t)r * CIN + c] = make_float2(acc[mt][nt][0], acc[mt][nt][1]);
            *(float2*)&outp[(size_t)(r + 8) * CIN + c] = make_float2(acc[mt][nt][2], acc[mt][nt][3]);
        }
    }
}

// ============ fused reduce + M2 -> fp16 g_AM2h ============
__global__ void k_m2(const float* __restrict__ oW)
{
    __shared__ float ssm[CIN];
    const int b = blockIdx.x >> 6;
    const int c = blockIdx.x & 63;
    const int o = threadIdx.x;
    const float* sp = g_simp + (size_t)b * NCH * CQK * CIN + (size_t)c * CIN + o;
    float s0 = 0.f;
#pragma unroll 8
    for (int ch = 0; ch < NCH; ch++)
        s0 += sp[(size_t)ch * CQK * CIN];
    ssm[o] = s0;
    __syncthreads();
    float s = 0.f;
#pragma unroll 8
    for (int v = 0; v < CIN; v++) s = fmaf(oW[(size_t)o * CIN + v], ssm[v], s);
    int kb = c >> 4, rem = c & 15;
    int hi = rem >> 3, kkv = (rem & 7) >> 1, low = rem & 1;
    __half* hp = (__half*)g_AM2h;
    hp[((((size_t)(b * 4 + kb) * 256 + o) * 4 + kkv) << 2) + hi * 2 + low] = __float2half(s);
}

// ============ K4: ctx mma (fp16) -> fuse -> fp16 pairs g_fth ============
__global__ void __launch_bounds__(256, 2)
k_ctx_mma(const float* __restrict__ x, const float* __restrict__ up,
          const float* __restrict__ os, const float* __restrict__ ob)
{
    extern __shared__ uint2 dynsm[];
    uint2* Asm = dynsm;
    uint2* Bsm = dynsm + 2048;
    float* upH = (float*)(dynsm + 4160);

    const int b = blockIdx.z;
    const int co0 = blockIdx.y * 128;
    const int h = blockIdx.x;
    const int n0 = h * Ww;
    const int tid = threadIdx.x, lane = tid & 31, w = tid >> 5;
    const int g = lane >> 2, kk = lane & 3;
    const int mg = w >> 1, ng = w & 1;
    const int m0w = mg * 32, n0w = ng * 64;
    const uint32_t aBase = (uint32_t)__cvta_generic_to_shared(dynsm);

#pragma unroll
    for (int i = 0; i < 4; i++) {
        int j = i * 256 + tid;
        int kb = j >> 8, r = j & 255;
        int m = r >> 1, kp = r & 1;
        cpa16(aBase + (kb * 512 + m * 4 + kp * 2) * 8,
              g_AM2h + ((size_t)(b * 4 + kb) * 256 + co0 + m) * 4 + kp * 2);
    }
#pragma unroll
    for (int i = 0; i < 4; i++) {
        int j = i * 256 + tid;
        int row = j >> 6, npair = (j & 63) * 2;
        cpa16(aBase + (2048 + row * 132 + npair) * 8,
              g_qnth + (size_t)(b * 16 + row) * HW + n0 + npair);
    }
    cpa_commit();

    {
        float shf = 0.5f * h - 0.25f;
        int h0 = (int)floorf(shf);
        float wh1 = shf - (float)h0;
        int h0c = h0 < 0 ? 0 : h0;
        int h1c = (h0 + 1) > 63 ? 63 : (h0 + 1);
        const float* ub = up + ((size_t)(b * CIN + co0)) * 64 * 64;
#pragma unroll
        for (int i = 0; i < 32; i++) {
            int idx = i * 256 + tid;
            int r = idx >> 6, sw = idx & 63;
            upH[r * 64 + sw] = (1.f - wh1) * ub[(r * 64 + h0c) * 64 + sw]
                             + wh1 * ub[(r * 64 + h1c) * 64 + sw];
        }
    }
    cpa_wait0(); __syncthreads();

    float acc[2][8][4];
#pragma unroll
    for (int mt = 0; mt < 2; mt++)
#pragma unroll
        for (int nt = 0; nt < 8; nt++)
#pragma unroll
            for (int i = 0; i < 4; i++) acc[mt][nt][i] = 0.f;

#pragma unroll
    for (int kb = 0; kb < 4; kb++) {
        uint2 alo[2], ahi[2];
#pragma unroll
        for (int mt = 0; mt < 2; mt++) {
            alo[mt] = Asm[kb * 512 + (m0w + mt * 16 + g) * 4 + kk];
            ahi[mt] = Asm[kb * 512 + (m0w + mt * 16 + 8 + g) * 4 + kk];
        }
#pragma unroll
        for (int nt = 0; nt < 8; nt++) {
            uint2 bb = Bsm[(kb * 4 + kk) * 132 + n0w + nt * 8 + g];
            mma16(acc[0][nt], alo[0], ahi[0], bb);
            mma16(acc[1][nt], alo[1], ahi[1], bb);
        }
    }

    const float* xb = x + ((size_t)b * CIN + co0) * HW + n0;
#pragma unroll
    for (int mt = 0; mt < 2; mt++) {
        int m = m0w + mt * 16 + g;
        int co = co0 + m;
        float sc0 = os[co], sh0 = ob[co];
        float sc1 = os[co + 8], sh1 = ob[co + 8];
        int ch16 = co >> 4;
        int jidx = g >> 1;
#pragma unroll
        for (int nt = 0; nt < 8; nt++) {
            int c0 = n0w + nt * 8 + (lane & 3) * 2;
            int c1 = c0 + 1;
            float sw0 = 0.5f * c0 - 0.25f, sw1 = 0.5f * c1 - 0.25f;
            int wa0 = (int)floorf(sw0), wa1 = (int)floorf(sw1);
            float t0 = sw0 - (float)wa0, t1 = sw1 - (float)wa1;
            int w00 = wa0 < 0 ? 0 : wa0, w01 = (wa0 + 1) > 63 ? 63 : (wa0 + 1);
            int w10 = wa1 < 0 ? 0 : wa1, w11 = (wa1 + 1) > 63 ? 63 : (wa1 + 1);

            float u0a = (1.f - t0) * upH[m * 64 + w00] + t0 * upH[m * 64 + w01];
            float u1a = (1.f - t1) * upH[m * 64 + w10] + t1 * upH[m * 64 + w11];
            float u0b = (1.f - t0) * upH[(m + 8) * 64 + w00] + t0 * upH[(m + 8) * 64 + w01];
            float u1b = (1.f - t1) * upH[(m + 8) * 64 + w10] + t1 * upH[(m + 8) * 64 + w11];

            float f0 = fmaxf(fmaf(acc[mt][nt][0], sc0, sh0), 0.f) + xb[(size_t)m * HW + c0] + u0a;
            float f1 = fmaxf(fmaf(acc[mt][nt][1], sc0, sh0), 0.f) + xb[(size_t)m * HW + c1] + u1a;
            float f2 = fmaxf(fmaf(acc[mt][nt][2], sc1, sh1), 0.f) + xb[(size_t)(m + 8) * HW + c0] + u0b;
            float f3 = fmaxf(fmaf(acc[mt][nt][3], sc1, sh1), 0.f) + xb[(size_t)(m + 8) * HW + c1] + u1b;

            float p0 = __shfl_xor_sync(0xffffffffu, f0, 4);
            float p1 = __shfl_xor_sync(0xffffffffu, f1, 4);
            float p2 = __shfl_xor_sync(0xffffffffu, f2, 4);
            float p3 = __shfl_xor_sync(0xffffffffu, f3, 4);
            if ((g & 1) == 0) {
                size_t base = (((size_t)(b * 16 + ch16) * 4 + jidx) * 130 + h + 1) * 132 + 1;
                g_fth[base + c0] = make_uint2(pkh2(f0, p0), pkh2(f2, p2));
                g_fth[base + c1] = make_uint2(pkh2(f1, p1), pkh2(f3, p3));
            }
        }
    }
}

// ============ K5: 3x3 conv, fp16, 4 rows x 64 co x 128 w per block ============
__global__ void __launch_bounds__(512, 1)
k_conv_h(const float* __restrict__ ss, const float* __restrict__ sb,
         float* __restrict__ out)
{
    extern __shared__ uint2 csm[];
    uint2* Ism = csm;
    uint2* Wsm = csm + 6336;

    const int h0 = blockIdx.x * 4;
    const int co0 = blockIdx.y * 64;
    const int b = blockIdx.z;
    const int tid = threadIdx.x, lane = tid & 31, w = tid >> 5;
    const int g = lane >> 2, kk = lane & 3;
    const int mg = w >> 3, ng = w & 7;
    const int m0w = mg * 32, n0w = ng * 64;
    const uint32_t smBase = (uint32_t)__cvta_generic_to_shared(csm);

    float acc[2][8][4];
#pragma unroll
    for (int mt = 0; mt < 2; mt++)
#pragma unroll
        for (int nt = 0; nt < 8; nt++)
#pragma unroll
            for (int i = 0; i < 4; i++) acc[mt][nt][i] = 0.f;

    const uint2* ftb = g_fth + (size_t)b * 16 * 4 * 130 * 132;

    auto fill = [&](int ch, int stage) {
        for (int j = tid; j < 1560; j += 512) {
            int rowplane = j / 65;
            int colpair = (j - rowplane * 65) * 2;
            int row = rowplane >> 2, jj = rowplane & 3;
            cpa16(smBase + (stage * 3168 + (row * 4 + jj) * 132 + colpair) * 8,
                  ftb + ((size_t)(ch * 4 + jj) * 130 + h0 + row) * 132 + colpair);
        }
        for (int j = tid; j < 1152; j += 512) {
            int u = j * 2;
            int grp = u >> 8, off = u & 255;
            int dh = grp / 3, tap = grp - dh * 3;
            cpa16(smBase + (6336 + stage * 2304 + grp * 256 + off) * 8,
                  g_wph + (size_t)((dh * 16 + ch) * 3 + tap) * 512 + co0 * 4 + off);
        }
    };

    fill(0, 0); cpa_commit(); cpa_wait0(); __syncthreads();

    for (int it = 0; it < 16; it++) {
        int cur = it & 1, nxt = cur ^ 1;
        if (it < 15) { fill(it + 1, nxt); cpa_commit(); }

        const uint2* Ic = Ism + cur * 3168;
        const uint2* Wc = Wsm + cur * 2304;
#pragma unroll
        for (int dh = 0; dh < 3; dh++) {
#pragma unroll
            for (int tap = 0; tap < 3; tap++) {
                const uint2* wb = Wc + (dh * 3 + tap) * 256;
                uint2 alo[2], ahi[2];
#pragma unroll
                for (int mt = 0; mt < 2; mt++) {
                    alo[mt] = wb[(m0w + mt * 16 + g) * 4 + kk];
                    ahi[mt] = wb[(m0w + mt * 16 + 8 + g) * 4 + kk];
                }
#pragma unroll
                for (int nt = 0; nt < 8; nt++) {
                    int n = n0w + nt * 8 + g;
                    int rrow = n >> 7, wx = n & 127;
                    uint2 bb = Ic[((rrow + dh) * 4 + kk) * 132 + wx + tap];
                    mma16(acc[0][nt], alo[0], ahi[0], bb);
                    mma16(acc[1][nt], alo[1], ahi[1], bb);
                }
            }
        }
        cpa_wait0(); __syncthreads();
    }

#pragma unroll
    for (int mt = 0; mt < 2; mt++) {
        int co = co0 + m0w + mt * 16 + g;
        float sc0 = ss[co], sh0 = sb[co];
        float sc1 = ss[co + 8], sh1 = sb[co + 8];
#pragma unroll
        for (int nt = 0; nt < 8; nt++) {
            int n = n0w + nt * 8 + (lane & 3) * 2;
            int r = n >> 7, wx = n & 127;
            float* o0p = out + (((size_t)b * CS + co) * Hh + h0 + r) * Ww + wx;
            float* o1p = out + (((size_t)b * CS + co + 8) * Hh + h0 + r) * Ww + wx;
            float2 o0 = make_float2(fmaxf(fmaf(acc[mt][nt][0], sc0, sh0), 0.f),
                                    fmaxf(fmaf(acc[mt][nt][1], sc0, sh0), 0.f));
            float2 o1 = make_float2(fmaxf(fmaf(acc[mt][nt][2], sc1, sh1), 0.f),
                                    fmaxf(fmaf(acc[mt][nt][3], sc1, sh1), 0.f));
            *(float2*)o0p = o0;
            *(float2*)o1p = o1;
        }
    }
}

// ============================================================
extern "C" void kernel_launch(void* const* d_in, const int* in_sizes, int n_in,
                              void* d_out, int out_size)
{
    (void)in_sizes; (void)n_in; (void)out_size;
    const float* x        = (const float*)d_in[0];
    const float* up       = (const float*)d_in[1];
    const float* qW       = (const float*)d_in[2];
    const float* q_scale  = (const float*)d_in[3];
    const float* q_shift  = (const float*)d_in[4];
    const float* kW       = (const float*)d_in[5];
    const float* k_scale  = (const float*)d_in[6];
    const float* k_shift  = (const float*)d_in[7];
    const float* vW       = (const float*)d_in[8];
    const float* v_scale  = (const float*)d_in[9];
    const float* v_shift  = (const float*)d_in[10];
    const float* oW       = (const float*)d_in[11];
    const float* o_scale  = (const float*)d_in[12];
    const float* o_shift  = (const float*)d_in[13];
    const float* sW       = (const float*)d_in[14];
    const float* s_scale  = (const float*)d_in[15];
    const float* s_shift  = (const float*)d_in[16];
    float* out = (float*)d_out;

    cudaFuncSetAttribute(k_qkv,     cudaFuncAttributeMaxDynamicSharedMemorySize, 36352);
    cudaFuncSetAttribute(k_sim_mma, cudaFuncAttributeMaxDynamicSharedMemorySize, 41472);
    cudaFuncSetAttribute(k_ctx_mma, cudaFuncAttributeMaxDynamicSharedMemorySize, 66048);
    cudaFuncSetAttribute(k_conv_h,  cudaFuncAttributeMaxDynamicSharedMemorySize, 87552);

    k_pack_all<<<4480, 256>>>(x, sW, vW, qW, kW);
    k_qkv<<<1536, 256, 36352>>>(q_scale, q_shift, k_scale, k_shift, v_scale, v_shift);
    k_sim_mma<<<dim3(NCH, Bn), 256, 41472>>>();
    k_m2<<<Bn * CQK, 256>>>(oW);
    k_ctx_mma<<<dim3(Hh, 2, Bn), 256, 66048>>>(x, up, o_scale, o_shift);
    k_conv_h<<<dim3(Hh / 4, 2, Bn), 512, 87552>>>(s_scale, s_shift, out);
}

// round 13
// speedup vs baseline: 1.8017x; 1.1172x over previous
#include <cuda_runtime.h>
#include <cuda_fp16.h>
#include <math.h>
#include <stdint.h>

#define Bn   4
#define CIN  256
#define CQK  64
#define CS   128
#define Hh   128
#define Ww   128
#define HW   (Hh*Ww)
#define NCH  64
#define PIX_PER_CHUNK (HW/NCH)

__device__ float g_simp[Bn*NCH*CQK*CIN];
__device__ float g_sim [Bn*CQK*CIN];
__device__ float g_oWT [CIN*CIN];

__device__ __align__(16) uint2 g_Aqk[8192];
__device__ __align__(16) uint2 g_Av [16384];
__device__ __align__(16) uint2 g_xt [Bn*8*8*HW];
__device__ __align__(16) uint2 g_knt[Bn*64*1024*4];
__device__ __align__(16) uint2 g_vt [Bn*1024*4*256];
__device__ __align__(16) uint2 g_AM2h[Bn*4096];
__device__ __align__(16) uint2 g_qnth[Bn*16*HW];
__device__ __align__(16) uint2 g_wph[73728];
__device__ __align__(16) uint2 g_fth[Bn*16*4*130*132];

__device__ __forceinline__ uint32_t pkh2(float lo, float hi) {
    uint32_t r; asm("cvt.rn.f16x2.f32 %0, %1, %2;" : "=r"(r) : "f"(hi), "f"(lo)); return r;
}
__device__ __forceinline__ void mma16(float* c, uint2 alo, uint2 ahi, uint2 b) {
    asm volatile(
        "mma.sync.aligned.m16n8k16.row.col.f32.f16.f16.f32 "
        "{%0,%1,%2,%3}, {%4,%5,%6,%7}, {%8,%9}, {%0,%1,%2,%3};"
        : "+f"(c[0]), "+f"(c[1]), "+f"(c[2]), "+f"(c[3])
        : "r"(alo.x), "r"(ahi.x), "r"(alo.y), "r"(ahi.y), "r"(b.x), "r"(b.y));
}
__device__ __forceinline__ void cpa16(uint32_t saddr, const void* g) {
    asm volatile("cp.async.cg.shared.global [%0], [%1], 16;" :: "r"(saddr), "l"(g));
}
__device__ __forceinline__ void cpa_commit() { asm volatile("cp.async.commit_group;"); }
__device__ __forceinline__ void cpa_wait0()  { asm volatile("cp.async.wait_group 0;" ::: "memory"); }

// ============ merged pack kernel ============
// blocks: [0,4096) packx | [4096,4384) conv | [4384,4448) v | [4448,4480) qk | [4480,4736) oWT
__global__ void k_pack_all(const float* __restrict__ x,  const float* __restrict__ sW,
                           const float* __restrict__ vW, const float* __restrict__ qW,
                           const float* __restrict__ kW, const float* __restrict__ oW)
{
    int bx = blockIdx.x;
    if (bx < 4096) {
        int idx = bx * 256 + threadIdx.x;
        int n4 = (idx & 4095) * 4;
        int kkb = (idx >> 12) & 7;
        int it = (idx >> 15) & 7;
        int b = idx >> 18;
        int kb = kkb >> 2, kk = kkb & 3;
        int K0 = it * 32 + kb * 16 + kk * 2;
        const float* xb = x + ((size_t)b * CIN + K0) * HW + n4;
        float4 r0 = *(const float4*)xb;
        float4 r1 = *(const float4*)(xb + HW);
        float4 r8 = *(const float4*)(xb + 8 * HW);
        float4 r9 = *(const float4*)(xb + 9 * HW);
        uint2* dst = g_xt + ((size_t)((b * 8 + it) * 8 + kkb)) * HW + n4;
        *(uint4*)dst = make_uint4(pkh2(r0.x, r1.x), pkh2(r8.x, r9.x),
                                  pkh2(r0.y, r1.y), pkh2(r8.y, r9.y));
        *(uint4*)(dst + 2) = make_uint4(pkh2(r0.z, r1.z), pkh2(r8.z, r9.z),
                                        pkh2(r0.w, r1.w), pkh2(r8.w, r9.w));
    } else if (bx < 4384) {
        int idx = (bx - 4096) * 256 + threadIdx.x;
        int r = idx & 511, s = idx >> 9;
        int j = r & 3, co = r >> 2;
        int tap = s % 3, t2 = s / 3, ch = t2 & 15, dh = t2 >> 4;
        int ci = ch * 16 + j * 2;
        const float* wp = sW + ((size_t)co * CIN + ci) * 9 + dh * 3 + tap;
        g_wph[idx] = make_uint2(pkh2(wp[0], wp[9]), pkh2(wp[8 * 9], wp[9 * 9]));
    } else if (bx < 4448) {
        int idx = (bx - 4384) * 256 + threadIdx.x;
        int kk = idx & 3, m = (idx >> 2) & 255, kb16 = idx >> 10;
        int K0 = kb16 * 16 + kk * 2;
        const float* wr = vW + (size_t)m * CIN;
        g_Av[idx] = make_uint2(pkh2(wr[K0], wr[K0 + 1]), pkh2(wr[K0 + 8], wr[K0 + 9]));
    } else if (bx < 4480) {
        int idx = (bx - 4448) * 256 + threadIdx.x;
        int kk = idx & 3, m = (idx >> 2) & 127, kb = (idx >> 9) & 1, it = idx >> 10;
        int K0 = it * 32 + kb * 16 + kk * 2;
        const float* wr = (m < 64) ? (qW + (size_t)m * CIN) : (kW + (size_t)(m - 64) * CIN);
        g_Aqk[idx] = make_uint2(pkh2(wr[K0], wr[K0 + 1]), pkh2(wr[K0 + 8], wr[K0 + 9]));
    } else {
        int idx = (bx - 4480) * 256 + threadIdx.x;   // < 65536
        int o = idx & 255, v = idx >> 8;
        g_oWT[v * CIN + o] = oW[o * CIN + v];
    }
}

// ============ qk body ============
__device__ __forceinline__ void qk_body(
    int b, int n0, uint2* dynsm,
    const float* __restrict__ qs, const float* __restrict__ qb,
    const float* __restrict__ kscale, const float* __restrict__ kshift)
{
    uint2* Asm = dynsm;
    uint2* Bsm = dynsm + 2048;
    float* Sq  = (float*)(dynsm + 4160);
    float* Nn  = Sq + 512;

    const int tid = threadIdx.x, lane = tid & 31, w = tid >> 5;
    const int g = lane >> 2, kk = lane & 3;
    const int mg = w >> 1, ng = w & 1;
    const int m0w = mg * 32, n0w = ng * 64;
    const uint32_t aBase = (uint32_t)__cvta_generic_to_shared(dynsm);
    const uint2* xtb = g_xt + (size_t)b * 8 * 8 * HW + n0;

    float acc[2][8][4];
#pragma unroll
    for (int mt = 0; mt < 2; mt++)
#pragma unroll
        for (int nt = 0; nt < 8; nt++)
#pragma unroll
            for (int i = 0; i < 4; i++) acc[mt][nt][i] = 0.f;

    auto fill = [&](int it, int stage) {
#pragma unroll
        for (int i = 0; i < 2; i++) {
            int j = i * 256 + tid;
            cpa16(aBase + (stage * 1024 + j * 2) * 8, g_Aqk + it * 1024 + j * 2);
        }
#pragma unroll
        for (int i = 0; i < 2; i++) {
            int j = i * 256 + tid;
            int kkb = j >> 6, npair = (j & 63) * 2;
            cpa16(aBase + (2048 + stage * 1056 + kkb * 132 + npair) * 8,
                  xtb + (size_t)((it * 8) + kkb) * HW + npair);
        }
    };

    fill(0, 0); cpa_commit(); cpa_wait0(); __syncthreads();

    for (int it = 0; it < 8; it++) {
        int cur = it & 1, nxt = cur ^ 1;
        if (it < 7) { fill(it + 1, nxt); cpa_commit(); }
        const uint2* Ac = Asm + cur * 1024;
        const uint2* Bc = Bsm + cur * 1056;
#pragma unroll
        for (int kb = 0; kb < 2; kb++) {
            uint2 alo[2], ahi[2];
#pragma unroll
            for (int mt = 0; mt < 2; mt++) {
                alo[mt] = Ac[(kb * 128 + m0w + mt * 16 + g) * 4 + kk];
                ahi[mt] = Ac[(kb * 128 + m0w + mt * 16 + 8 + g) * 4 + kk];
            }
#pragma unroll
            for (int nt = 0; nt < 8; nt++) {
                uint2 bb = Bc[(kb * 4 + kk) * 132 + n0w + nt * 8 + g];
                mma16(acc[0][nt], alo[0], ahi[0], bb);
                mma16(acc[1][nt], alo[1], ahi[1], bb);
            }
        }
        cpa_wait0(); __syncthreads();
    }

    float sq[8][2];
#pragma unroll
    for (int nt = 0; nt < 8; nt++) { sq[nt][0] = 0.f; sq[nt][1] = 0.f; }
#pragma unroll
    for (int mt = 0; mt < 2; mt++) {
        int r0 = m0w + mt * 16 + g, r1 = r0 + 8;
        bool isq = (r0 < 64);
        float sc0 = isq ? qs[r0] : kscale[r0 - 64];
        float sh0 = isq ? qb[r0] : kshift[r0 - 64];
        float sc1 = isq ? qs[r1] : kscale[r1 - 64];
        float sh1 = isq ? qb[r1] : kshift[r1 - 64];
#pragma unroll
        for (int nt = 0; nt < 8; nt++) {
            float v0 = fmaf(acc[mt][nt][0], sc0, sh0);
            float v1 = fmaf(acc[mt][nt][1], sc0, sh0);
            float v2 = fmaf(acc[mt][nt][2], sc1, sh1);
            float v3 = fmaf(acc[mt][nt][3], sc1, sh1);
            acc[mt][nt][0] = v0; acc[mt][nt][1] = v1;
            acc[mt][nt][2] = v2; acc[mt][nt][3] = v3;
            sq[nt][0] += v0 * v0 + v2 * v2;
            sq[nt][1] += v1 * v1 + v3 * v3;
        }
    }
#pragma unroll
    for (int nt = 0; nt < 8; nt++) {
#pragma unroll
        for (int o = 4; o < 32; o <<= 1) {
            sq[nt][0] += __shfl_xor_sync(0xffffffffu, sq[nt][0], o);
            sq[nt][1] += __shfl_xor_sync(0xffffffffu, sq[nt][1], o);
        }
    }
    if (lane < 4) {
#pragma unroll
        for (int nt = 0; nt < 8; nt++) {
            int c = n0w + nt * 8 + lane * 2;
            Sq[mg * 128 + c] = sq[nt][0];
            Sq[mg * 128 + c + 1] = sq[nt][1];
        }
    }
    __syncthreads();
    {
        int col = tid & 127, half = tid >> 7;
        float s = Sq[half * 256 + col] + Sq[half * 256 + 128 + col];
        Nn[half * 128 + col] = 1.f / fmaxf(sqrtf(s), 1e-12f);
    }
    __syncthreads();

    if (mg < 2) {
#pragma unroll
        for (int mt = 0; mt < 2; mt++) {
            int r0 = m0w + mt * 16 + g;
            int row = (r0 >> 4) * 4 + (g >> 1);
#pragma unroll
            for (int nt = 0; nt < 8; nt++) {
                int c = n0w + nt * 8 + (lane & 3) * 2;
                float i0 = Nn[c], i1 = Nn[c + 1];
                float v0 = acc[mt][nt][0] * i0, v1 = acc[mt][nt][1] * i1;
                float v2 = acc[mt][nt][2] * i0, v3 = acc[mt][nt][3] * i1;
                float p0 = __shfl_xor_sync(0xffffffffu, v0, 4);
                float p1 = __shfl_xor_sync(0xffffffffu, v1, 4);
                float p2 = __shfl_xor_sync(0xffffffffu, v2, 4);
                float p3 = __shfl_xor_sync(0xffffffffu, v3, 4);
                if ((g & 1) == 0) {
                    uint2* dst = g_qnth + (size_t)(b * 16 + row) * HW + n0 + c;
                    dst[0] = make_uint2(pkh2(v0, p0), pkh2(v2, p2));
                    dst[1] = make_uint2(pkh2(v1, p1), pkh2(v3, p3));
                }
            }
        }
    } else {
#pragma unroll
        for (int mt = 0; mt < 2; mt++) {
            int r0 = m0w + mt * 16 + g - 64;
#pragma unroll
            for (int nt = 0; nt < 8; nt += 2) {
                int c0 = n0w + nt * 8 + (lane & 3) * 2;
                int kbpix = (n0 + c0) >> 4, kkp = lane & 3;
                float i0 = Nn[128 + c0], i1 = Nn[128 + c0 + 1];
                float i8 = Nn[128 + c0 + 8], i9 = Nn[128 + c0 + 9];
                float a0 = acc[mt][nt][0] * i0,     a1 = acc[mt][nt][1] * i1;
                float b0 = acc[mt][nt + 1][0] * i8, b1 = acc[mt][nt + 1][1] * i9;
                float a2 = acc[mt][nt][2] * i0,     a3 = acc[mt][nt][3] * i1;
                float b2 = acc[mt][nt + 1][2] * i8, b3 = acc[mt][nt + 1][3] * i9;
                g_knt[((size_t)(b * 64 + r0) * 1024 + kbpix) * 4 + kkp] =
                    make_uint2(pkh2(a0, a1), pkh2(b0, b1));
                g_knt[((size_t)(b * 64 + r0 + 8) * 1024 + kbpix) * 4 + kkp] =
                    make_uint2(pkh2(a2, a3), pkh2(b2, b3));
            }
        }
    }
}

// ============ v body ============
__device__ __forceinline__ void v_body(
    int b, int co0, int n0, uint2* dynsm,
    const float* __restrict__ vs, const float* __restrict__ vb)
{
    uint2* Asm = dynsm;
    uint2* Bsm = dynsm + 2048;

    const int tid = threadIdx.x, lane = tid & 31, w = tid >> 5;
    const int g = lane >> 2, kk = lane & 3;
    const int mg = w >> 1, ng = w & 1;
    const int m0w = mg * 32, n0w = ng * 64;
    const uint32_t aBase = (uint32_t)__cvta_generic_to_shared(dynsm);
    const uint2* xtb = g_xt + (size_t)b * 8 * 8 * HW + n0;

    float acc[2][8][4];
#pragma unroll
    for (int mt = 0; mt < 2; mt++)
#pragma unroll
        for (int nt = 0; nt < 8; nt++)
#pragma unroll
            for (int i = 0; i < 4; i++) acc[mt][nt][i] = 0.f;

    auto fill = [&](int it, int stage) {
#pragma unroll
        for (int i = 0; i < 2; i++) {
            int j = i * 256 + tid;
            int kb = j >> 8, r = (j & 255) * 2;
            cpa16(aBase + (stage * 1024 + kb * 512 + r) * 8,
                  g_Av + (size_t)(it * 2 + kb) * 1024 + co0 * 4 + r);
        }
#pragma unroll
        for (int i = 0; i < 2; i++) {
            int j = i * 256 + tid;
            int kkb = j >> 6, npair = (j & 63) * 2;
            cpa16(aBase + (2048 + stage * 1056 + kkb * 132 + npair) * 8,
                  xtb + (size_t)((it * 8) + kkb) * HW + npair);
        }
    };

    fill(0, 0); cpa_commit(); cpa_wait0(); __syncthreads();

    for (int it = 0; it < 8; it++) {
        int cur = it & 1, nxt = cur ^ 1;
        if (it < 7) { fill(it + 1, nxt); cpa_commit(); }
        const uint2* Ac = Asm + cur * 1024;
        const uint2* Bc = Bsm + cur * 1056;
#pragma unroll
        for (int kb = 0; kb < 2; kb++) {
            uint2 alo[2], ahi[2];
#pragma unroll
            for (int mt = 0; mt < 2; mt++) {
                alo[mt] = Ac[(kb * 128 + m0w + mt * 16 + g) * 4 + kk];
                ahi[mt] = Ac[(kb * 128 + m0w + mt * 16 + 8 + g) * 4 + kk];
            }
#pragma unroll
            for (int nt = 0; nt < 8; nt++) {
                uint2 bb = Bc[(kb * 4 + kk) * 132 + n0w + nt * 8 + g];
                mma16(acc[0][nt], alo[0], ahi[0], bb);
                mma16(acc[1][nt], alo[1], ahi[1], bb);
            }
        }
        cpa_wait0(); __syncthreads();
    }

#pragma unroll
    for (int mt = 0; mt < 2; mt++) {
        int co = co0 + m0w + mt * 16 + g;
        float sc0 = vs[co], sh0 = vb[co];
        float sc1 = vs[co + 8], sh1 = vb[co + 8];
#pragma unroll
        for (int nt = 0; nt < 8; nt += 2) {
            int c0 = n0w + nt * 8 + (lane & 3) * 2;
            int kbpix = (n0 + c0) >> 4, kkp = lane & 3;
            float a0 = fmaxf(fmaf(acc[mt][nt][0], sc0, sh0), 0.f);
            float a1 = fmaxf(fmaf(acc[mt][nt][1], sc0, sh0), 0.f);
            float b0 = fmaxf(fmaf(acc[mt][nt + 1][0], sc0, sh0), 0.f);
            float b1 = fmaxf(fmaf(acc[mt][nt + 1][1], sc0, sh0), 0.f);
            float a2 = fmaxf(fmaf(acc[mt][nt][2], sc1, sh1), 0.f);
            float a3 = fmaxf(fmaf(acc[mt][nt][3], sc1, sh1), 0.f);
            float b2 = fmaxf(fmaf(acc[mt][nt + 1][2], sc1, sh1), 0.f);
            float b3 = fmaxf(fmaf(acc[mt][nt + 1][3], sc1, sh1), 0.f);
            g_vt[(((size_t)b * 1024 + kbpix) * 4 + kkp) * 256 + co] =
                make_uint2(pkh2(a0, a1), pkh2(b0, b1));
            g_vt[(((size_t)b * 1024 + kbpix) * 4 + kkp) * 256 + co + 8] =
                make_uint2(pkh2(a2, a3), pkh2(b2, b3));
        }
    }
}

// ============ merged K1+K2 ============
__global__ void __launch_bounds__(256, 2)
k_qkv(const float* __restrict__ qs, const float* __restrict__ qb,
      const float* __restrict__ kscale, const float* __restrict__ kshift,
      const float* __restrict__ vs, const float* __restrict__ vb)
{
    extern __shared__ uint2 dynsm[];
    int bx = blockIdx.x;
    if (bx < 512) {
        qk_body(bx >> 7, (bx & 127) * 128, dynsm, qs, qb, kscale, kshift);
    } else {
        int t = bx - 512;
        v_body(t >> 8, ((t >> 7) & 1) * 128, (t & 127) * 128, dynsm, vs, vb);
    }
}

// ============ K3: partial sim ============
__global__ void __launch_bounds__(256, 2) k_sim_mma()
{
    extern __shared__ uint2 dynsm[];
    const int b = blockIdx.y, ch = blockIdx.x;
    const int kbp0 = (ch * PIX_PER_CHUNK) >> 4;
    const int tid = threadIdx.x, lane = tid & 31, w = tid >> 5;
    const int g = lane >> 2, kk = lane & 3;
    const int mg = w >> 2, ng = w & 3;
    const int m0w = mg * 32, n0w = ng * 64;
    const uint32_t smBase = (uint32_t)__cvta_generic_to_shared(dynsm);

    float acc[2][8][4];
#pragma unroll
    for (int mt = 0; mt < 2; mt++)
#pragma unroll
        for (int nt = 0; nt < 8; nt++)
#pragma unroll
            for (int i = 0; i < 4; i++) acc[mt][nt][i] = 0.f;

    auto fill = [&](int it, int stage) {
        int kbpix = kbp0 + it * 2;
        {
            int j = tid;
            int m = j >> 2, kb = (j >> 1) & 1, kp = j & 1;
            cpa16(smBase + (stage * 512 + (kb * 64 + m) * 4 + kp * 2) * 8,
                  g_knt + ((size_t)(b * 64 + m) * 1024 + kbpix + kb) * 4 + kp * 2);
        }
#pragma unroll
        for (int i = 0; i < 4; i++) {
            int j = i * 256 + tid;
            int row = j >> 7, npair = (j & 127) * 2;
            int kb = row >> 2, kkr = row & 3;
            cpa16(smBase + (1024 + stage * 2080 + row * 260 + npair) * 8,
                  g_vt + (((size_t)b * 1024 + kbpix + kb) * 4 + kkr) * 256 + npair);
        }
    };

    fill(0, 0); cpa_commit(); cpa_wait0(); __syncthreads();

    for (int it = 0; it < 8; it++) {
        int cur = it & 1, nxt = cur ^ 1;
        if (it < 7) { fill(it + 1, nxt); cpa_commit(); }
        const uint2* Ac = dynsm + cur * 512;
        const uint2* Bc = dynsm + 1024 + cur * 2080;
#pragma unroll
        for (int kb = 0; kb < 2; kb++) {
            uint2 alo[2], ahi[2];
#pragma unroll
            for (int mt = 0; mt < 2; mt++) {
                alo[mt] = Ac[(kb * 64 + m0w + mt * 16 + g) * 4 + kk];
                ahi[mt] = Ac[(kb * 64 + m0w + mt * 16 + 8 + g) * 4 + kk];
            }
#pragma unroll
            for (int nt = 0; nt < 8; nt++) {
                uint2 bb = Bc[(kb * 4 + kk) * 260 + n0w + nt * 8 + g];
                mma16(acc[0][nt], alo[0], ahi[0], bb);
                mma16(acc[1][nt], alo[1], ahi[1], bb);
            }
        }
        cpa_wait0(); __syncthreads();
    }

    float* outp = g_simp + (size_t)(b * NCH + ch) * CQK * CIN;
#pragma unroll
    for (int mt = 0; mt < 2; mt++) {
        int r = m0w + mt * 16 + g;
#pragma unroll
        for (int nt = 0; nt < 8; nt++) {
            int c = n0w + nt * 8 + (lane & 3) * 2;
            *(float2*)&outp[(size_t)r * CIN + c] = make_float2(acc[mt][nt][0], acc[mt][nt][1]);
            *(float2*)&outp[(size_t)(r + 8) * CIN + c] = make_float2(acc[mt][nt][2], acc[mt][nt][3]);
        }
    }
}

// ============ K3b: reduce partials -> g_sim ============
__global__ void k_simred()
{
    int o = blockIdx.x * 256 + threadIdx.x;    // [b][c][o256]
    int b = o >> 14;
    int cv = o & 16383;
    const float* sp = g_simp + (size_t)b * NCH * CQK * CIN + cv;
    float s = 0.f;
#pragma unroll 8
    for (int ch = 0; ch < NCH; ch++)
        s += sp[(size_t)ch * CQK * CIN];
    g_sim[o] = s;
}

// ============ K4a: M2 = oWT^T-dot -> fp16 g_AM2h (coalesced oWT) ============
// grid 64 = Bn x 16 c-groups (4 c each), block 256
__global__ void k_m2()
{
    __shared__ float ssm[4][CIN];
    const int b = blockIdx.x >> 4;
    const int c0 = (blockIdx.x & 15) * 4;
    const int o = threadIdx.x;
    // load 4 c-rows of sim into smem (coalesced)
#pragma unroll
    for (int i = 0; i < 4; i++)
        ssm[i][o] = g_sim[((size_t)b * CQK + c0 + i) * CIN + o];
    __syncthreads();
    float s0 = 0.f, s1 = 0.f, s2 = 0.f, s3 = 0.f;
#pragma unroll 4
    for (int v = 0; v < CIN; v++) {
        float wv = g_oWT[v * CIN + o];
        s0 = fmaf(wv, ssm[0][v], s0);
        s1 = fmaf(wv, ssm[1][v], s1);
        s2 = fmaf(wv, ssm[2][v], s2);
        s3 = fmaf(wv, ssm[3][v], s3);
    }
    __half* hp = (__half*)g_AM2h;
    float sv[4] = {s0, s1, s2, s3};
#pragma unroll
    for (int i = 0; i < 4; i++) {
        int c = c0 + i;
        int kb = c >> 4, rem = c & 15;
        int hi = rem >> 3, kkv = (rem & 7) >> 1, low = rem & 1;
        hp[((((size_t)(b * 4 + kb) * 256 + o) * 4 + kkv) << 2) + hi * 2 + low] = __float2half(sv[i]);
    }
}

// ============ K4: ctx mma (fp16) -> fuse -> fp16 pairs g_fth ============
__global__ void __launch_bounds__(256, 2)
k_ctx_mma(const float* __restrict__ x, const float* __restrict__ up,
          const float* __restrict__ os, const float* __restrict__ ob)
{
    extern __shared__ uint2 dynsm[];
    uint2* Asm = dynsm;
    uint2* Bsm = dynsm + 2048;
    float* upH = (float*)(dynsm + 4160);

    const int b = blockIdx.z;
    const int co0 = blockIdx.y * 128;
    const int h = blockIdx.x;
    const int n0 = h * Ww;
    const int tid = threadIdx.x, lane = tid & 31, w = tid >> 5;
    const int g = lane >> 2, kk = lane & 3;
    const int mg = w >> 1, ng = w & 1;
    const int m0w = mg * 32, n0w = ng * 64;
    const uint32_t aBase = (uint32_t)__cvta_generic_to_shared(dynsm);

#pragma unroll
    for (int i = 0; i < 4; i++) {
        int j = i * 256 + tid;
        int kb = j >> 8, r = j & 255;
        int m = r >> 1, kp = r & 1;
        cpa16(aBase + (kb * 512 + m * 4 + kp * 2) * 8,
              g_AM2h + ((size_t)(b * 4 + kb) * 256 + co0 + m) * 4 + kp * 2);
    }
#pragma unroll
    for (int i = 0; i < 4; i++) {
        int j = i * 256 + tid;
        int row = j >> 6, npair = (j & 63) * 2;
        cpa16(aBase + (2048 + row * 132 + npair) * 8,
              g_qnth + (size_t)(b * 16 + row) * HW + n0 + npair);
    }
    cpa_commit();

    {
        float shf = 0.5f * h - 0.25f;
        int h0 = (int)floorf(shf);
        float wh1 = shf - (float)h0;
        int h0c = h0 < 0 ? 0 : h0;
        int h1c = (h0 + 1) > 63 ? 63 : (h0 + 1);
        const float* ub = up + ((size_t)(b * CIN + co0)) * 64 * 64;
#pragma unroll
        for (int i = 0; i < 32; i++) {
            int idx = i * 256 + tid;
            int r = idx >> 6, sw = idx & 63;
            upH[r * 64 + sw] = (1.f - wh1) * ub[(r * 64 + h0c) * 64 + sw]
                             + wh1 * ub[(r * 64 + h1c) * 64 + sw];
        }
    }
    cpa_wait0(); __syncthreads();

    float acc[2][8][4];
#pragma unroll
    for (int mt = 0; mt < 2; mt++)
#pragma unroll
        for (int nt = 0; nt < 8; nt++)
#pragma unroll
            for (int i = 0; i < 4; i++) acc[mt][nt][i] = 0.f;

#pragma unroll
    for (int kb = 0; kb < 4; kb++) {
        uint2 alo[2], ahi[2];
#pragma unroll
        for (int mt = 0; mt < 2; mt++) {
            alo[mt] = Asm[kb * 512 + (m0w + mt * 16 + g) * 4 + kk];
            ahi[mt] = Asm[kb * 512 + (m0w + mt * 16 + 8 + g) * 4 + kk];
        }
#pragma unroll
        for (int nt = 0; nt < 8; nt++) {
            uint2 bb = Bsm[(kb * 4 + kk) * 132 + n0w + nt * 8 + g];
            mma16(acc[0][nt], alo[0], ahi[0], bb);
            mma16(acc[1][nt], alo[1], ahi[1], bb);
        }
    }

    const float* xb = x + ((size_t)b * CIN + co0) * HW + n0;
#pragma unroll
    for (int mt = 0; mt < 2; mt++) {
        int m = m0w + mt * 16 + g;
        int co = co0 + m;
        float sc0 = os[co], sh0 = ob[co];
        float sc1 = os[co + 8], sh1 = ob[co + 8];
        int ch16 = co >> 4;
        int jidx = g >> 1;
#pragma unroll
        for (int nt = 0; nt < 8; nt++) {
            int c0 = n0w + nt * 8 + (lane & 3) * 2;
            int c1 = c0 + 1;
            float sw0 = 0.5f * c0 - 0.25f, sw1 = 0.5f * c1 - 0.25f;
            int wa0 = (int)floorf(sw0), wa1 = (int)floorf(sw1);
            float t0 = sw0 - (float)wa0, t1 = sw1 - (float)wa1;
            int w00 = wa0 < 0 ? 0 : wa0, w01 = (wa0 + 1) > 63 ? 63 : (wa0 + 1);
            int w10 = wa1 < 0 ? 0 : wa1, w11 = (wa1 + 1) > 63 ? 63 : (wa1 + 1);

            float u0a = (1.f - t0) * upH[m * 64 + w00] + t0 * upH[m * 64 + w01];
            float u1a = (1.f - t1) * upH[m * 64 + w10] + t1 * upH[m * 64 + w11];
            float u0b = (1.f - t0) * upH[(m + 8) * 64 + w00] + t0 * upH[(m + 8) * 64 + w01];
            float u1b = (1.f - t1) * upH[(m + 8) * 64 + w10] + t1 * upH[(m + 8) * 64 + w11];

            float f0 = fmaxf(fmaf(acc[mt][nt][0], sc0, sh0), 0.f) + xb[(size_t)m * HW + c0] + u0a;
            float f1 = fmaxf(fmaf(acc[mt][nt][1], sc0, sh0), 0.f) + xb[(size_t)m * HW + c1] + u1a;
            float f2 = fmaxf(fmaf(acc[mt][nt][2], sc1, sh1), 0.f) + xb[(size_t)(m + 8) * HW + c0] + u0b;
            float f3 = fmaxf(fmaf(acc[mt][nt][3], sc1, sh1), 0.f) + xb[(size_t)(m + 8) * HW + c1] + u1b;

            float p0 = __shfl_xor_sync(0xffffffffu, f0, 4);
            float p1 = __shfl_xor_sync(0xffffffffu, f1, 4);
            float p2 = __shfl_xor_sync(0xffffffffu, f2, 4);
            float p3 = __shfl_xor_sync(0xffffffffu, f3, 4);
            if ((g & 1) == 0) {
                size_t base = (((size_t)(b * 16 + ch16) * 4 + jidx) * 130 + h + 1) * 132 + 1;
                g_fth[base + c0] = make_uint2(pkh2(f0, p0), pkh2(f2, p2));
                g_fth[base + c1] = make_uint2(pkh2(f1, p1), pkh2(f3, p3));
            }
        }
    }
}

// ============ K5: 3x3 conv, fp16, 4 rows x 64 co x 128 w ============
__global__ void __launch_bounds__(512, 1)
k_conv_h(const float* __restrict__ ss, const float* __restrict__ sb,
         float* __restrict__ out)
{
    extern __shared__ uint2 csm[];
    uint2* Ism = csm;
    uint2* Wsm = csm + 6336;

    const int h0 = blockIdx.x * 4;
    const int co0 = blockIdx.y * 64;
    const int b = blockIdx.z;
    const int tid = threadIdx.x, lane = tid & 31, w = tid >> 5;
    const int g = lane >> 2, kk = lane & 3;
    const int mg = w >> 3, ng = w & 7;
    const int m0w = mg * 32, n0w = ng * 64;
    const uint32_t smBase = (uint32_t)__cvta_generic_to_shared(csm);

    float acc[2][8][4];
#pragma unroll
    for (int mt = 0; mt < 2; mt++)
#pragma unroll
        for (int nt = 0; nt < 8; nt++)
#pragma unroll
            for (int i = 0; i < 4; i++) acc[mt][nt][i] = 0.f;

    const uint2* ftb = g_fth + (size_t)b * 16 * 4 * 130 * 132;

    auto fill = [&](int ch, int stage) {
        for (int j = tid; j < 1560; j += 512) {
            int rowplane = j / 65;
            int colpair = (j - rowplane * 65) * 2;
            int row = rowplane >> 2, jj = rowplane & 3;
            cpa16(smBase + (stage * 3168 + (row * 4 + jj) * 132 + colpair) * 8,
                  ftb + ((size_t)(ch * 4 + jj) * 130 + h0 + row) * 132 + colpair);
        }
        for (int j = tid; j < 1152; j += 512) {
            int u = j * 2;
            int grp = u >> 8, off = u & 255;
            int dh = grp / 3, tap = grp - dh * 3;
            cpa16(smBase + (6336 + stage * 2304 + grp * 256 + off) * 8,
                  g_wph + (size_t)((dh * 16 + ch) * 3 + tap) * 512 + co0 * 4 + off);
        }
    };

    fill(0, 0); cpa_commit(); cpa_wait0(); __syncthreads();

    for (int it = 0; it < 16; it++) {
        int cur = it & 1, nxt = cur ^ 1;
        if (it < 15) { fill(it + 1, nxt); cpa_commit(); }

        const uint2* Ic = Ism + cur * 3168;
        const uint2* Wc = Wsm + cur * 2304;
#pragma unroll
        for (int dh = 0; dh < 3; dh++) {
#pragma unroll
            for (int tap = 0; tap < 3; tap++) {
                const uint2* wb = Wc + (dh * 3 + tap) * 256;
                uint2 alo[2], ahi[2];
#pragma unroll
                for (int mt = 0; mt < 2; mt++) {
                    alo[mt] = wb[(m0w + mt * 16 + g) * 4 + kk];
                    ahi[mt] = wb[(m0w + mt * 16 + 8 + g) * 4 + kk];
                }
#pragma unroll
                for (int nt = 0; nt < 8; nt++) {
                    int n = n0w + nt * 8 + g;
                    int rrow = n >> 7, wx = n & 127;
                    uint2 bb = Ic[((rrow + dh) * 4 + kk) * 132 + wx + tap];
                    mma16(acc[0][nt], alo[0], ahi[0], bb);
                    mma16(acc[1][nt], alo[1], ahi[1], bb);
                }
            }
        }
        cpa_wait0(); __syncthreads();
    }

#pragma unroll
    for (int mt = 0; mt < 2; mt++) {
        int co = co0 + m0w + mt * 16 + g;
        float sc0 = ss[co], sh0 = sb[co];
        float sc1 = ss[co + 8], sh1 = sb[co + 8];
#pragma unroll
        for (int nt = 0; nt < 8; nt++) {
            int n = n0w + nt * 8 + (lane & 3) * 2;
            int r = n >> 7, wx = n & 127;
            float* o0p = out + (((size_t)b * CS + co) * Hh + h0 + r) * Ww + wx;
            float* o1p = out + (((size_t)b * CS + co + 8) * Hh + h0 + r) * Ww + wx;
            float2 o0 = make_float2(fmaxf(fmaf(acc[mt][nt][0], sc0, sh0), 0.f),
                                    fmaxf(fmaf(acc[mt][nt][1], sc0, sh0), 0.f));
            float2 o1 = make_float2(fmaxf(fmaf(acc[mt][nt][2], sc1, sh1), 0.f),
                                    fmaxf(fmaf(acc[mt][nt][3], sc1, sh1), 0.f));
            *(float2*)o0p = o0;
            *(float2*)o1p = o1;
        }
    }
}

// ============================================================
extern "C" void kernel_launch(void* const* d_in, const int* in_sizes, int n_in,
                              void* d_out, int out_size)
{
    (void)in_sizes; (void)n_in; (void)out_size;
    const float* x        = (const float*)d_in[0];
    const float* up       = (const float*)d_in[1];
    const float* qW       = (const float*)d_in[2];
    const float* q_scale  = (const float*)d_in[3];
    const float* q_shift  = (const float*)d_in[4];
    const float* kW       = (const float*)d_in[5];
    const float* k_scale  = (const float*)d_in[6];
    const float* k_shift  = (const float*)d_in[7];
    const float* vW       = (const float*)d_in[8];
    const float* v_scale  = (const float*)d_in[9];
    const float* v_shift  = (const float*)d_in[10];
    const float* oW       = (const float*)d_in[11];
    const float* o_scale  = (const float*)d_in[12];
    const float* o_shift  = (const float*)d_in[13];
    const float* sW       = (const float*)d_in[14];
    const float* s_scale  = (const float*)d_in[15];
    const float* s_shift  = (const float*)d_in[16];
    float* out = (float*)d_out;

    cudaFuncSetAttribute(k_qkv,     cudaFuncAttributeMaxDynamicSharedMemorySize, 36352);
    cudaFuncSetAttribute(k_sim_mma, cudaFuncAttributeMaxDynamicSharedMemorySize, 41472);
    cudaFuncSetAttribute(k_ctx_mma, cudaFuncAttributeMaxDynamicSharedMemorySize, 66048);
    cudaFuncSetAttribute(k_conv_h,  cudaFuncAttributeMaxDynamicSharedMemorySize, 87552);

    k_pack_all<<<4736, 256>>>(x, sW, vW, qW, kW, oW);
    k_qkv<<<1536, 256, 36352>>>(q_scale, q_shift, k_scale, k_shift, v_scale, v_shift);
    k_sim_mma<<<dim3(NCH, Bn), 256, 41472>>>();
    k_simred<<<256, 256>>>();
    k_m2<<<64, 256>>>();
    k_ctx_mma<<<dim3(Hh, 2, Bn), 256, 66048>>>(x, up, o_scale, o_shift);
    k_conv_h<<<dim3(Hh / 4, 2, Bn), 512, 87552>>>(s_scale, s_shift, out);
}

// round 14
// speedup vs baseline: 1.8060x; 1.0024x over previous
#include <cuda_runtime.h>
#include <cuda_fp16.h>
#include <math.h>
#include <stdint.h>

#define Bn   4
#define CIN  256
#define CQK  64
#define CS   128
#define Hh   128
#define Ww   128
#define HW   (Hh*Ww)
#define NCH  32
#define PIX_PER_CHUNK (HW/NCH)

__device__ float g_simp[Bn*NCH*CQK*CIN];
__device__ float g_oWT [CIN*CIN];

__device__ __align__(16) uint2 g_Aqk[8192];
__device__ __align__(16) uint2 g_Av [16384];
__device__ __align__(16) uint2 g_xt [Bn*8*8*HW];
__device__ __align__(16) uint2 g_knt[Bn*64*1024*4];
__device__ __align__(16) uint2 g_vt [Bn*1024*4*256];
__device__ __align__(16) uint2 g_AM2h[Bn*4096];
__device__ __align__(16) uint2 g_qnth[Bn*16*HW];
__device__ __align__(16) uint2 g_wph[73728];
__device__ __align__(16) uint2 g_fth[Bn*16*4*130*132];
__device__ __align__(16) unsigned g_xrh[Bn*16*8*HW];   // x residual fp16 pairs (co, co+8)

__device__ __forceinline__ uint32_t pkh2(float lo, float hi) {
    uint32_t r; asm("cvt.rn.f16x2.f32 %0, %1, %2;" : "=r"(r) : "f"(hi), "f"(lo)); return r;
}
__device__ __forceinline__ void mma16(float* c, uint2 alo, uint2 ahi, uint2 b) {
    asm volatile(
        "mma.sync.aligned.m16n8k16.row.col.f32.f16.f16.f32 "
        "{%0,%1,%2,%3}, {%4,%5,%6,%7}, {%8,%9}, {%0,%1,%2,%3};"
        : "+f"(c[0]), "+f"(c[1]), "+f"(c[2]), "+f"(c[3])
        : "r"(alo.x), "r"(ahi.x), "r"(alo.y), "r"(ahi.y), "r"(b.x), "r"(b.y));
}
__device__ __forceinline__ void cpa16(uint32_t saddr, const void* g) {
    asm volatile("cp.async.cg.shared.global [%0], [%1], 16;" :: "r"(saddr), "l"(g));
}
__device__ __forceinline__ void cpa_commit() { asm volatile("cp.async.commit_group;"); }
__device__ __forceinline__ void cpa_wait0()  { asm volatile("cp.async.wait_group 0;" ::: "memory"); }

// ============ merged pack kernel ============
// blocks: [0,4096) packx(+xrh) | [4096,4384) conv | [4384,4448) v | [4448,4480) qk | [4480,4736) oWT
__global__ void k_pack_all(const float* __restrict__ x,  const float* __restrict__ sW,
                           const float* __restrict__ vW, const float* __restrict__ qW,
                           const float* __restrict__ kW, const float* __restrict__ oW)
{
    int bx = blockIdx.x;
    if (bx < 4096) {
        int idx = bx * 256 + threadIdx.x;
        int n4 = (idx & 4095) * 4;
        int kkb = (idx >> 12) & 7;
        int it = (idx >> 15) & 7;
        int b = idx >> 18;
        int kb = kkb >> 2, kk = kkb & 3;
        int K0 = it * 32 + kb * 16 + kk * 2;
        const float* xb = x + ((size_t)b * CIN + K0) * HW + n4;
        float4 r0 = *(const float4*)xb;
        float4 r1 = *(const float4*)(xb + HW);
        float4 r8 = *(const float4*)(xb + 8 * HW);
        float4 r9 = *(const float4*)(xb + 9 * HW);
        uint2* dst = g_xt + ((size_t)((b * 8 + it) * 8 + kkb)) * HW + n4;
        *(uint4*)dst = make_uint4(pkh2(r0.x, r1.x), pkh2(r8.x, r9.x),
                                  pkh2(r0.y, r1.y), pkh2(r8.y, r9.y));
        *(uint4*)(dst + 2) = make_uint4(pkh2(r0.z, r1.z), pkh2(r8.z, r9.z),
                                        pkh2(r0.w, r1.w), pkh2(r8.w, r9.w));
        // residual pairs (co, co+8): ch = K0>>4, sub = kk*2 and kk*2+1
        int ch = it * 2 + kb;
        unsigned* xd = g_xrh + ((size_t)((b * 16 + ch) * 8 + kk * 2)) * HW + n4;
        *(uint4*)xd = make_uint4(pkh2(r0.x, r8.x), pkh2(r0.y, r8.y),
                                 pkh2(r0.z, r8.z), pkh2(r0.w, r8.w));
        *(uint4*)(xd + HW) = make_uint4(pkh2(r1.x, r9.x), pkh2(r1.y, r9.y),
                                        pkh2(r1.z, r9.z), pkh2(r1.w, r9.w));
    } else if (bx < 4384) {
        int idx = (bx - 4096) * 256 + threadIdx.x;
        int r = idx & 511, s = idx >> 9;
        int j = r & 3, co = r >> 2;
        int tap = s % 3, t2 = s / 3, ch = t2 & 15, dh = t2 >> 4;
        int ci = ch * 16 + j * 2;
        const float* wp = sW + ((size_t)co * CIN + ci) * 9 + dh * 3 + tap;
        g_wph[idx] = make_uint2(pkh2(wp[0], wp[9]), pkh2(wp[8 * 9], wp[9 * 9]));
    } else if (bx < 4448) {
        int idx = (bx - 4384) * 256 + threadIdx.x;
        int kk = idx & 3, m = (idx >> 2) & 255, kb16 = idx >> 10;
        int K0 = kb16 * 16 + kk * 2;
        const float* wr = vW + (size_t)m * CIN;
        g_Av[idx] = make_uint2(pkh2(wr[K0], wr[K0 + 1]), pkh2(wr[K0 + 8], wr[K0 + 9]));
    } else if (bx < 4480) {
        int idx = (bx - 4448) * 256 + threadIdx.x;
        int kk = idx & 3, m = (idx >> 2) & 127, kb = (idx >> 9) & 1, it = idx >> 10;
        int K0 = it * 32 + kb * 16 + kk * 2;
        const float* wr = (m < 64) ? (qW + (size_t)m * CIN) : (kW + (size_t)(m - 64) * CIN);
        g_Aqk[idx] = make_uint2(pkh2(wr[K0], wr[K0 + 1]), pkh2(wr[K0 + 8], wr[K0 + 9]));
    } else {
        int idx = (bx - 4480) * 256 + threadIdx.x;
        int o = idx & 255, v = idx >> 8;
        g_oWT[v * CIN + o] = oW[o * CIN + v];
    }
}

// ============ qk body ============
__device__ __forceinline__ void qk_body(
    int b, int n0, uint2* dynsm,
    const float* __restrict__ qs, const float* __restrict__ qb,
    const float* __restrict__ kscale, const float* __restrict__ kshift)
{
    uint2* Asm = dynsm;
    uint2* Bsm = dynsm + 2048;
    float* Sq  = (float*)(dynsm + 4160);
    float* Nn  = Sq + 512;

    const int tid = threadIdx.x, lane = tid & 31, w = tid >> 5;
    const int g = lane >> 2, kk = lane & 3;
    const int mg = w >> 1, ng = w & 1;
    const int m0w = mg * 32, n0w = ng * 64;
    const uint32_t aBase = (uint32_t)__cvta_generic_to_shared(dynsm);
    const uint2* xtb = g_xt + (size_t)b * 8 * 8 * HW + n0;

    float acc[2][8][4];
#pragma unroll
    for (int mt = 0; mt < 2; mt++)
#pragma unroll
        for (int nt = 0; nt < 8; nt++)
#pragma unroll
            for (int i = 0; i < 4; i++) acc[mt][nt][i] = 0.f;

    auto fill = [&](int it, int stage) {
#pragma unroll
        for (int i = 0; i < 2; i++) {
            int j = i * 256 + tid;
            cpa16(aBase + (stage * 1024 + j * 2) * 8, g_Aqk + it * 1024 + j * 2);
        }
#pragma unroll
        for (int i = 0; i < 2; i++) {
            int j = i * 256 + tid;
            int kkb = j >> 6, npair = (j & 63) * 2;
            cpa16(aBase + (2048 + stage * 1056 + kkb * 132 + npair) * 8,
                  xtb + (size_t)((it * 8) + kkb) * HW + npair);
        }
    };

    fill(0, 0); cpa_commit(); cpa_wait0(); __syncthreads();

    for (int it = 0; it < 8; it++) {
        int cur = it & 1, nxt = cur ^ 1;
        if (it < 7) { fill(it + 1, nxt); cpa_commit(); }
        const uint2* Ac = Asm + cur * 1024;
        const uint2* Bc = Bsm + cur * 1056;
#pragma unroll
        for (int kb = 0; kb < 2; kb++) {
            uint2 alo[2], ahi[2];
#pragma unroll
            for (int mt = 0; mt < 2; mt++) {
                alo[mt] = Ac[(kb * 128 + m0w + mt * 16 + g) * 4 + kk];
                ahi[mt] = Ac[(kb * 128 + m0w + mt * 16 + 8 + g) * 4 + kk];
            }
#pragma unroll
            for (int nt = 0; nt < 8; nt++) {
                uint2 bb = Bc[(kb * 4 + kk) * 132 + n0w + nt * 8 + g];
                mma16(acc[0][nt], alo[0], ahi[0], bb);
                mma16(acc[1][nt], alo[1], ahi[1], bb);
            }
        }
        cpa_wait0(); __syncthreads();
    }

    float sq[8][2];
#pragma unroll
    for (int nt = 0; nt < 8; nt++) { sq[nt][0] = 0.f; sq[nt][1] = 0.f; }
#pragma unroll
    for (int mt = 0; mt < 2; mt++) {
        int r0 = m0w + mt * 16 + g, r1 = r0 + 8;
        bool isq = (r0 < 64);
        float sc0 = isq ? qs[r0] : kscale[r0 - 64];
        float sh0 = isq ? qb[r0] : kshift[r0 - 64];
        float sc1 = isq ? qs[r1] : kscale[r1 - 64];
        float sh1 = isq ? qb[r1] : kshift[r1 - 64];
#pragma unroll
        for (int nt = 0; nt < 8; nt++) {
            float v0 = fmaf(acc[mt][nt][0], sc0, sh0);
            float v1 = fmaf(acc[mt][nt][1], sc0, sh0);
            float v2 = fmaf(acc[mt][nt][2], sc1, sh1);
            float v3 = fmaf(acc[mt][nt][3], sc1, sh1);
            acc[mt][nt][0] = v0; acc[mt][nt][1] = v1;
            acc[mt][nt][2] = v2; acc[mt][nt][3] = v3;
            sq[nt][0] += v0 * v0 + v2 * v2;
            sq[nt][1] += v1 * v1 + v3 * v3;
        }
    }
#pragma unroll
    for (int nt = 0; nt < 8; nt++) {
#pragma unroll
        for (int o = 4; o < 32; o <<= 1) {
            sq[nt][0] += __shfl_xor_sync(0xffffffffu, sq[nt][0], o);
            sq[nt][1] += __shfl_xor_sync(0xffffffffu, sq[nt][1], o);
        }
    }
    if (lane < 4) {
#pragma unroll
        for (int nt = 0; nt < 8; nt++) {
            int c = n0w + nt * 8 + lane * 2;
            Sq[mg * 128 + c] = sq[nt][0];
            Sq[mg * 128 + c + 1] = sq[nt][1];
        }
    }
    __syncthreads();
    {
        int col = tid & 127, half = tid >> 7;
        float s = Sq[half * 256 + col] + Sq[half * 256 + 128 + col];
        Nn[half * 128 + col] = 1.f / fmaxf(sqrtf(s), 1e-12f);
    }
    __syncthreads();

    if (mg < 2) {
#pragma unroll
        for (int mt = 0; mt < 2; mt++) {
            int r0 = m0w + mt * 16 + g;
            int row = (r0 >> 4) * 4 + (g >> 1);
#pragma unroll
            for (int nt = 0; nt < 8; nt++) {
                int c = n0w + nt * 8 + (lane & 3) * 2;
                float i0 = Nn[c], i1 = Nn[c + 1];
                float v0 = acc[mt][nt][0] * i0, v1 = acc[mt][nt][1] * i1;
                float v2 = acc[mt][nt][2] * i0, v3 = acc[mt][nt][3] * i1;
                float p0 = __shfl_xor_sync(0xffffffffu, v0, 4);
                float p1 = __shfl_xor_sync(0xffffffffu, v1, 4);
                float p2 = __shfl_xor_sync(0xffffffffu, v2, 4);
                float p3 = __shfl_xor_sync(0xffffffffu, v3, 4);
                if ((g & 1) == 0) {
                    uint2* dst = g_qnth + (size_t)(b * 16 + row) * HW + n0 + c;
                    dst[0] = make_uint2(pkh2(v0, p0), pkh2(v2, p2));
                    dst[1] = make_uint2(pkh2(v1, p1), pkh2(v3, p3));
                }
            }
        }
    } else {
#pragma unroll
        for (int mt = 0; mt < 2; mt++) {
            int r0 = m0w + mt * 16 + g - 64;
#pragma unroll
            for (int nt = 0; nt < 8; nt += 2) {
                int c0 = n0w + nt * 8 + (lane & 3) * 2;
                int kbpix = (n0 + c0) >> 4, kkp = lane & 3;
                float i0 = Nn[128 + c0], i1 = Nn[128 + c0 + 1];
                float i8 = Nn[128 + c0 + 8], i9 = Nn[128 + c0 + 9];
                float a0 = acc[mt][nt][0] * i0,     a1 = acc[mt][nt][1] * i1;
                float b0 = acc[mt][nt + 1][0] * i8, b1 = acc[mt][nt + 1][1] * i9;
                float a2 = acc[mt][nt][2] * i0,     a3 = acc[mt][nt][3] * i1;
                float b2 = acc[mt][nt + 1][2] * i8, b3 = acc[mt][nt + 1][3] * i9;
                g_knt[((size_t)(b * 64 + r0) * 1024 + kbpix) * 4 + kkp] =
                    make_uint2(pkh2(a0, a1), pkh2(b0, b1));
                g_knt[((size_t)(b * 64 + r0 + 8) * 1024 + kbpix) * 4 + kkp] =
                    make_uint2(pkh2(a2, a3), pkh2(b2, b3));
            }
        }
    }
}

// ============ v body ============
__device__ __forceinline__ void v_body(
    int b, int co0, int n0, uint2* dynsm,
    const float* __restrict__ vs, const float* __restrict__ vb)
{
    uint2* Asm = dynsm;
    uint2* Bsm = dynsm + 2048;

    const int tid = threadIdx.x, lane = tid & 31, w = tid >> 5;
    const int g = lane >> 2, kk = lane & 3;
    const int mg = w >> 1, ng = w & 1;
    const int m0w = mg * 32, n0w = ng * 64;
    const uint32_t aBase = (uint32_t)__cvta_generic_to_shared(dynsm);
    const uint2* xtb = g_xt + (size_t)b * 8 * 8 * HW + n0;

    float acc[2][8][4];
#pragma unroll
    for (int mt = 0; mt < 2; mt++)
#pragma unroll
        for (int nt = 0; nt < 8; nt++)
#pragma unroll
            for (int i = 0; i < 4; i++) acc[mt][nt][i] = 0.f;

    auto fill = [&](int it, int stage) {
#pragma unroll
        for (int i = 0; i < 2; i++) {
            int j = i * 256 + tid;
            int kb = j >> 8, r = (j & 255) * 2;
            cpa16(aBase + (stage * 1024 + kb * 512 + r) * 8,
                  g_Av + (size_t)(it * 2 + kb) * 1024 + co0 * 4 + r);
        }
#pragma unroll
        for (int i = 0; i < 2; i++) {
            int j = i * 256 + tid;
            int kkb = j >> 6, npair = (j & 63) * 2;
            cpa16(aBase + (2048 + stage * 1056 + kkb * 132 + npair) * 8,
                  xtb + (size_t)((it * 8) + kkb) * HW + npair);
        }
    };

    fill(0, 0); cpa_commit(); cpa_wait0(); __syncthreads();

    for (int it = 0; it < 8; it++) {
        int cur = it & 1, nxt = cur ^ 1;
        if (it < 7) { fill(it + 1, nxt); cpa_commit(); }
        const uint2* Ac = Asm + cur * 1024;
        const uint2* Bc = Bsm + cur * 1056;
#pragma unroll
        for (int kb = 0; kb < 2; kb++) {
            uint2 alo[2], ahi[2];
#pragma unroll
            for (int mt = 0; mt < 2; mt++) {
                alo[mt] = Ac[(kb * 128 + m0w + mt * 16 + g) * 4 + kk];
                ahi[mt] = Ac[(kb * 128 + m0w + mt * 16 + 8 + g) * 4 + kk];
            }
#pragma unroll
            for (int nt = 0; nt < 8; nt++) {
                uint2 bb = Bc[(kb * 4 + kk) * 132 + n0w + nt * 8 + g];
                mma16(acc[0][nt], alo[0], ahi[0], bb);
                mma16(acc[1][nt], alo[1], ahi[1], bb);
            }
        }
        cpa_wait0(); __syncthreads();
    }

#pragma unroll
    for (int mt = 0; mt < 2; mt++) {
        int co = co0 + m0w + mt * 16 + g;
        float sc0 = vs[co], sh0 = vb[co];
        float sc1 = vs[co + 8], sh1 = vb[co + 8];
#pragma unroll
        for (int nt = 0; nt < 8; nt += 2) {
            int c0 = n0w + nt * 8 + (lane & 3) * 2;
            int kbpix = (n0 + c0) >> 4, kkp = lane & 3;
            float a0 = fmaxf(fmaf(acc[mt][nt][0], sc0, sh0), 0.f);
            float a1 = fmaxf(fmaf(acc[mt][nt][1], sc0, sh0), 0.f);
            float b0 = fmaxf(fmaf(acc[mt][nt + 1][0], sc0, sh0), 0.f);
            float b1 = fmaxf(fmaf(acc[mt][nt + 1][1], sc0, sh0), 0.f);
            float a2 = fmaxf(fmaf(acc[mt][nt][2], sc1, sh1), 0.f);
            float a3 = fmaxf(fmaf(acc[mt][nt][3], sc1, sh1), 0.f);
            float b2 = fmaxf(fmaf(acc[mt][nt + 1][2], sc1, sh1), 0.f);
            float b3 = fmaxf(fmaf(acc[mt][nt + 1][3], sc1, sh1), 0.f);
            g_vt[(((size_t)b * 1024 + kbpix) * 4 + kkp) * 256 + co] =
                make_uint2(pkh2(a0, a1), pkh2(b0, b1));
            g_vt[(((size_t)b * 1024 + kbpix) * 4 + kkp) * 256 + co + 8] =
                make_uint2(pkh2(a2, a3), pkh2(b2, b3));
        }
    }
}

// ============ merged K1+K2 ============
__global__ void __launch_bounds__(256, 2)
k_qkv(const float* __restrict__ qs, const float* __restrict__ qb,
      const float* __restrict__ kscale, const float* __restrict__ kshift,
      const float* __restrict__ vs, const float* __restrict__ vb)
{
    extern __shared__ uint2 dynsm[];
    int bx = blockIdx.x;
    if (bx < 512) {
        qk_body(bx >> 7, (bx & 127) * 128, dynsm, qs, qb, kscale, kshift);
    } else {
        int t = bx - 512;
        v_body(t >> 8, ((t >> 7) & 1) * 128, (t & 127) * 128, dynsm, vs, vb);
    }
}

// ============ K3: partial sim (NCH=32, 16 k-iterations) ============
__global__ void __launch_bounds__(256, 2) k_sim_mma()
{
    extern __shared__ uint2 dynsm[];
    const int b = blockIdx.y, ch = blockIdx.x;
    const int kbp0 = (ch * PIX_PER_CHUNK) >> 4;
    const int tid = threadIdx.x, lane = tid & 31, w = tid >> 5;
    const int g = lane >> 2, kk = lane & 3;
    const int mg = w >> 2, ng = w & 3;
    const int m0w = mg * 32, n0w = ng * 64;
    const uint32_t smBase = (uint32_t)__cvta_generic_to_shared(dynsm);

    float acc[2][8][4];
#pragma unroll
    for (int mt = 0; mt < 2; mt++)
#pragma unroll
        for (int nt = 0; nt < 8; nt++)
#pragma unroll
            for (int i = 0; i < 4; i++) acc[mt][nt][i] = 0.f;

    auto fill = [&](int it, int stage) {
        int kbpix = kbp0 + it * 2;
        {
            int j = tid;
            int m = j >> 2, kb = (j >> 1) & 1, kp = j & 1;
            cpa16(smBase + (stage * 512 + (kb * 64 + m) * 4 + kp * 2) * 8,
                  g_knt + ((size_t)(b * 64 + m) * 1024 + kbpix + kb) * 4 + kp * 2);
        }
#pragma unroll
        for (int i = 0; i < 4; i++) {
            int j = i * 256 + tid;
            int row = j >> 7, npair = (j & 127) * 2;
            int kb = row >> 2, kkr = row & 3;
            cpa16(smBase + (1024 + stage * 2080 + row * 260 + npair) * 8,
                  g_vt + (((size_t)b * 1024 + kbpix + kb) * 4 + kkr) * 256 + npair);
        }
    };

    fill(0, 0); cpa_commit(); cpa_wait0(); __syncthreads();

    for (int it = 0; it < 16; it++) {
        int cur = it & 1, nxt = cur ^ 1;
        if (it < 15) { fill(it + 1, nxt); cpa_commit(); }
        const uint2* Ac = dynsm + cur * 512;
        const uint2* Bc = dynsm + 1024 + cur * 2080;
#pragma unroll
        for (int kb = 0; kb < 2; kb++) {
            uint2 alo[2], ahi[2];
#pragma unroll
            for (int mt = 0; mt < 2; mt++) {
                alo[mt] = Ac[(kb * 64 + m0w + mt * 16 + g) * 4 + kk];
                ahi[mt] = Ac[(kb * 64 + m0w + mt * 16 + 8 + g) * 4 + kk];
            }
#pragma unroll
            for (int nt = 0; nt < 8; nt++) {
                uint2 bb = Bc[(kb * 4 + kk) * 260 + n0w + nt * 8 + g];
                mma16(acc[0][nt], alo[0], ahi[0], bb);
                mma16(acc[1][nt], alo[1], ahi[1], bb);
            }
        }
        cpa_wait0(); __syncthreads();
    }

    float* outp = g_simp + (size_t)(b * NCH + ch) * CQK * CIN;
#pragma unroll
    for (int mt = 0; mt < 2; mt++) {
        int r = m0w + mt * 16 + g;
#pragma unroll
        for (int nt = 0; nt < 8; nt++) {
            int c = n0w + nt * 8 + (lane & 3) * 2;
            *(float2*)&outp[(size_t)r * CIN + c] = make_float2(acc[mt][nt][0], acc[mt][nt][1]);
            *(float2*)&outp[(size_t)(r + 8) * CIN + c] = make_float2(acc[mt][nt][2], acc[mt][nt][3]);
        }
    }
}

// ============ K4a: fused reduce + M2 -> fp16 g_AM2h (coalesced oWT) ============
__global__ void k_m2()
{
    __shared__ float ssm[4][CIN];
    const int b = blockIdx.x >> 4;
    const int c0 = (blockIdx.x & 15) * 4;
    const int o = threadIdx.x;
#pragma unroll
    for (int i = 0; i < 4; i++) {
        const float* sp = g_simp + ((size_t)b * NCH * CQK + c0 + i) * CIN + o;
        float s = 0.f;
#pragma unroll 8
        for (int ch = 0; ch < NCH; ch++)
            s += sp[(size_t)ch * CQK * CIN];
        ssm[i][o] = s;
    }
    __syncthreads();
    float s0 = 0.f, s1 = 0.f, s2 = 0.f, s3 = 0.f;
#pragma unroll 4
    for (int v = 0; v < CIN; v++) {
        float wv = g_oWT[v * CIN + o];
        s0 = fmaf(wv, ssm[0][v], s0);
        s1 = fmaf(wv, ssm[1][v], s1);
        s2 = fmaf(wv, ssm[2][v], s2);
        s3 = fmaf(wv, ssm[3][v], s3);
    }
    __half* hp = (__half*)g_AM2h;
    float sv[4] = {s0, s1, s2, s3};
#pragma unroll
    for (int i = 0; i < 4; i++) {
        int c = c0 + i;
        int kb = c >> 4, rem = c & 15;
        int hi = rem >> 3, kkv = (rem & 7) >> 1, low = rem & 1;
        hp[((((size_t)(b * 4 + kb) * 256 + o) * 4 + kkv) << 2) + hi * 2 + low] = __float2half(sv[i]);
    }
}

// ============ K4: ctx mma (fp16) -> fuse -> fp16 pairs g_fth ============
__global__ void __launch_bounds__(256, 2)
k_ctx_mma(const float* __restrict__ up,
          const float* __restrict__ os, const float* __restrict__ ob)
{
    extern __shared__ uint2 dynsm[];
    uint2* Asm = dynsm;
    uint2* Bsm = dynsm + 2048;
    float* upH = (float*)(dynsm + 4160);

    const int b = blockIdx.z;
    const int co0 = blockIdx.y * 128;
    const int h = blockIdx.x;
    const int n0 = h * Ww;
    const int tid = threadIdx.x, lane = tid & 31, w = tid >> 5;
    const int g = lane >> 2, kk = lane & 3;
    const int mg = w >> 1, ng = w & 1;
    const int m0w = mg * 32, n0w = ng * 64;
    const uint32_t aBase = (uint32_t)__cvta_generic_to_shared(dynsm);

#pragma unroll
    for (int i = 0; i < 4; i++) {
        int j = i * 256 + tid;
        int kb = j >> 8, r = j & 255;
        int m = r >> 1, kp = r & 1;
        cpa16(aBase + (kb * 512 + m * 4 + kp * 2) * 8,
              g_AM2h + ((size_t)(b * 4 + kb) * 256 + co0 + m) * 4 + kp * 2);
    }
#pragma unroll
    for (int i = 0; i < 4; i++) {
        int j = i * 256 + tid;
        int row = j >> 6, npair = (j & 63) * 2;
        cpa16(aBase + (2048 + row * 132 + npair) * 8,
              g_qnth + (size_t)(b * 16 + row) * HW + n0 + npair);
    }
    cpa_commit();

    {
        float shf = 0.5f * h - 0.25f;
        int h0 = (int)floorf(shf);
        float wh1 = shf - (float)h0;
        int h0c = h0 < 0 ? 0 : h0;
        int h1c = (h0 + 1) > 63 ? 63 : (h0 + 1);
        const float* ub = up + ((size_t)(b * CIN + co0)) * 64 * 64;
#pragma unroll
        for (int i = 0; i < 32; i++) {
            int idx = i * 256 + tid;
            int r = idx >> 6, sw = idx & 63;
            upH[r * 64 + sw] = (1.f - wh1) * ub[(r * 64 + h0c) * 64 + sw]
                             + wh1 * ub[(r * 64 + h1c) * 64 + sw];
        }
    }
    cpa_wait0(); __syncthreads();

    float acc[2][8][4];
#pragma unroll
    for (int mt = 0; mt < 2; mt++)
#pragma unroll
        for (int nt = 0; nt < 8; nt++)
#pragma unroll
            for (int i = 0; i < 4; i++) acc[mt][nt][i] = 0.f;

#pragma unroll
    for (int kb = 0; kb < 4; kb++) {
        uint2 alo[2], ahi[2];
#pragma unroll
        for (int mt = 0; mt < 2; mt++) {
            alo[mt] = Asm[kb * 512 + (m0w + mt * 16 + g) * 4 + kk];
            ahi[mt] = Asm[kb * 512 + (m0w + mt * 16 + 8 + g) * 4 + kk];
        }
#pragma unroll
        for (int nt = 0; nt < 8; nt++) {
            uint2 bb = Bsm[(kb * 4 + kk) * 132 + n0w + nt * 8 + g];
            mma16(acc[0][nt], alo[0], ahi[0], bb);
            mma16(acc[1][nt], alo[1], ahi[1], bb);
        }
    }

#pragma unroll
    for (int mt = 0; mt < 2; mt++) {
        int m = m0w + mt * 16 + g;
        int co = co0 + m;
        float sc0 = os[co], sh0 = ob[co];
        float sc1 = os[co + 8], sh1 = ob[co + 8];
        int ch16 = co >> 4;
        int jidx = g >> 1;
        const unsigned* xrb = g_xrh + ((size_t)(b * 16 + ch16) * 8 + g) * HW + n0;
#pragma unroll
        for (int nt = 0; nt < 8; nt++) {
            int c0 = n0w + nt * 8 + (lane & 3) * 2;
            int c1 = c0 + 1;
            float sw0 = 0.5f * c0 - 0.25f, sw1 = 0.5f * c1 - 0.25f;
            int wa0 = (int)floorf(sw0), wa1 = (int)floorf(sw1);
            float t0 = sw0 - (float)wa0, t1 = sw1 - (float)wa1;
            int w00 = wa0 < 0 ? 0 : wa0, w01 = (wa0 + 1) > 63 ? 63 : (wa0 + 1);
            int w10 = wa1 < 0 ? 0 : wa1, w11 = (wa1 + 1) > 63 ? 63 : (wa1 + 1);

            float u0a = (1.f - t0) * upH[m * 64 + w00] + t0 * upH[m * 64 + w01];
            float u1a = (1.f - t1) * upH[m * 64 + w10] + t1 * upH[m * 64 + w11];
            float u0b = (1.f - t0) * upH[(m + 8) * 64 + w00] + t0 * upH[(m + 8) * 64 + w01];
            float u1b = (1.f - t1) * upH[(m + 8) * 64 + w10] + t1 * upH[(m + 8) * 64 + w11];

            uint2 xr2 = *(const uint2*)(xrb + c0);
            float2 xa = __half22float2(*(const __half2*)&xr2.x);   // (x[co][c0], x[co+8][c0])
            float2 xc = __half22float2(*(const __half2*)&xr2.y);   // (x[co][c1], x[co+8][c1])

            float f0 = fmaxf(fmaf(acc[mt][nt][0], sc0, sh0), 0.f) + xa.x + u0a;
            float f1 = fmaxf(fmaf(acc[mt][nt][1], sc0, sh0), 0.f) + xc.x + u1a;
            float f2 = fmaxf(fmaf(acc[mt][nt][2], sc1, sh1), 0.f) + xa.y + u0b;
            float f3 = fmaxf(fmaf(acc[mt][nt][3], sc1, sh1), 0.f) + xc.y + u1b;

            float p0 = __shfl_xor_sync(0xffffffffu, f0, 4);
            float p1 = __shfl_xor_sync(0xffffffffu, f1, 4);
            float p2 = __shfl_xor_sync(0xffffffffu, f2, 4);
            float p3 = __shfl_xor_sync(0xffffffffu, f3, 4);
            if ((g & 1) == 0) {
                size_t base = (((size_t)(b * 16 + ch16) * 4 + jidx) * 130 + h + 1) * 132 + 1;
                g_fth[base + c0] = make_uint2(pkh2(f0, p0), pkh2(f2, p2));
                g_fth[base + c1] = make_uint2(pkh2(f1, p1), pkh2(f3, p3));
            }
        }
    }
}

// ============ K5: 3x3 conv, fp16, 4 rows x 64 co x 128 w ============
__global__ void __launch_bounds__(512, 1)
k_conv_h(const float* __restrict__ ss, const float* __restrict__ sb,
         float* __restrict__ out)
{
    extern __shared__ uint2 csm[];
    uint2* Ism = csm;
    uint2* Wsm = csm + 6336;

    const int h0 = blockIdx.x * 4;
    const int co0 = blockIdx.y * 64;
    const int b = blockIdx.z;
    const int tid = threadIdx.x, lane = tid & 31, w = tid >> 5;
    const int g = lane >> 2, kk = lane & 3;
    const int mg = w >> 3, ng = w & 7;
    const int m0w = mg * 32, n0w = ng * 64;
    const uint32_t smBase = (uint32_t)__cvta_generic_to_shared(csm);

    float acc[2][8][4];
#pragma unroll
    for (int mt = 0; mt < 2; mt++)
#pragma unroll
        for (int nt = 0; nt < 8; nt++)
#pragma unroll
            for (int i = 0; i < 4; i++) acc[mt][nt][i] = 0.f;

    const uint2* ftb = g_fth + (size_t)b * 16 * 4 * 130 * 132;

    auto fill = [&](int ch, int stage) {
        for (int j = tid; j < 1560; j += 512) {
            int rowplane = j / 65;
            int colpair = (j - rowplane * 65) * 2;
            int row = rowplane >> 2, jj = rowplane & 3;
            cpa16(smBase + (stage * 3168 + (row * 4 + jj) * 132 + colpair) * 8,
                  ftb + ((size_t)(ch * 4 + jj) * 130 + h0 + row) * 132 + colpair);
        }
        for (int j = tid; j < 1152; j += 512) {
            int u = j * 2;
            int grp = u >> 8, off = u & 255;
            int dh = grp / 3, tap = grp - dh * 3;
            cpa16(smBase + (6336 + stage * 2304 + grp * 256 + off) * 8,
                  g_wph + (size_t)((dh * 16 + ch) * 3 + tap) * 512 + co0 * 4 + off);
        }
    };

    fill(0, 0); cpa_commit(); cpa_wait0(); __syncthreads();

    for (int it = 0; it < 16; it++) {
        int cur = it & 1, nxt = cur ^ 1;
        if (it < 15) { fill(it + 1, nxt); cpa_commit(); }

        const uint2* Ic = Ism + cur * 3168;
        const uint2* Wc = Wsm + cur * 2304;
#pragma unroll
        for (int dh = 0; dh < 3; dh++) {
#pragma unroll
            for (int tap = 0; tap < 3; tap++) {
                const uint2* wb = Wc + (dh * 3 + tap) * 256;
                uint2 alo[2], ahi[2];
#pragma unroll
                for (int mt = 0; mt < 2; mt++) {
                    alo[mt] = wb[(m0w + mt * 16 + g) * 4 + kk];
                    ahi[mt] = wb[(m0w + mt * 16 + 8 + g) * 4 + kk];
                }
#pragma unroll
                for (int nt = 0; nt < 8; nt++) {
                    int n = n0w + nt * 8 + g;
                    int rrow = n >> 7, wx = n & 127;
                    uint2 bb = Ic[((rrow + dh) * 4 + kk) * 132 + wx + tap];
                    mma16(acc[0][nt], alo[0], ahi[0], bb);
                    mma16(acc[1][nt], alo[1], ahi[1], bb);
                }
            }
        }
        cpa_wait0(); __syncthreads();
    }

#pragma unroll
    for (int mt = 0; mt < 2; mt++) {
        int co = co0 + m0w + mt * 16 + g;
        float sc0 = ss[co], sh0 = sb[co];
        float sc1 = ss[co + 8], sh1 = sb[co + 8];
#pragma unroll
        for (int nt = 0; nt < 8; nt++) {
            int n = n0w + nt * 8 + (lane & 3) * 2;
            int r = n >> 7, wx = n & 127;
            float* o0p = out + (((size_t)b * CS + co) * Hh + h0 + r) * Ww + wx;
            float* o1p = out + (((size_t)b * CS + co + 8) * Hh + h0 + r) * Ww + wx;
            float2 o0 = make_float2(fmaxf(fmaf(acc[mt][nt][0], sc0, sh0), 0.f),
                                    fmaxf(fmaf(acc[mt][nt][1], sc0, sh0), 0.f));
            float2 o1 = make_float2(fmaxf(fmaf(acc[mt][nt][2], sc1, sh1), 0.f),
                                    fmaxf(fmaf(acc[mt][nt][3], sc1, sh1), 0.f));
            *(float2*)o0p = o0;
            *(float2*)o1p = o1;
        }
    }
}

// ============================================================
extern "C" void kernel_launch(void* const* d_in, const int* in_sizes, int n_in,
                              void* d_out, int out_size)
{
    (void)in_sizes; (void)n_in; (void)out_size;
    const float* x        = (const float*)d_in[0];
    const float* up       = (const float*)d_in[1];
    const float* qW       = (const float*)d_in[2];
    const float* q_scale  = (const float*)d_in[3];
    const float* q_shift  = (const float*)d_in[4];
    const float* kW       = (const float*)d_in[5];
    const float* k_scale  = (const float*)d_in[6];
    const float* k_shift  = (const float*)d_in[7];
    const float* vW       = (const float*)d_in[8];
    const float* v_scale  = (const float*)d_in[9];
    const float* v_shift  = (const float*)d_in[10];
    const float* oW       = (const float*)d_in[11];
    const float* o_scale  = (const float*)d_in[12];
    const float* o_shift  = (const float*)d_in[13];
    const float* sW       = (const float*)d_in[14];
    const float* s_scale  = (const float*)d_in[15];
    const float* s_shift  = (const float*)d_in[16];
    float* out = (float*)d_out;

    cudaFuncSetAttribute(k_qkv,     cudaFuncAttributeMaxDynamicSharedMemorySize, 36352);
    cudaFuncSetAttribute(k_sim_mma, cudaFuncAttributeMaxDynamicSharedMemorySize, 41472);
    cudaFuncSetAttribute(k_ctx_mma, cudaFuncAttributeMaxDynamicSharedMemorySize, 66048);
    cudaFuncSetAttribute(k_conv_h,  cudaFuncAttributeMaxDynamicSharedMemorySize, 87552);

    k_pack_all<<<4736, 256>>>(x, sW, vW, qW, kW, oW);
    k_qkv<<<1536, 256, 36352>>>(q_scale, q_shift, k_scale, k_shift, v_scale, v_shift);
    k_sim_mma<<<dim3(NCH, Bn), 256, 41472>>>();
    k_m2<<<64, 256>>>();
    k_ctx_mma<<<dim3(Hh, 2, Bn), 256, 66048>>>(up, o_scale, o_shift);
    k_conv_h<<<dim3(Hh / 4, 2, Bn), 512, 87552>>>(s_scale, s_shift, out);
}

// round 16
// speedup vs baseline: 1.8120x; 1.0033x over previous
#include <cuda_runtime.h>
#include <cuda_fp16.h>
#include <math.h>
#include <stdint.h>

#define Bn   4
#define CIN  256
#define CQK  64
#define CS   128
#define Hh   128
#define Ww   128
#define HW   (Hh*Ww)
#define NCH  32
#define PIX_PER_CHUNK (HW/NCH)

__device__ float g_simp[Bn*NCH*CQK*CIN];
__device__ float g_sim [Bn*CQK*CIN];
__device__ float g_oWT [CIN*CIN];

__device__ __align__(16) uint2 g_Aqk[8192];
__device__ __align__(16) uint2 g_Av [16384];
__device__ __align__(16) uint2 g_xt [Bn*8*8*HW];
__device__ __align__(16) uint2 g_knt[Bn*64*1024*4];
__device__ __align__(16) uint2 g_vt [Bn*1024*4*256];
__device__ __align__(16) uint2 g_AM2h[Bn*4096];
__device__ __align__(16) uint2 g_qnth[Bn*16*HW];
__device__ __align__(16) uint2 g_wph[73728];
__device__ __align__(16) uint2 g_fth[Bn*16*4*130*132];
__device__ __align__(16) unsigned g_xrh[Bn*16*8*HW];

__device__ __forceinline__ uint32_t pkh2(float lo, float hi) {
    uint32_t r; asm("cvt.rn.f16x2.f32 %0, %1, %2;" : "=r"(r) : "f"(hi), "f"(lo)); return r;
}
__device__ __forceinline__ void mma16(float* c, uint2 alo, uint2 ahi, uint2 b) {
    asm volatile(
        "mma.sync.aligned.m16n8k16.row.col.f32.f16.f16.f32 "
        "{%0,%1,%2,%3}, {%4,%5,%6,%7}, {%8,%9}, {%0,%1,%2,%3};"
        : "+f"(c[0]), "+f"(c[1]), "+f"(c[2]), "+f"(c[3])
        : "r"(alo.x), "r"(ahi.x), "r"(alo.y), "r"(ahi.y), "r"(b.x), "r"(b.y));
}
__device__ __forceinline__ void cpa16(uint32_t saddr, const void* g) {
    asm volatile("cp.async.cg.shared.global [%0], [%1], 16;" :: "r"(saddr), "l"(g));
}
__device__ __forceinline__ void cpa_commit() { asm volatile("cp.async.commit_group;"); }
__device__ __forceinline__ void cpa_wait0()  { asm volatile("cp.async.wait_group 0;" ::: "memory"); }

// ============ merged pack kernel ============
__global__ void k_pack_all(const float* __restrict__ x,  const float* __restrict__ sW,
                           const float* __restrict__ vW, const float* __restrict__ qW,
                           const float* __restrict__ kW, const float* __restrict__ oW)
{
    int bx = blockIdx.x;
    if (bx < 4096) {
        int idx = bx * 256 + threadIdx.x;
        int n4 = (idx & 4095) * 4;
        int kkb = (idx >> 12) & 7;
        int it = (idx >> 15) & 7;
        int b = idx >> 18;
        int kb = kkb >> 2, kk = kkb & 3;
        int K0 = it * 32 + kb * 16 + kk * 2;
        const float* xb = x + ((size_t)b * CIN + K0) * HW + n4;
        float4 r0 = *(const float4*)xb;
        float4 r1 = *(const float4*)(xb + HW);
        float4 r8 = *(const float4*)(xb + 8 * HW);
        float4 r9 = *(const float4*)(xb + 9 * HW);
        uint2* dst = g_xt + ((size_t)((b * 8 + it) * 8 + kkb)) * HW + n4;
        *(uint4*)dst = make_uint4(pkh2(r0.x, r1.x), pkh2(r8.x, r9.x),
                                  pkh2(r0.y, r1.y), pkh2(r8.y, r9.y));
        *(uint4*)(dst + 2) = make_uint4(pkh2(r0.z, r1.z), pkh2(r8.z, r9.z),
                                        pkh2(r0.w, r1.w), pkh2(r8.w, r9.w));
        int ch = it * 2 + kb;
        unsigned* xd = g_xrh + ((size_t)((b * 16 + ch) * 8 + kk * 2)) * HW + n4;
        *(uint4*)xd = make_uint4(pkh2(r0.x, r8.x), pkh2(r0.y, r8.y),
                                 pkh2(r0.z, r8.z), pkh2(r0.w, r8.w));
        *(uint4*)(xd + HW) = make_uint4(pkh2(r1.x, r9.x), pkh2(r1.y, r9.y),
                                        pkh2(r1.z, r9.z), pkh2(r1.w, r9.w));
    } else if (bx < 4384) {
        int idx = (bx - 4096) * 256 + threadIdx.x;
        int r = idx & 511, s = idx >> 9;
        int j = r & 3, co = r >> 2;
        int tap = s % 3, t2 = s / 3, ch = t2 & 15, dh = t2 >> 4;
        int ci = ch * 16 + j * 2;
        const float* wp = sW + ((size_t)co * CIN + ci) * 9 + dh * 3 + tap;
        g_wph[idx] = make_uint2(pkh2(wp[0], wp[9]), pkh2(wp[8 * 9], wp[9 * 9]));
    } else if (bx < 4448) {
        int idx = (bx - 4384) * 256 + threadIdx.x;
        int kk = idx & 3, m = (idx >> 2) & 255, kb16 = idx >> 10;
        int K0 = kb16 * 16 + kk * 2;
        const float* wr = vW + (size_t)m * CIN;
        g_Av[idx] = make_uint2(pkh2(wr[K0], wr[K0 + 1]), pkh2(wr[K0 + 8], wr[K0 + 9]));
    } else if (bx < 4480) {
        int idx = (bx - 4448) * 256 + threadIdx.x;
        int kk = idx & 3, m = (idx >> 2) & 127, kb = (idx >> 9) & 1, it = idx >> 10;
        int K0 = it * 32 + kb * 16 + kk * 2;
        const float* wr = (m < 64) ? (qW + (size_t)m * CIN) : (kW + (size_t)(m - 64) * CIN);
        g_Aqk[idx] = make_uint2(pkh2(wr[K0], wr[K0 + 1]), pkh2(wr[K0 + 8], wr[K0 + 9]));
    } else {
        int idx = (bx - 4480) * 256 + threadIdx.x;
        int o = idx & 255, v = idx >> 8;
        g_oWT[v * CIN + o] = oW[o * CIN + v];
    }
}

// ============ qk body ============
__device__ __forceinline__ void qk_body(
    int b, int n0, uint2* dynsm,
    const float* __restrict__ qs, const float* __restrict__ qb,
    const float* __restrict__ kscale, const float* __restrict__ kshift)
{
    uint2* Asm = dynsm;
    uint2* Bsm = dynsm + 2048;
    float* Sq  = (float*)(dynsm + 4160);
    float* Nn  = Sq + 512;

    const int tid = threadIdx.x, lane = tid & 31, w = tid >> 5;
    const int g = lane >> 2, kk = lane & 3;
    const int mg = w >> 1, ng = w & 1;
    const int m0w = mg * 32, n0w = ng * 64;
    const uint32_t aBase = (uint32_t)__cvta_generic_to_shared(dynsm);
    const uint2* xtb = g_xt + (size_t)b * 8 * 8 * HW + n0;

    float acc[2][8][4];
#pragma unroll
    for (int mt = 0; mt < 2; mt++)
#pragma unroll
        for (int nt = 0; nt < 8; nt++)
#pragma unroll
            for (int i = 0; i < 4; i++) acc[mt][nt][i] = 0.f;

    auto fill = [&](int it, int stage) {
#pragma unroll
        for (int i = 0; i < 2; i++) {
            int j = i * 256 + tid;
            cpa16(aBase + (stage * 1024 + j * 2) * 8, g_Aqk + it * 1024 + j * 2);
        }
#pragma unroll
        for (int i = 0; i < 2; i++) {
            int j = i * 256 + tid;
            int kkb = j >> 6, npair = (j & 63) * 2;
            cpa16(aBase + (2048 + stage * 1056 + kkb * 132 + npair) * 8,
                  xtb + (size_t)((it * 8) + kkb) * HW + npair);
        }
    };

    fill(0, 0); cpa_commit(); cpa_wait0(); __syncthreads();

    for (int it = 0; it < 8; it++) {
        int cur = it & 1, nxt = cur ^ 1;
        if (it < 7) { fill(it + 1, nxt); cpa_commit(); }
        const uint2* Ac = Asm + cur * 1024;
        const uint2* Bc = Bsm + cur * 1056;
#pragma unroll
        for (int kb = 0; kb < 2; kb++) {
            uint2 alo[2], ahi[2];
#pragma unroll
            for (int mt = 0; mt < 2; mt++) {
                alo[mt] = Ac[(kb * 128 + m0w + mt * 16 + g) * 4 + kk];
                ahi[mt] = Ac[(kb * 128 + m0w + mt * 16 + 8 + g) * 4 + kk];
            }
#pragma unroll
            for (int nt = 0; nt < 8; nt++) {
                uint2 bb = Bc[(kb * 4 + kk) * 132 + n0w + nt * 8 + g];
                mma16(acc[0][nt], alo[0], ahi[0], bb);
                mma16(acc[1][nt], alo[1], ahi[1], bb);
            }
        }
        cpa_wait0(); __syncthreads();
    }

    float sq[8][2];
#pragma unroll
    for (int nt = 0; nt < 8; nt++) { sq[nt][0] = 0.f; sq[nt][1] = 0.f; }
#pragma unroll
    for (int mt = 0; mt < 2; mt++) {
        int r0 = m0w + mt * 16 + g, r1 = r0 + 8;
        bool isq = (r0 < 64);
        float sc0 = isq ? qs[r0] : kscale[r0 - 64];
        float sh0 = isq ? qb[r0] : kshift[r0 - 64];
        float sc1 = isq ? qs[r1] : kscale[r1 - 64];
        float sh1 = isq ? qb[r1] : kshift[r1 - 64];
#pragma unroll
        for (int nt = 0; nt < 8; nt++) {
            float v0 = fmaf(acc[mt][nt][0], sc0, sh0);
            float v1 = fmaf(acc[mt][nt][1], sc0, sh0);
            float v2 = fmaf(acc[mt][nt][2], sc1, sh1);
            float v3 = fmaf(acc[mt][nt][3], sc1, sh1);
            acc[mt][nt][0] = v0; acc[mt][nt][1] = v1;
            acc[mt][nt][2] = v2; acc[mt][nt][3] = v3;
            sq[nt][0] += v0 * v0 + v2 * v2;
            sq[nt][1] += v1 * v1 + v3 * v3;
        }
    }
#pragma unroll
    for (int nt = 0; nt < 8; nt++) {
#pragma unroll
        for (int o = 4; o < 32; o <<= 1) {
            sq[nt][0] += __shfl_xor_sync(0xffffffffu, sq[nt][0], o);
            sq[nt][1] += __shfl_xor_sync(0xffffffffu, sq[nt][1], o);
        }
    }
    if (lane < 4) {
#pragma unroll
        for (int nt = 0; nt < 8; nt++) {
            int c = n0w + nt * 8 + lane * 2;
            Sq[mg * 128 + c] = sq[nt][0];
            Sq[mg * 128 + c + 1] = sq[nt][1];
        }
    }
    __syncthreads();
    {
        int col = tid & 127, half = tid >> 7;
        float s = Sq[half * 256 + col] + Sq[half * 256 + 128 + col];
        Nn[half * 128 + col] = 1.f / fmaxf(sqrtf(s), 1e-12f);
    }
    __syncthreads();

    if (mg < 2) {
#pragma unroll
        for (int mt = 0; mt < 2; mt++) {
            int r0 = m0w + mt * 16 + g;
            int row = (r0 >> 4) * 4 + (g >> 1);
#pragma unroll
            for (int nt = 0; nt < 8; nt++) {
                int c = n0w + nt * 8 + (lane & 3) * 2;
                float i0 = Nn[c], i1 = Nn[c + 1];
                float v0 = acc[mt][nt][0] * i0, v1 = acc[mt][nt][1] * i1;
                float v2 = acc[mt][nt][2] * i0, v3 = acc[mt][nt][3] * i1;
                float p0 = __shfl_xor_sync(0xffffffffu, v0, 4);
                float p1 = __shfl_xor_sync(0xffffffffu, v1, 4);
                float p2 = __shfl_xor_sync(0xffffffffu, v2, 4);
                float p3 = __shfl_xor_sync(0xffffffffu, v3, 4);
                if ((g & 1) == 0) {
                    uint2* dst = g_qnth + (size_t)(b * 16 + row) * HW + n0 + c;
                    dst[0] = make_uint2(pkh2(v0, p0), pkh2(v2, p2));
                    dst[1] = make_uint2(pkh2(v1, p1), pkh2(v3, p3));
                }
            }
        }
    } else {
#pragma unroll
        for (int mt = 0; mt < 2; mt++) {
            int r0 = m0w + mt * 16 + g - 64;
#pragma unroll
            for (int nt = 0; nt < 8; nt += 2) {
                int c0 = n0w + nt * 8 + (lane & 3) * 2;
                int kbpix = (n0 + c0) >> 4, kkp = lane & 3;
                float i0 = Nn[128 + c0], i1 = Nn[128 + c0 + 1];
                float i8 = Nn[128 + c0 + 8], i9 = Nn[128 + c0 + 9];
                float a0 = acc[mt][nt][0] * i0,     a1 = acc[mt][nt][1] * i1;
                float b0 = acc[mt][nt + 1][0] * i8, b1 = acc[mt][nt + 1][1] * i9;
                float a2 = acc[mt][nt][2] * i0,     a3 = acc[mt][nt][3] * i1;
                float b2 = acc[mt][nt + 1][2] * i8, b3 = acc[mt][nt + 1][3] * i9;
                g_knt[((size_t)(b * 64 + r0) * 1024 + kbpix) * 4 + kkp] =
                    make_uint2(pkh2(a0, a1), pkh2(b0, b1));
                g_knt[((size_t)(b * 64 + r0 + 8) * 1024 + kbpix) * 4 + kkp] =
                    make_uint2(pkh2(a2, a3), pkh2(b2, b3));
            }
        }
    }
}

// ============ v body ============
__device__ __forceinline__ void v_body(
    int b, int co0, int n0, uint2* dynsm,
    const float* __restrict__ vs, const float* __restrict__ vb)
{
    uint2* Asm = dynsm;
    uint2* Bsm = dynsm + 2048;

    const int tid = threadIdx.x, lane = tid & 31, w = tid >> 5;
    const int g = lane >> 2, kk = lane & 3;
    const int mg = w >> 1, ng = w & 1;
    const int m0w = mg * 32, n0w = ng * 64;
    const uint32_t aBase = (uint32_t)__cvta_generic_to_shared(dynsm);
    const uint2* xtb = g_xt + (size_t)b * 8 * 8 * HW + n0;

    float acc[2][8][4];
#pragma unroll
    for (int mt = 0; mt < 2; mt++)
#pragma unroll
        for (int nt = 0; nt < 8; nt++)
#pragma unroll
            for (int i = 0; i < 4; i++) acc[mt][nt][i] = 0.f;

    auto fill = [&](int it, int stage) {
#pragma unroll
        for (int i = 0; i < 2; i++) {
            int j = i * 256 + tid;
            int kb = j >> 8, r = (j & 255) * 2;
            cpa16(aBase + (stage * 1024 + kb * 512 + r) * 8,
                  g_Av + (size_t)(it * 2 + kb) * 1024 + co0 * 4 + r);
        }
#pragma unroll
        for (int i = 0; i < 2; i++) {
            int j = i * 256 + tid;
            int kkb = j >> 6, npair = (j & 63) * 2;
            cpa16(aBase + (2048 + stage * 1056 + kkb * 132 + npair) * 8,
                  xtb + (size_t)((it * 8) + kkb) * HW + npair);
        }
    };

    fill(0, 0); cpa_commit(); cpa_wait0(); __syncthreads();

    for (int it = 0; it < 8; it++) {
        int cur = it & 1, nxt = cur ^ 1;
        if (it < 7) { fill(it + 1, nxt); cpa_commit(); }
        const uint2* Ac = Asm + cur * 1024;
        const uint2* Bc = Bsm + cur * 1056;
#pragma unroll
        for (int kb = 0; kb < 2; kb++) {
            uint2 alo[2], ahi[2];
#pragma unroll
            for (int mt = 0; mt < 2; mt++) {
                alo[mt] = Ac[(kb * 128 + m0w + mt * 16 + g) * 4 + kk];
                ahi[mt] = Ac[(kb * 128 + m0w + mt * 16 + 8 + g) * 4 + kk];
            }
#pragma unroll
            for (int nt = 0; nt < 8; nt++) {
                uint2 bb = Bc[(kb * 4 + kk) * 132 + n0w + nt * 8 + g];
                mma16(acc[0][nt], alo[0], ahi[0], bb);
                mma16(acc[1][nt], alo[1], ahi[1], bb);
            }
        }
        cpa_wait0(); __syncthreads();
    }

#pragma unroll
    for (int mt = 0; mt < 2; mt++) {
        int co = co0 + m0w + mt * 16 + g;
        float sc0 = vs[co], sh0 = vb[co];
        float sc1 = vs[co + 8], sh1 = vb[co + 8];
#pragma unroll
        for (int nt = 0; nt < 8; nt += 2) {
            int c0 = n0w + nt * 8 + (lane & 3) * 2;
            int kbpix = (n0 + c0) >> 4, kkp = lane & 3;
            float a0 = fmaxf(fmaf(acc[mt][nt][0], sc0, sh0), 0.f);
            float a1 = fmaxf(fmaf(acc[mt][nt][1], sc0, sh0), 0.f);
            float b0 = fmaxf(fmaf(acc[mt][nt + 1][0], sc0, sh0), 0.f);
            float b1 = fmaxf(fmaf(acc[mt][nt + 1][1], sc0, sh0), 0.f);
            float a2 = fmaxf(fmaf(acc[mt][nt][2], sc1, sh1), 0.f);
            float a3 = fmaxf(fmaf(acc[mt][nt][3], sc1, sh1), 0.f);
            float b2 = fmaxf(fmaf(acc[mt][nt + 1][2], sc1, sh1), 0.f);
            float b3 = fmaxf(fmaf(acc[mt][nt + 1][3], sc1, sh1), 0.f);
            g_vt[(((size_t)b * 1024 + kbpix) * 4 + kkp) * 256 + co] =
                make_uint2(pkh2(a0, a1), pkh2(b0, b1));
            g_vt[(((size_t)b * 1024 + kbpix) * 4 + kkp) * 256 + co + 8] =
                make_uint2(pkh2(a2, a3), pkh2(b2, b3));
        }
    }
}

// ============ merged K1+K2 ============
__global__ void __launch_bounds__(256, 2)
k_qkv(const float* __restrict__ qs, const float* __restrict__ qb,
      const float* __restrict__ kscale, const float* __restrict__ kshift,
      const float* __restrict__ vs, const float* __restrict__ vb)
{
    extern __shared__ uint2 dynsm[];
    int bx = blockIdx.x;
    if (bx < 512) {
        qk_body(bx >> 7, (bx & 127) * 128, dynsm, qs, qb, kscale, kshift);
    } else {
        int t = bx - 512;
        v_body(t >> 8, ((t >> 7) & 1) * 128, (t & 127) * 128, dynsm, vs, vb);
    }
}

// ============ K3: partial sim (NCH=32) ============
__global__ void __launch_bounds__(256, 2) k_sim_mma()
{
    extern __shared__ uint2 dynsm[];
    const int b = blockIdx.y, ch = blockIdx.x;
    const int kbp0 = (ch * PIX_PER_CHUNK) >> 4;
    const int tid = threadIdx.x, lane = tid & 31, w = tid >> 5;
    const int g = lane >> 2, kk = lane & 3;
    const int mg = w >> 2, ng = w & 3;
    const int m0w = mg * 32, n0w = ng * 64;
    const uint32_t smBase = (uint32_t)__cvta_generic_to_shared(dynsm);

    float acc[2][8][4];
#pragma unroll
    for (int mt = 0; mt < 2; mt++)
#pragma unroll
        for (int nt = 0; nt < 8; nt++)
#pragma unroll
            for (int i = 0; i < 4; i++) acc[mt][nt][i] = 0.f;

    auto fill = [&](int it, int stage) {
        int kbpix = kbp0 + it * 2;
        {
            int j = tid;
            int m = j >> 2, kb = (j >> 1) & 1, kp = j & 1;
            cpa16(smBase + (stage * 512 + (kb * 64 + m) * 4 + kp * 2) * 8,
                  g_knt + ((size_t)(b * 64 + m) * 1024 + kbpix + kb) * 4 + kp * 2);
        }
#pragma unroll
        for (int i = 0; i < 4; i++) {
            int j = i * 256 + tid;
            int row = j >> 7, npair = (j & 127) * 2;
            int kb = row >> 2, kkr = row & 3;
            cpa16(smBase + (1024 + stage * 2080 + row * 260 + npair) * 8,
                  g_vt + (((size_t)b * 1024 + kbpix + kb) * 4 + kkr) * 256 + npair);
        }
    };

    fill(0, 0); cpa_commit(); cpa_wait0(); __syncthreads();

    for (int it = 0; it < 16; it++) {
        int cur = it & 1, nxt = cur ^ 1;
        if (it < 15) { fill(it + 1, nxt); cpa_commit(); }
        const uint2* Ac = dynsm + cur * 512;
        const uint2* Bc = dynsm + 1024 + cur * 2080;
#pragma unroll
        for (int kb = 0; kb < 2; kb++) {
            uint2 alo[2], ahi[2];
#pragma unroll
            for (int mt = 0; mt < 2; mt++) {
                alo[mt] = Ac[(kb * 64 + m0w + mt * 16 + g) * 4 + kk];
                ahi[mt] = Ac[(kb * 64 + m0w + mt * 16 + 8 + g) * 4 + kk];
            }
#pragma unroll
            for (int nt = 0; nt < 8; nt++) {
                uint2 bb = Bc[(kb * 4 + kk) * 260 + n0w + nt * 8 + g];
                mma16(acc[0][nt], alo[0], ahi[0], bb);
                mma16(acc[1][nt], alo[1], ahi[1], bb);
            }
        }
        cpa_wait0(); __syncthreads();
    }

    float* outp = g_simp + (size_t)(b * NCH + ch) * CQK * CIN;
#pragma unroll
    for (int mt = 0; mt < 2; mt++) {
        int r = m0w + mt * 16 + g;
#pragma unroll
        for (int nt = 0; nt < 8; nt++) {
            int c = n0w + nt * 8 + (lane & 3) * 2;
            *(float2*)&outp[(size_t)r * CIN + c] = make_float2(acc[mt][nt][0], acc[mt][nt][1]);
            *(float2*)&outp[(size_t)(r + 8) * CIN + c] = make_float2(acc[mt][nt][2], acc[mt][nt][3]);
        }
    }
}

// ============ K3b: reduce partials -> g_sim (128 blocks, float2/thread) ============
__global__ void k_simred()
{
    int u = blockIdx.x * 256 + threadIdx.x;    // < 32768, each handles 2 floats
    int o2 = u * 2;                            // < 65536 = Bn*CQK*CIN
    int b = o2 >> 14;
    int cv = o2 & 16383;
    const float* sp = g_simp + (size_t)b * NCH * CQK * CIN + cv;
    float2 s = make_float2(0.f, 0.f);
#pragma unroll 8
    for (int ch = 0; ch < NCH; ch++) {
        float2 v = *(const float2*)(sp + (size_t)ch * CQK * CIN);
        s.x += v.x; s.y += v.y;
    }
    *(float2*)(g_sim + o2) = s;
}

// ============ K4a: M2 (coalesced oWT) -> fp16 g_AM2h ============
__global__ void k_m2()
{
    __shared__ float ssm[4][CIN];
    const int b = blockIdx.x >> 4;
    const int c0 = (blockIdx.x & 15) * 4;
    const int o = threadIdx.x;
#pragma unroll
    for (int i = 0; i < 4; i++)
        ssm[i][o] = g_sim[((size_t)b * CQK + c0 + i) * CIN + o];
    __syncthreads();
    float s0 = 0.f, s1 = 0.f, s2 = 0.f, s3 = 0.f;
#pragma unroll 4
    for (int v = 0; v < CIN; v++) {
        float wv = g_oWT[v * CIN + o];
        s0 = fmaf(wv, ssm[0][v], s0);
        s1 = fmaf(wv, ssm[1][v], s1);
        s2 = fmaf(wv, ssm[2][v], s2);
        s3 = fmaf(wv, ssm[3][v], s3);
    }
    __half* hp = (__half*)g_AM2h;
    float sv[4] = {s0, s1, s2, s3};
#pragma unroll
    for (int i = 0; i < 4; i++) {
        int c = c0 + i;
        int kb = c >> 4, rem = c & 15;
        int hi = rem >> 3, kkv = (rem & 7) >> 1, low = rem & 1;
        hp[((((size_t)(b * 4 + kb) * 256 + o) * 4 + kkv) << 2) + hi * 2 + low] = __float2half(sv[i]);
    }
}

// ============ K4: ctx mma (fp16) -> fuse -> fp16 pairs g_fth ============
__global__ void __launch_bounds__(256, 2)
k_ctx_mma(const float* __restrict__ up,
          const float* __restrict__ os, const float* __restrict__ ob)
{
    extern __shared__ uint2 dynsm[];
    uint2* Asm = dynsm;
    uint2* Bsm = dynsm + 2048;
    float* upH = (float*)(dynsm + 4160);

    const int b = blockIdx.z;
    const int co0 = blockIdx.y * 128;
    const int h = blockIdx.x;
    const int n0 = h * Ww;
    const int tid = threadIdx.x, lane = tid & 31, w = tid >> 5;
    const int g = lane >> 2, kk = lane & 3;
    const int mg = w >> 1, ng = w & 1;
    const int m0w = mg * 32, n0w = ng * 64;
    const uint32_t aBase = (uint32_t)__cvta_generic_to_shared(dynsm);

#pragma unroll
    for (int i = 0; i < 4; i++) {
        int j = i * 256 + tid;
        int kb = j >> 8, r = j & 255;
        int m = r >> 1, kp = r & 1;
        cpa16(aBase + (kb * 512 + m * 4 + kp * 2) * 8,
              g_AM2h + ((size_t)(b * 4 + kb) * 256 + co0 + m) * 4 + kp * 2);
    }
#pragma unroll
    for (int i = 0; i < 4; i++) {
        int j = i * 256 + tid;
        int row = j >> 6, npair = (j & 63) * 2;
        cpa16(aBase + (2048 + row * 132 + npair) * 8,
              g_qnth + (size_t)(b * 16 + row) * HW + n0 + npair);
    }
    cpa_commit();

    {
        float shf = 0.5f * h - 0.25f;
        int h0 = (int)floorf(shf);
        float wh1 = shf - (float)h0;
        int h0c = h0 < 0 ? 0 : h0;
        int h1c = (h0 + 1) > 63 ? 63 : (h0 + 1);
        const float* ub = up + ((size_t)(b * CIN + co0)) * 64 * 64;
#pragma unroll
        for (int i = 0; i < 32; i++) {
            int idx = i * 256 + tid;
            int r = idx >> 6, sw = idx & 63;
            upH[r * 64 + sw] = (1.f - wh1) * ub[(r * 64 + h0c) * 64 + sw]
                             + wh1 * ub[(r * 64 + h1c) * 64 + sw];
        }
    }
    cpa_wait0(); __syncthreads();

    float acc[2][8][4];
#pragma unroll
    for (int mt = 0; mt < 2; mt++)
#pragma unroll
        for (int nt = 0; nt < 8; nt++)
#pragma unroll
            for (int i = 0; i < 4; i++) acc[mt][nt][i] = 0.f;

#pragma unroll
    for (int kb = 0; kb < 4; kb++) {
        uint2 alo[2], ahi[2];
#pragma unroll
        for (int mt = 0; mt < 2; mt++) {
            alo[mt] = Asm[kb * 512 + (m0w + mt * 16 + g) * 4 + kk];
            ahi[mt] = Asm[kb * 512 + (m0w + mt * 16 + 8 + g) * 4 + kk];
        }
#pragma unroll
        for (int nt = 0; nt < 8; nt++) {
            uint2 bb = Bsm[(kb * 4 + kk) * 132 + n0w + nt * 8 + g];
            mma16(acc[0][nt], alo[0], ahi[0], bb);
            mma16(acc[1][nt], alo[1], ahi[1], bb);
        }
    }

#pragma unroll
    for (int mt = 0; mt < 2; mt++) {
        int m = m0w + mt * 16 + g;
        int co = co0 + m;
        float sc0 = os[co], sh0 = ob[co];
        float sc1 = os[co + 8], sh1 = ob[co + 8];
        int ch16 = co >> 4;
        int jidx = g >> 1;
        const unsigned* xrb = g_xrh + ((size_t)(b * 16 + ch16) * 8 + g) * HW + n0;
#pragma unroll
        for (int nt = 0; nt < 8; nt++) {
            int c0 = n0w + nt * 8 + (lane & 3) * 2;
            int c1 = c0 + 1;
            float sw0 = 0.5f * c0 - 0.25f, sw1 = 0.5f * c1 - 0.25f;
            int wa0 = (int)floorf(sw0), wa1 = (int)floorf(sw1);
            float t0 = sw0 - (float)wa0, t1 = sw1 - (float)wa1;
            int w00 = wa0 < 0 ? 0 : wa0, w01 = (wa0 + 1) > 63 ? 63 : (wa0 + 1);
            int w10 = wa1 < 0 ? 0 : wa1, w11 = (wa1 + 1) > 63 ? 63 : (wa1 + 1);

            float u0a = (1.f - t0) * upH[m * 64 + w00] + t0 * upH[m * 64 + w01];
            float u1a = (1.f - t1) * upH[m * 64 + w10] + t1 * upH[m * 64 + w11];
            float u0b = (1.f - t0) * upH[(m + 8) * 64 + w00] + t0 * upH[(m + 8) * 64 + w01];
            float u1b = (1.f - t1) * upH[(m + 8) * 64 + w10] + t1 * upH[(m + 8) * 64 + w11];

            uint2 xr2 = *(const uint2*)(xrb + c0);
            float2 xa = __half22float2(*(const __half2*)&xr2.x);
            float2 xc = __half22float2(*(const __half2*)&xr2.y);

            float f0 = fmaxf(fmaf(acc[mt][nt][0], sc0, sh0), 0.f) + xa.x + u0a;
            float f1 = fmaxf(fmaf(acc[mt][nt][1], sc0, sh0), 0.f) + xc.x + u1a;
            float f2 = fmaxf(fmaf(acc[mt][nt][2], sc1, sh1), 0.f) + xa.y + u0b;
            float f3 = fmaxf(fmaf(acc[mt][nt][3], sc1, sh1), 0.f) + xc.y + u1b;

            float p0 = __shfl_xor_sync(0xffffffffu, f0, 4);
            float p1 = __shfl_xor_sync(0xffffffffu, f1, 4);
            float p2 = __shfl_xor_sync(0xffffffffu, f2, 4);
            float p3 = __shfl_xor_sync(0xffffffffu, f3, 4);
            if ((g & 1) == 0) {
                size_t base = (((size_t)(b * 16 + ch16) * 4 + jidx) * 130 + h + 1) * 132 + 1;
                g_fth[base + c0] = make_uint2(pkh2(f0, p0), pkh2(f2, p2));
                g_fth[base + c1] = make_uint2(pkh2(f1, p1), pkh2(f3, p3));
            }
        }
    }
}

// ============ K5: 3x3 conv, fp16, 4 rows x 64 co x 128 w ============
__global__ void __launch_bounds__(512, 1)
k_conv_h(const float* __restrict__ ss, const float* __restrict__ sb,
         float* __restrict__ out)
{
    extern __shared__ uint2 csm[];
    uint2* Ism = csm;
    uint2* Wsm = csm + 6336;

    const int h0 = blockIdx.x * 4;
    const int co0 = blockIdx.y * 64;
    const int b = blockIdx.z;
    const int tid = threadIdx.x, lane = tid & 31, w = tid >> 5;
    const int g = lane >> 2, kk = lane & 3;
    const int mg = w >> 3, ng = w & 7;
    const int m0w = mg * 32, n0w = ng * 64;
    const uint32_t smBase = (uint32_t)__cvta_generic_to_shared(csm);

    float acc[2][8][4];
#pragma unroll
    for (int mt = 0; mt < 2; mt++)
#pragma unroll
        for (int nt = 0; nt < 8; nt++)
#pragma unroll
            for (int i = 0; i < 4; i++) acc[mt][nt][i] = 0.f;

    const uint2* ftb = g_fth + (size_t)b * 16 * 4 * 130 * 132;

    auto fill = [&](int ch, int stage) {
        for (int j = tid; j < 1560; j += 512) {
            int rowplane = j / 65;
            int colpair = (j - rowplane * 65) * 2;
            int row = rowplane >> 2, jj = rowplane & 3;
            cpa16(smBase + (stage * 3168 + (row * 4 + jj) * 132 + colpair) * 8,
                  ftb + ((size_t)(ch * 4 + jj) * 130 + h0 + row) * 132 + colpair);
        }
        for (int j = tid; j < 1152; j += 512) {
            int u = j * 2;
            int grp = u >> 8, off = u & 255;
            int dh = grp / 3, tap = grp - dh * 3;
            cpa16(smBase + (6336 + stage * 2304 + grp * 256 + off) * 8,
                  g_wph + (size_t)((dh * 16 + ch) * 3 + tap) * 512 + co0 * 4 + off);
        }
    };

    fill(0, 0); cpa_commit(); cpa_wait0(); __syncthreads();

    for (int it = 0; it < 16; it++) {
        int cur = it & 1, nxt = cur ^ 1;
        if (it < 15) { fill(it + 1, nxt); cpa_commit(); }

        const uint2* Ic = Ism + cur * 3168;
        const uint2* Wc = Wsm + cur * 2304;
#pragma unroll
        for (int dh = 0; dh < 3; dh++) {
#pragma unroll
            for (int tap = 0; tap < 3; tap++) {
                const uint2* wb = Wc + (dh * 3 + tap) * 256;
                uint2 alo[2], ahi[2];
#pragma unroll
                for (int mt = 0; mt < 2; mt++) {
                    alo[mt] = wb[(m0w + mt * 16 + g) * 4 + kk];
                    ahi[mt] = wb[(m0w + mt * 16 + 8 + g) * 4 + kk];
                }
#pragma unroll
                for (int nt = 0; nt < 8; nt++) {
                    int n = n0w + nt * 8 + g;
                    int rrow = n >> 7, wx = n & 127;
                    uint2 bb = Ic[((rrow + dh) * 4 + kk) * 132 + wx + tap];
                    mma16(acc[0][nt], alo[0], ahi[0], bb);
                    mma16(acc[1][nt], alo[1], ahi[1], bb);
                }
            }
        }
        cpa_wait0(); __syncthreads();
    }

#pragma unroll
    for (int mt = 0; mt < 2; mt++) {
        int co = co0 + m0w + mt * 16 + g;
        float sc0 = ss[co], sh0 = sb[co];
        float sc1 = ss[co + 8], sh1 = sb[co + 8];
#pragma unroll
        for (int nt = 0; nt < 8; nt++) {
            int n = n0w + nt * 8 + (lane & 3) * 2;
            int r = n >> 7, wx = n & 127;
            float* o0p = out + (((size_t)b * CS + co) * Hh + h0 + r) * Ww + wx;
            float* o1p = out + (((size_t)b * CS + co + 8) * Hh + h0 + r) * Ww + wx;
            float2 o0 = make_float2(fmaxf(fmaf(acc[mt][nt][0], sc0, sh0), 0.f),
                                    fmaxf(fmaf(acc[mt][nt][1], sc0, sh0), 0.f));
            float2 o1 = make_float2(fmaxf(fmaf(acc[mt][nt][2], sc1, sh1), 0.f),
                                    fmaxf(fmaf(acc[mt][nt][3], sc1, sh1), 0.f));
            *(float2*)o0p = o0;
            *(float2*)o1p = o1;
        }
    }
}

// ============================================================
extern "C" void kernel_launch(void* const* d_in, const int* in_sizes, int n_in,
                              void* d_out, int out_size)
{
    (void)in_sizes; (void)n_in; (void)out_size;
    const float* x        = (const float*)d_in[0];
    const float* up       = (const float*)d_in[1];
    const float* qW       = (const float*)d_in[2];
    const float* q_scale  = (const float*)d_in[3];
    const float* q_shift  = (const float*)d_in[4];
    const float* kW       = (const float*)d_in[5];
    const float* k_scale  = (const float*)d_in[6];
    const float* k_shift  = (const float*)d_in[7];
    const float* vW       = (const float*)d_in[8];
    const float* v_scale  = (const float*)d_in[9];
    const float* v_shift  = (const float*)d_in[10];
    const float* oW       = (const float*)d_in[11];
    const float* o_scale  = (const float*)d_in[12];
    const float* o_shift  = (const float*)d_in[13];
    const float* sW       = (const float*)d_in[14];
    const float* s_scale  = (const float*)d_in[15];
    const float* s_shift  = (const float*)d_in[16];
    float* out = (float*)d_out;

    cudaFuncSetAttribute(k_qkv,     cudaFuncAttributeMaxDynamicSharedMemorySize, 36352);
    cudaFuncSetAttribute(k_sim_mma, cudaFuncAttributeMaxDynamicSharedMemorySize, 41472);
    cudaFuncSetAttribute(k_ctx_mma, cudaFuncAttributeMaxDynamicSharedMemorySize, 66048);
    cudaFuncSetAttribute(k_conv_h,  cudaFuncAttributeMaxDynamicSharedMemorySize, 87552);

    k_pack_all<<<4736, 256>>>(x, sW, vW, qW, kW, oW);
    k_qkv<<<1536, 256, 36352>>>(q_scale, q_shift, k_scale, k_shift, v_scale, v_shift);
    k_sim_mma<<<dim3(NCH, Bn), 256, 41472>>>();
    k_simred<<<128, 256>>>();
    k_m2<<<64, 256>>>();
    k_ctx_mma<<<dim3(Hh, 2, Bn), 256, 66048>>>(up, o_scale, o_shift);
    k_conv_h<<<dim3(Hh / 4, 2, Bn), 512, 87552>>>(s_scale, s_shift, out);
}